// round 1
// baseline (speedup 1.0000x reference)
#include <cuda_runtime.h>
#include <cuda_bf16.h>
#include <cstdint>

// Problem constants
#define BATCH 2
#define SEQ   2048
#define DMODEL 2048
#define NHEADS 16
#define HDIM  128
#define ROWS  (BATCH * SEQ)          // 4096
#define QKV_ELEMS (ROWS * DMODEL)    // 8388608

// ---------------- scratch (device globals; no allocation) ----------------
__device__ float g_q[QKV_ELEMS];     // [B,H,S,hd]
__device__ float g_k[QKV_ELEMS];     // [B,H,S,hd]
__device__ float g_v[QKV_ELEMS];     // [B,H,S,hd]
__device__ float g_att[QKV_ELEMS];   // [B*S, H*hd] row-major

// ---------------- SGEMM: C = A[M,K] @ B[K,N], fp32 ----------------
// 128x128 block tile, BK=16, 8x8 per thread, 256 threads.
// mode 0: write to [B,H,S,hd] layout (QKV). mode 1: plain row-major.
#define BM 128
#define BN 128
#define BKK 16
#define TM 8
#define TN 8

__global__ __launch_bounds__(256) void sgemm_k(
    const float* __restrict__ A, const float* __restrict__ B,
    float* __restrict__ C, int M, int N, int K, int mode)
{
    __shared__ float As[BKK][BM + 4];
    __shared__ float Bs[BKK][BN];

    const int t  = threadIdx.x;
    const int tx = t & 15;          // 0..15 -> N direction
    const int ty = t >> 4;          // 0..15 -> M direction
    const int bm0 = blockIdx.y * BM;
    const int bn0 = blockIdx.x * BN;

    const float* Ab = A + (size_t)bm0 * K;
    const float* Bb = B + bn0;

    float acc[TM][TN];
    #pragma unroll
    for (int i = 0; i < TM; i++)
        #pragma unroll
        for (int j = 0; j < TN; j++) acc[i][j] = 0.f;

    for (int k0 = 0; k0 < K; k0 += BKK) {
        // Load A tile (128x16) as float4, store transposed As[k][m]
        #pragma unroll
        for (int r = 0; r < 2; r++) {
            int f = t + r * 256;                 // 0..511 float4 idx
            int row = f >> 2;                    // 0..127
            int kc  = (f & 3) * 4;               // 0,4,8,12
            float4 v = *(const float4*)(Ab + (size_t)row * K + k0 + kc);
            As[kc + 0][row] = v.x;
            As[kc + 1][row] = v.y;
            As[kc + 2][row] = v.z;
            As[kc + 3][row] = v.w;
        }
        // Load B tile (16x128) as float4, natural layout
        #pragma unroll
        for (int r = 0; r < 2; r++) {
            int f = t + r * 256;                 // 0..511
            int krow = f >> 5;                   // 0..15
            int c4   = (f & 31) * 4;             // 0..124
            *(float4*)&Bs[krow][c4] =
                *(const float4*)(Bb + (size_t)(k0 + krow) * N + c4);
        }
        __syncthreads();

        #pragma unroll
        for (int k = 0; k < BKK; k++) {
            float rm[TM], rn[TN];
            *(float4*)&rm[0] = *(const float4*)&As[k][ty * TM];
            *(float4*)&rm[4] = *(const float4*)&As[k][ty * TM + 4];
            *(float4*)&rn[0] = *(const float4*)&Bs[k][tx * TN];
            *(float4*)&rn[4] = *(const float4*)&Bs[k][tx * TN + 4];
            #pragma unroll
            for (int i = 0; i < TM; i++)
                #pragma unroll
                for (int j = 0; j < TN; j++)
                    acc[i][j] += rm[i] * rn[j];
        }
        __syncthreads();
    }

    // Epilogue
    #pragma unroll
    for (int i = 0; i < TM; i++) {
        int row = bm0 + ty * TM + i;
        #pragma unroll
        for (int j4 = 0; j4 < TN; j4 += 4) {
            int col = bn0 + tx * TN + j4;
            float4 v = make_float4(acc[i][j4], acc[i][j4 + 1],
                                   acc[i][j4 + 2], acc[i][j4 + 3]);
            size_t idx;
            if (mode == 0) {
                // row = b*SEQ + s ; col = h*HDIM + d  ->  [B,H,S,hd]
                int b = row >> 11;       // /SEQ
                int s = row & 2047;
                int h = col >> 7;        // /HDIM
                int d = col & 127;
                idx = (((size_t)(b * NHEADS + h) * SEQ) + s) * HDIM + d;
            } else {
                idx = (size_t)row * N + col;
            }
            *(float4*)(C + idx) = v;
        }
    }
}

// ---------------- RoPE (in place on q and k, [B,H,S,hd]) ----------------
__global__ __launch_bounds__(256) void rope_k(
    float* __restrict__ q, float* __restrict__ k,
    const float* __restrict__ fcos, const float* __restrict__ fsin)
{
    int p = blockIdx.x * blockDim.x + threadIdx.x;   // pair id, 0..4194303
    int d = p & 63;
    int s = (p >> 6) & 2047;
    int base = (p >> 6) * 128 + d;
    float c  = fcos[s * 64 + d];
    float si = fsin[s * 64 + d];

    float q0 = q[base], q1 = q[base + 64];
    q[base]      = q0 * c - q1 * si;
    q[base + 64] = q1 * c + q0 * si;

    float k0 = k[base], k1 = k[base + 64];
    k[base]      = k0 * c - k1 * si;
    k[base + 64] = k1 * c + k0 * si;
}

// ---------------- Flash attention fp32, causal ----------------
// Block: 128 threads. Q tile = 64 rows; 2 threads per row, each owns 64 dims.
// K/V tiles (64x128) + score tile in dynamic smem. All lanes iterate the same
// n in the inner loops -> K/V smem reads are warp-broadcast (conflict free).
#define ATT_SMEM ((2 * 64 * 128 + 64 * 65) * 4)

__global__ __launch_bounds__(128) void flash_k(
    const float* __restrict__ Q, const float* __restrict__ K,
    const float* __restrict__ V, float* __restrict__ O)
{
    extern __shared__ float sm[];
    float* Ks = sm;                 // 64*128
    float* Vs = sm + 64 * 128;      // 64*128
    float* Ss = sm + 2 * 64 * 128;  // 64*65 (padded)

    const int t    = threadIdx.x;
    const int row  = t >> 1;        // 0..63
    const int half = t & 1;
    const int d0   = half * 64;
    const int bh   = blockIdx.y;    // 0..31
    const int m0   = blockIdx.x * 64;

    // fold 1/sqrt(hd) and log2(e) into q: softmax via exp2
    const float qscale = 0.08838834764831845f * 1.4426950408889634f;

    const float* Qr = Q + ((size_t)bh * SEQ + m0 + row) * HDIM + d0;
    float q[64];
    #pragma unroll
    for (int i = 0; i < 16; i++) {
        float4 v = *(const float4*)(Qr + 4 * i);
        q[4 * i + 0] = v.x * qscale;
        q[4 * i + 1] = v.y * qscale;
        q[4 * i + 2] = v.z * qscale;
        q[4 * i + 3] = v.w * qscale;
    }

    float acc[64];
    #pragma unroll
    for (int d = 0; d < 64; d++) acc[d] = 0.f;
    float m_run = -1e30f, l = 0.f;

    const int ntiles = blockIdx.x + 1;   // causal: only tiles up to diagonal
    for (int jt = 0; jt < ntiles; jt++) {
        const float4* Kb = (const float4*)(K + ((size_t)bh * SEQ + jt * 64) * HDIM);
        const float4* Vb = (const float4*)(V + ((size_t)bh * SEQ + jt * 64) * HDIM);
        #pragma unroll
        for (int i = 0; i < 16; i++) {
            int f = t + i * 128;         // 0..2047 float4
            ((float4*)Ks)[f] = Kb[f];
            ((float4*)Vs)[f] = Vb[f];
        }
        __syncthreads();

        const bool diag = (jt == blockIdx.x);
        float tmax = -1e30f;
        #pragma unroll 2
        for (int n = 0; n < 64; n++) {
            const float4* kr = (const float4*)(Ks + n * 128 + d0);
            float p0 = 0.f, p1 = 0.f, p2 = 0.f, p3 = 0.f;
            #pragma unroll
            for (int i = 0; i < 16; i++) {
                float4 kv = kr[i];
                p0 += q[4 * i + 0] * kv.x;
                p1 += q[4 * i + 1] * kv.y;
                p2 += q[4 * i + 2] * kv.z;
                p3 += q[4 * i + 3] * kv.w;
            }
            float partial = (p0 + p1) + (p2 + p3);
            float full = partial + __shfl_xor_sync(0xffffffffu, partial, 1);
            if (diag && n > row) full = -1e30f;
            if (half == 0) Ss[row * 65 + n] = full;
            tmax = fmaxf(tmax, full);
        }
        __syncwarp();

        float m_new = fmaxf(m_run, tmax);
        float corr  = exp2f(m_run - m_new);
        l *= corr;
        #pragma unroll
        for (int d = 0; d < 64; d++) acc[d] *= corr;

        #pragma unroll 2
        for (int n = 0; n < 64; n++) {
            float p = exp2f(Ss[row * 65 + n] - m_new);
            l += p;
            const float4* vr = (const float4*)(Vs + n * 128 + d0);
            #pragma unroll
            for (int i = 0; i < 16; i++) {
                float4 vv = vr[i];
                acc[4 * i + 0] += p * vv.x;
                acc[4 * i + 1] += p * vv.y;
                acc[4 * i + 2] += p * vv.z;
                acc[4 * i + 3] += p * vv.w;
            }
        }
        m_run = m_new;
        __syncthreads();
    }

    const float inv = 1.f / l;
    const int b = bh >> 4, h = bh & 15;
    float* Or = O + ((size_t)(b * SEQ) + m0 + row) * DMODEL + h * HDIM + d0;
    #pragma unroll
    for (int i = 0; i < 16; i++) {
        float4 v = make_float4(acc[4 * i] * inv, acc[4 * i + 1] * inv,
                               acc[4 * i + 2] * inv, acc[4 * i + 3] * inv);
        *(float4*)(Or + 4 * i) = v;
    }
}

// ---------------- launch ----------------
extern "C" void kernel_launch(void* const* d_in, const int* in_sizes, int n_in,
                              void* d_out, int out_size)
{
    const float* x    = (const float*)d_in[0];
    const float* fcos = (const float*)d_in[1];
    const float* fsin = (const float*)d_in[2];
    const float* wq   = (const float*)d_in[3];
    const float* wk   = (const float*)d_in[4];
    const float* wv   = (const float*)d_in[5];
    const float* wo   = (const float*)d_in[6];
    float* out = (float*)d_out;

    float *q, *k, *v, *att;
    cudaGetSymbolAddress((void**)&q,   g_q);
    cudaGetSymbolAddress((void**)&k,   g_k);
    cudaGetSymbolAddress((void**)&v,   g_v);
    cudaGetSymbolAddress((void**)&att, g_att);

    dim3 gg(DMODEL / BN, ROWS / BM);   // (16, 32)

    sgemm_k<<<gg, 256>>>(x, wq, q, ROWS, DMODEL, DMODEL, 0);
    sgemm_k<<<gg, 256>>>(x, wk, k, ROWS, DMODEL, DMODEL, 0);
    sgemm_k<<<gg, 256>>>(x, wv, v, ROWS, DMODEL, DMODEL, 0);

    rope_k<<<(BATCH * NHEADS * SEQ * 64) / 256, 256>>>(q, k, fcos, fsin);

    cudaFuncSetAttribute(flash_k, cudaFuncAttributeMaxDynamicSharedMemorySize,
                         ATT_SMEM);
    flash_k<<<dim3(SEQ / 64, BATCH * NHEADS), 128, ATT_SMEM>>>(q, k, v, att);

    sgemm_k<<<gg, 256>>>(att, wo, out, ROWS, DMODEL, DMODEL, 1);
}

// round 5
// speedup vs baseline: 1.4597x; 1.4597x over previous
#include <cuda_runtime.h>
#include <cuda_bf16.h>
#include <cstdint>

// Problem constants
#define BATCH 2
#define SEQ   2048
#define DMODEL 2048
#define NHEADS 16
#define HDIM  128
#define ROWS  (BATCH * SEQ)          // 4096
#define QKV_ELEMS (ROWS * DMODEL)    // 8388608
#define WELEMS (DMODEL * DMODEL)     // 4194304

// ---------------- scratch (device globals; no allocation) ----------------
__device__ float g_q[QKV_ELEMS];     // [B,H,S,hd]
__device__ float g_k[QKV_ELEMS];
__device__ float g_v[QKV_ELEMS];
__device__ float g_att[QKV_ELEMS];   // [B*S, H*hd]

__device__ __align__(256) __nv_bfloat16 g_xh[QKV_ELEMS];
__device__ __align__(256) __nv_bfloat16 g_xl[QKV_ELEMS];
__device__ __align__(256) __nv_bfloat16 g_ath[QKV_ELEMS];
__device__ __align__(256) __nv_bfloat16 g_atl[QKV_ELEMS];
// transposed weights [N,K] hi/lo
__device__ __align__(256) __nv_bfloat16 g_wqh[WELEMS], g_wql[WELEMS];
__device__ __align__(256) __nv_bfloat16 g_wkh[WELEMS], g_wkl[WELEMS];
__device__ __align__(256) __nv_bfloat16 g_wvh[WELEMS], g_wvl[WELEMS];
__device__ __align__(256) __nv_bfloat16 g_woh[WELEMS], g_wol[WELEMS];

// ---------------- PTX helpers (sm_80-class only; no tcgen05) ----------------
__device__ __forceinline__ uint32_t s2u(const void* p) {
    uint32_t a;
    asm("{ .reg .u64 t; cvta.to.shared.u64 t, %1; cvt.u32.u64 %0, t; }"
        : "=r"(a) : "l"(p));
    return a;
}
#define CPASYNC16(sa, g) asm volatile("cp.async.cg.shared.global [%0], [%1], 16;" :: "r"(sa), "l"(g))
#define CPCOMMIT()  asm volatile("cp.async.commit_group;" ::: "memory")
#define CPWAIT1()   asm volatile("cp.async.wait_group 1;" ::: "memory")
#define CPWAIT0()   asm volatile("cp.async.wait_group 0;" ::: "memory")

#define LDSM4(r0, r1, r2, r3, a) \
    asm volatile("ldmatrix.sync.aligned.m8n8.x4.shared.b16 {%0,%1,%2,%3}, [%4];" \
                 : "=r"(r0), "=r"(r1), "=r"(r2), "=r"(r3) : "r"(a))
#define LDSM2(r0, r1, a) \
    asm volatile("ldmatrix.sync.aligned.m8n8.x2.shared.b16 {%0,%1}, [%2];" \
                 : "=r"(r0), "=r"(r1) : "r"(a))

#define MMA16816(c, a, b) \
    asm volatile("mma.sync.aligned.m16n8k16.row.col.f32.bf16.bf16.f32 " \
                 "{%0,%1,%2,%3}, {%4,%5,%6,%7}, {%8,%9}, {%0,%1,%2,%3};" \
                 : "+f"((c)[0]), "+f"((c)[1]), "+f"((c)[2]), "+f"((c)[3]) \
                 : "r"((a)[0]), "r"((a)[1]), "r"((a)[2]), "r"((a)[3]), \
                   "r"((b)[0]), "r"((b)[1]))

// ---------------- split conversion: fp32 -> bf16 hi/lo ----------------
__global__ __launch_bounds__(256) void split_k(
    const float* __restrict__ in, __nv_bfloat16* __restrict__ hi,
    __nv_bfloat16* __restrict__ lo, int n4)
{
    int i = blockIdx.x * blockDim.x + threadIdx.x;
    if (i >= n4) return;
    float4 v = ((const float4*)in)[i];
    __nv_bfloat16 h0 = __float2bfloat16(v.x), h1 = __float2bfloat16(v.y);
    __nv_bfloat16 h2 = __float2bfloat16(v.z), h3 = __float2bfloat16(v.w);
    __nv_bfloat16 l0 = __float2bfloat16(v.x - __bfloat162float(h0));
    __nv_bfloat16 l1 = __float2bfloat16(v.y - __bfloat162float(h1));
    __nv_bfloat16 l2 = __float2bfloat16(v.z - __bfloat162float(h2));
    __nv_bfloat16 l3 = __float2bfloat16(v.w - __bfloat162float(h3));
    __nv_bfloat162* H = (__nv_bfloat162*)hi;
    __nv_bfloat162* L = (__nv_bfloat162*)lo;
    H[2 * i]     = __nv_bfloat162(h0, h1);
    H[2 * i + 1] = __nv_bfloat162(h2, h3);
    L[2 * i]     = __nv_bfloat162(l0, l1);
    L[2 * i + 1] = __nv_bfloat162(l2, l3);
}

// ---------------- split + transpose: W[K,N] fp32 -> [N,K] bf16 hi/lo ----------------
__global__ __launch_bounds__(256) void splitT_k(
    const float* __restrict__ W, __nv_bfloat16* __restrict__ Th,
    __nv_bfloat16* __restrict__ Tl)
{
    __shared__ float tile[32][33];
    int bx = blockIdx.x * 32, by = blockIdx.y * 32;
    int tx = threadIdx.x, ty = threadIdx.y;   // block (32,8)
    #pragma unroll
    for (int r = 0; r < 32; r += 8)
        tile[ty + r][tx] = W[(size_t)(by + ty + r) * DMODEL + bx + tx];
    __syncthreads();
    #pragma unroll
    for (int r = 0; r < 32; r += 8) {
        float v = tile[tx][ty + r];
        __nv_bfloat16 h = __float2bfloat16(v);
        __nv_bfloat16 l = __float2bfloat16(v - __bfloat162float(h));
        size_t o = (size_t)(bx + ty + r) * DMODEL + by + tx;
        Th[o] = h;
        Tl[o] = l;
    }
}

// ---------------- HMMA split-bf16 GEMM ----------------
// C[M,N] = A[M,K] @ B^T. A hi/lo [M,K], B hi/lo [N,K], both K-major bf16.
// CTA tile 128x128, BK=32, 256 threads (8 warps as 2m x 4n, warp tile 64x32).
// Smem tile: 128 rows x 64B, 16B chunks xor-swizzled by (row&3).
#define NCHUNK 64                 // K / 32
#define GTILE_B 8192              // one operand tile: 128*64B
#define GSTAGE_B (4 * GTILE_B)    // Ah, Al, Bh, Bl
#define GSMEM (2 * GSTAGE_B)      // 64 KB

__global__ __launch_bounds__(256, 1) void gemm_mma(
    const __nv_bfloat16* __restrict__ Ah, const __nv_bfloat16* __restrict__ Al,
    const __nv_bfloat16* __restrict__ Bh, const __nv_bfloat16* __restrict__ Bl,
    float* __restrict__ C, int mode)
{
    extern __shared__ __align__(128) char smem[];
    const uint32_t sbase = s2u(smem);

    const int t = threadIdx.x;
    const int lane = t & 31, wid = t >> 5;
    const int wm = wid >> 2;         // 0..1 (64 rows each)
    const int wn = wid & 3;          // 0..3 (32 cols each)
    const int n0 = blockIdx.x * 128;
    const int m0 = blockIdx.y * 128;

    const char* pAh = (const char*)(Ah + (size_t)m0 * DMODEL);
    const char* pAl = (const char*)(Al + (size_t)m0 * DMODEL);
    const char* pBh = (const char*)(Bh + (size_t)n0 * DMODEL);
    const char* pBl = (const char*)(Bl + (size_t)n0 * DMODEL);

    float acc[4][4][4];
    #pragma unroll
    for (int i = 0; i < 4; i++)
        #pragma unroll
        for (int j = 0; j < 4; j++)
            #pragma unroll
            for (int r = 0; r < 4; r++) acc[i][j][r] = 0.f;

    // ---- stage loader: chunk -> stage s
    auto load_stage = [&](int s, int chunk) {
        uint32_t base = sbase + (uint32_t)s * GSTAGE_B;
        #pragma unroll
        for (int half = 0; half < 2; half++) {
            int u = t + half * 256;       // 0..511
            int row = u >> 2, c = u & 3;
            uint32_t off = (uint32_t)(row * 64 + ((c ^ (row & 3)) * 16));
            size_t go = (size_t)row * 4096 + (size_t)chunk * 64 + c * 16;
            CPASYNC16(base + 0 * GTILE_B + off, pAh + go);
            CPASYNC16(base + 1 * GTILE_B + off, pAl + go);
            CPASYNC16(base + 2 * GTILE_B + off, pBh + go);
            CPASYNC16(base + 3 * GTILE_B + off, pBl + go);
        }
        CPCOMMIT();
    };

    load_stage(0, 0);

    // lane-derived fragment addresses (row part constant across chunks)
    const int arow_in = (lane & 15);       // A frag row within 16
    const int achk_hi = (lane >> 4);       // 0/1 -> k half
    const int brow_in = (lane & 7);        // B frag row within 8
    const int bchk_hi = ((lane >> 3) & 1);

    for (int ic = 0; ic < NCHUNK; ic++) {
        const int s = ic & 1;
        if (ic + 1 < NCHUNK) {
            load_stage(s ^ 1, ic + 1);
            CPWAIT1();
        } else {
            CPWAIT0();
        }
        __syncthreads();

        const uint32_t stb = sbase + (uint32_t)s * GSTAGE_B;
        #pragma unroll
        for (int ks = 0; ks < 2; ks++) {
            uint32_t ahf[4][4], alf[4][4];
            #pragma unroll
            for (int ms = 0; ms < 4; ms++) {
                int r = wm * 64 + ms * 16 + arow_in;
                uint32_t c = (uint32_t)((2 * ks + achk_hi) ^ (r & 3));
                uint32_t ad = stb + (uint32_t)(r * 64) + c * 16;
                LDSM4(ahf[ms][0], ahf[ms][1], ahf[ms][2], ahf[ms][3], ad + 0 * GTILE_B);
                LDSM4(alf[ms][0], alf[ms][1], alf[ms][2], alf[ms][3], ad + 1 * GTILE_B);
            }
            uint32_t bhf[4][2], blf[4][2];
            #pragma unroll
            for (int ns = 0; ns < 4; ns++) {
                int r = wn * 32 + ns * 8 + brow_in;
                uint32_t c = (uint32_t)((2 * ks + bchk_hi) ^ (r & 3));
                uint32_t bd = stb + (uint32_t)(r * 64) + c * 16;
                LDSM2(bhf[ns][0], bhf[ns][1], bd + 2 * GTILE_B);
                LDSM2(blf[ns][0], blf[ns][1], bd + 3 * GTILE_B);
            }
            #pragma unroll
            for (int ms = 0; ms < 4; ms++)
                #pragma unroll
                for (int ns = 0; ns < 4; ns++) {
                    MMA16816(acc[ms][ns], ahf[ms], bhf[ns]);
                    MMA16816(acc[ms][ns], ahf[ms], blf[ns]);
                    MMA16816(acc[ms][ns], alf[ms], bhf[ns]);
                }
        }
        __syncthreads();
    }

    // ---- epilogue: acc -> C
    #pragma unroll
    for (int ms = 0; ms < 4; ms++) {
        #pragma unroll
        for (int rh = 0; rh < 2; rh++) {
            int m = m0 + wm * 64 + ms * 16 + (lane >> 2) + rh * 8;
            #pragma unroll
            for (int ns = 0; ns < 4; ns++) {
                int n = n0 + wn * 32 + ns * 8 + 2 * (lane & 3);
                float2 v = rh ? make_float2(acc[ms][ns][2], acc[ms][ns][3])
                              : make_float2(acc[ms][ns][0], acc[ms][ns][1]);
                size_t idx;
                if (mode == 0) {
                    int b = m >> 11, si = m & 2047, h = n >> 7, d = n & 127;
                    idx = (((size_t)(b * NHEADS + h) * SEQ) + si) * HDIM + d;
                } else {
                    idx = (size_t)m * DMODEL + n;
                }
                *(float2*)(C + idx) = v;
            }
        }
    }
}

// ---------------- RoPE (in place on q and k, [B,H,S,hd]) ----------------
__global__ __launch_bounds__(256) void rope_k(
    float* __restrict__ q, float* __restrict__ k,
    const float* __restrict__ fcos, const float* __restrict__ fsin)
{
    int p = blockIdx.x * blockDim.x + threadIdx.x;
    int d = p & 63;
    int s = (p >> 6) & 2047;
    int base = (p >> 6) * 128 + d;
    float c  = fcos[s * 64 + d];
    float si = fsin[s * 64 + d];
    float q0 = q[base], q1 = q[base + 64];
    q[base]      = q0 * c - q1 * si;
    q[base + 64] = q1 * c + q0 * si;
    float k0 = k[base], k1 = k[base + 64];
    k[base]      = k0 * c - k1 * si;
    k[base + 64] = k1 * c + k0 * si;
}

// ---------------- Flash attention fp32, causal ----------------
#define ATT_SMEM ((2 * 64 * 128 + 64 * 65) * 4)

__global__ __launch_bounds__(128) void flash_k(
    const float* __restrict__ Q, const float* __restrict__ K,
    const float* __restrict__ V, float* __restrict__ O)
{
    extern __shared__ float sm[];
    float* Ks = sm;
    float* Vs = sm + 64 * 128;
    float* Ss = sm + 2 * 64 * 128;

    const int t    = threadIdx.x;
    const int row  = t >> 1;
    const int half = t & 1;
    const int d0   = half * 64;
    const int bh   = blockIdx.y;
    const int m0   = blockIdx.x * 64;

    const float qscale = 0.08838834764831845f * 1.4426950408889634f;

    const float* Qr = Q + ((size_t)bh * SEQ + m0 + row) * HDIM + d0;
    float q[64];
    #pragma unroll
    for (int i = 0; i < 16; i++) {
        float4 v = *(const float4*)(Qr + 4 * i);
        q[4 * i + 0] = v.x * qscale;
        q[4 * i + 1] = v.y * qscale;
        q[4 * i + 2] = v.z * qscale;
        q[4 * i + 3] = v.w * qscale;
    }

    float acc[64];
    #pragma unroll
    for (int d = 0; d < 64; d++) acc[d] = 0.f;
    float m_run = -1e30f, l = 0.f;

    const int ntiles = blockIdx.x + 1;
    for (int jt = 0; jt < ntiles; jt++) {
        const float4* Kb = (const float4*)(K + ((size_t)bh * SEQ + jt * 64) * HDIM);
        const float4* Vb = (const float4*)(V + ((size_t)bh * SEQ + jt * 64) * HDIM);
        #pragma unroll
        for (int i = 0; i < 16; i++) {
            int f = t + i * 128;
            ((float4*)Ks)[f] = Kb[f];
            ((float4*)Vs)[f] = Vb[f];
        }
        __syncthreads();

        const bool diag = (jt == blockIdx.x);
        float tmax = -1e30f;
        #pragma unroll 2
        for (int n = 0; n < 64; n++) {
            const float4* kr = (const float4*)(Ks + n * 128 + d0);
            float p0 = 0.f, p1 = 0.f, p2 = 0.f, p3 = 0.f;
            #pragma unroll
            for (int i = 0; i < 16; i++) {
                float4 kv = kr[i];
                p0 += q[4 * i + 0] * kv.x;
                p1 += q[4 * i + 1] * kv.y;
                p2 += q[4 * i + 2] * kv.z;
                p3 += q[4 * i + 3] * kv.w;
            }
            float partial = (p0 + p1) + (p2 + p3);
            float full = partial + __shfl_xor_sync(0xffffffffu, partial, 1);
            if (diag && n > row) full = -1e30f;
            if (half == 0) Ss[row * 65 + n] = full;
            tmax = fmaxf(tmax, full);
        }
        __syncwarp();

        float m_new = fmaxf(m_run, tmax);
        float corr  = exp2f(m_run - m_new);
        l *= corr;
        #pragma unroll
        for (int d = 0; d < 64; d++) acc[d] *= corr;

        #pragma unroll 2
        for (int n = 0; n < 64; n++) {
            float p = exp2f(Ss[row * 65 + n] - m_new);
            l += p;
            const float4* vr = (const float4*)(Vs + n * 128 + d0);
            #pragma unroll
            for (int i = 0; i < 16; i++) {
                float4 vv = vr[i];
                acc[4 * i + 0] += p * vv.x;
                acc[4 * i + 1] += p * vv.y;
                acc[4 * i + 2] += p * vv.z;
                acc[4 * i + 3] += p * vv.w;
            }
        }
        m_run = m_new;
        __syncthreads();
    }

    const float inv = 1.f / l;
    const int b = bh >> 4, h = bh & 15;
    float* Or = O + ((size_t)(b * SEQ) + m0 + row) * DMODEL + h * HDIM + d0;
    #pragma unroll
    for (int i = 0; i < 16; i++) {
        float4 v = make_float4(acc[4 * i] * inv, acc[4 * i + 1] * inv,
                               acc[4 * i + 2] * inv, acc[4 * i + 3] * inv);
        *(float4*)(Or + 4 * i) = v;
    }
}

// ---------------- launch ----------------
extern "C" void kernel_launch(void* const* d_in, const int* in_sizes, int n_in,
                              void* d_out, int out_size)
{
    (void)in_sizes; (void)n_in; (void)out_size;
    const float* x    = (const float*)d_in[0];
    const float* fcos = (const float*)d_in[1];
    const float* fsin = (const float*)d_in[2];
    const float* wq   = (const float*)d_in[3];
    const float* wk   = (const float*)d_in[4];
    const float* wv   = (const float*)d_in[5];
    const float* wo   = (const float*)d_in[6];
    float* out = (float*)d_out;

    float *q, *k, *v, *att;
    __nv_bfloat16 *xh, *xl, *ath, *atl;
    __nv_bfloat16 *wqh, *wql, *wkh, *wkl, *wvh, *wvl, *woh, *wol;
    cudaGetSymbolAddress((void**)&q,   g_q);
    cudaGetSymbolAddress((void**)&k,   g_k);
    cudaGetSymbolAddress((void**)&v,   g_v);
    cudaGetSymbolAddress((void**)&att, g_att);
    cudaGetSymbolAddress((void**)&xh,  g_xh);
    cudaGetSymbolAddress((void**)&xl,  g_xl);
    cudaGetSymbolAddress((void**)&ath, g_ath);
    cudaGetSymbolAddress((void**)&atl, g_atl);
    cudaGetSymbolAddress((void**)&wqh, g_wqh);
    cudaGetSymbolAddress((void**)&wql, g_wql);
    cudaGetSymbolAddress((void**)&wkh, g_wkh);
    cudaGetSymbolAddress((void**)&wkl, g_wkl);
    cudaGetSymbolAddress((void**)&wvh, g_wvh);
    cudaGetSymbolAddress((void**)&wvl, g_wvl);
    cudaGetSymbolAddress((void**)&woh, g_woh);
    cudaGetSymbolAddress((void**)&wol, g_wol);

    cudaFuncSetAttribute(gemm_mma, cudaFuncAttributeMaxDynamicSharedMemorySize, GSMEM);
    cudaFuncSetAttribute(flash_k, cudaFuncAttributeMaxDynamicSharedMemorySize, ATT_SMEM);

    // conversions
    split_k<<<QKV_ELEMS / 4 / 256, 256>>>(x, xh, xl, QKV_ELEMS / 4);
    dim3 tg(DMODEL / 32, DMODEL / 32), tb(32, 8);
    splitT_k<<<tg, tb>>>(wq, wqh, wql);
    splitT_k<<<tg, tb>>>(wk, wkh, wkl);
    splitT_k<<<tg, tb>>>(wv, wvh, wvl);
    splitT_k<<<tg, tb>>>(wo, woh, wol);

    dim3 gg(DMODEL / 128, ROWS / 128);   // (16, 32)
    gemm_mma<<<gg, 256, GSMEM>>>(xh, xl, wqh, wql, q, 0);
    gemm_mma<<<gg, 256, GSMEM>>>(xh, xl, wkh, wkl, k, 0);
    gemm_mma<<<gg, 256, GSMEM>>>(xh, xl, wvh, wvl, v, 0);

    rope_k<<<(BATCH * NHEADS * SEQ * 64) / 256, 256>>>(q, k, fcos, fsin);

    flash_k<<<dim3(SEQ / 64, BATCH * NHEADS), 128, ATT_SMEM>>>(q, k, v, att);

    split_k<<<QKV_ELEMS / 4 / 256, 256>>>(att, ath, atl, QKV_ELEMS / 4);
    gemm_mma<<<gg, 256, GSMEM>>>(ath, atl, woh, wol, out, 1);
}

// round 7
// speedup vs baseline: 3.2650x; 2.2368x over previous
#include <cuda_runtime.h>
#include <cuda_bf16.h>
#include <cstdint>

// Problem constants
#define BATCH 2
#define SEQ   2048
#define DMODEL 2048
#define NHEADS 16
#define HDIM  128
#define ROWS  (BATCH * SEQ)          // 4096
#define QKV_ELEMS (ROWS * DMODEL)    // 8388608
#define WELEMS (DMODEL * DMODEL)     // 4194304

// ---------------- scratch (device globals; no allocation) ----------------
__device__ float g_q[QKV_ELEMS];     // fp32 [B,H,S,hd] (pre-rope)
__device__ float g_k[QKV_ELEMS];

__device__ __align__(256) __nv_bfloat16 g_xh[QKV_ELEMS];
__device__ __align__(256) __nv_bfloat16 g_xl[QKV_ELEMS];
__device__ __align__(256) __nv_bfloat16 g_ath[QKV_ELEMS];
__device__ __align__(256) __nv_bfloat16 g_atl[QKV_ELEMS];
__device__ __align__(256) __nv_bfloat16 g_qh[QKV_ELEMS], g_ql[QKV_ELEMS];
__device__ __align__(256) __nv_bfloat16 g_kh[QKV_ELEMS], g_kl[QKV_ELEMS];
__device__ __align__(256) __nv_bfloat16 g_vh[QKV_ELEMS], g_vl[QKV_ELEMS];
// transposed weights [N,K] hi/lo
__device__ __align__(256) __nv_bfloat16 g_wqh[WELEMS], g_wql[WELEMS];
__device__ __align__(256) __nv_bfloat16 g_wkh[WELEMS], g_wkl[WELEMS];
__device__ __align__(256) __nv_bfloat16 g_wvh[WELEMS], g_wvl[WELEMS];
__device__ __align__(256) __nv_bfloat16 g_woh[WELEMS], g_wol[WELEMS];

// ---------------- PTX helpers (sm_80-class only) ----------------
__device__ __forceinline__ uint32_t s2u(const void* p) {
    uint32_t a;
    asm("{ .reg .u64 t; cvta.to.shared.u64 t, %1; cvt.u32.u64 %0, t; }"
        : "=r"(a) : "l"(p));
    return a;
}
#define CPASYNC16(sa, g) asm volatile("cp.async.cg.shared.global [%0], [%1], 16;" :: "r"(sa), "l"(g))
#define CPCOMMIT()  asm volatile("cp.async.commit_group;" ::: "memory")
#define CPWAIT1()   asm volatile("cp.async.wait_group 1;" ::: "memory")
#define CPWAIT0()   asm volatile("cp.async.wait_group 0;" ::: "memory")

#define LDSM4(r0, r1, r2, r3, a) \
    asm volatile("ldmatrix.sync.aligned.m8n8.x4.shared.b16 {%0,%1,%2,%3}, [%4];" \
                 : "=r"(r0), "=r"(r1), "=r"(r2), "=r"(r3) : "r"(a))
#define LDSM2(r0, r1, a) \
    asm volatile("ldmatrix.sync.aligned.m8n8.x2.shared.b16 {%0,%1}, [%2];" \
                 : "=r"(r0), "=r"(r1) : "r"(a))
#define LDSM4T(r, a) \
    asm volatile("ldmatrix.sync.aligned.m8n8.x4.trans.shared.b16 {%0,%1,%2,%3}, [%4];" \
                 : "=r"((r)[0]), "=r"((r)[1]), "=r"((r)[2]), "=r"((r)[3]) : "r"(a))

#define MMA16816(c, a, b) \
    asm volatile("mma.sync.aligned.m16n8k16.row.col.f32.bf16.bf16.f32 " \
                 "{%0,%1,%2,%3}, {%4,%5,%6,%7}, {%8,%9}, {%0,%1,%2,%3};" \
                 : "+f"((c)[0]), "+f"((c)[1]), "+f"((c)[2]), "+f"((c)[3]) \
                 : "r"((a)[0]), "r"((a)[1]), "r"((a)[2]), "r"((a)[3]), \
                   "r"((b)[0]), "r"((b)[1]))

// pack two fp32 into hi-bf16x2 and lo-bf16x2 (lo = residual)
__device__ __forceinline__ void split2(float a, float b, uint32_t& h, uint32_t& l) {
    __nv_bfloat16 ha = __float2bfloat16(a), hb = __float2bfloat16(b);
    float la = a - __bfloat162float(ha), lb = b - __bfloat162float(hb);
    __nv_bfloat162 H(ha, hb), L(__float2bfloat16(la), __float2bfloat16(lb));
    h = *(uint32_t*)&H;
    l = *(uint32_t*)&L;
}

// ---------------- split conversion: fp32 -> bf16 hi/lo ----------------
__global__ __launch_bounds__(256) void split_k(
    const float* __restrict__ in, __nv_bfloat16* __restrict__ hi,
    __nv_bfloat16* __restrict__ lo, int n4)
{
    int i = blockIdx.x * blockDim.x + threadIdx.x;
    if (i >= n4) return;
    float4 v = ((const float4*)in)[i];
    uint32_t h0, l0, h1, l1;
    split2(v.x, v.y, h0, l0);
    split2(v.z, v.w, h1, l1);
    uint32_t* H = (uint32_t*)hi;
    uint32_t* L = (uint32_t*)lo;
    H[2 * i] = h0; H[2 * i + 1] = h1;
    L[2 * i] = l0; L[2 * i + 1] = l1;
}

// ---------------- split + transpose: W[K,N] fp32 -> [N,K] bf16 hi/lo ----------------
__global__ __launch_bounds__(256) void splitT_k(
    const float* __restrict__ W, __nv_bfloat16* __restrict__ Th,
    __nv_bfloat16* __restrict__ Tl)
{
    __shared__ float tile[32][33];
    int bx = blockIdx.x * 32, by = blockIdx.y * 32;
    int tx = threadIdx.x, ty = threadIdx.y;   // block (32,8)
    #pragma unroll
    for (int r = 0; r < 32; r += 8)
        tile[ty + r][tx] = W[(size_t)(by + ty + r) * DMODEL + bx + tx];
    __syncthreads();
    #pragma unroll
    for (int r = 0; r < 32; r += 8) {
        float v = tile[tx][ty + r];
        __nv_bfloat16 h = __float2bfloat16(v);
        __nv_bfloat16 l = __float2bfloat16(v - __bfloat162float(h));
        size_t o = (size_t)(bx + ty + r) * DMODEL + by + tx;
        Th[o] = h;
        Tl[o] = l;
    }
}

// ---------------- HMMA split-bf16 GEMM ----------------
// mode 0: fp32 out, QKV layout. mode 1: fp32 out, row-major. mode 2: bf16 hi/lo out, QKV layout.
#define NCHUNK 64
#define GTILE_B 8192
#define GSTAGE_B (4 * GTILE_B)
#define GSMEM (2 * GSTAGE_B)

__global__ __launch_bounds__(256, 1) void gemm_mma(
    const __nv_bfloat16* __restrict__ Ah, const __nv_bfloat16* __restrict__ Al,
    const __nv_bfloat16* __restrict__ Bh, const __nv_bfloat16* __restrict__ Bl,
    float* __restrict__ C, __nv_bfloat16* __restrict__ Ch,
    __nv_bfloat16* __restrict__ Cl, int mode)
{
    extern __shared__ __align__(128) char smem[];
    const uint32_t sbase = s2u(smem);

    const int t = threadIdx.x;
    const int lane = t & 31, wid = t >> 5;
    const int wm = wid >> 2;
    const int wn = wid & 3;
    const int n0 = blockIdx.x * 128;
    const int m0 = blockIdx.y * 128;

    const char* pAh = (const char*)(Ah + (size_t)m0 * DMODEL);
    const char* pAl = (const char*)(Al + (size_t)m0 * DMODEL);
    const char* pBh = (const char*)(Bh + (size_t)n0 * DMODEL);
    const char* pBl = (const char*)(Bl + (size_t)n0 * DMODEL);

    float acc[4][4][4];
    #pragma unroll
    for (int i = 0; i < 4; i++)
        #pragma unroll
        for (int j = 0; j < 4; j++)
            #pragma unroll
            for (int r = 0; r < 4; r++) acc[i][j][r] = 0.f;

    auto load_stage = [&](int s, int chunk) {
        uint32_t base = sbase + (uint32_t)s * GSTAGE_B;
        #pragma unroll
        for (int half = 0; half < 2; half++) {
            int u = t + half * 256;
            int row = u >> 2, c = u & 3;
            uint32_t off = (uint32_t)(row * 64 + ((c ^ (row & 3)) * 16));
            size_t go = (size_t)row * 4096 + (size_t)chunk * 64 + c * 16;
            CPASYNC16(base + 0 * GTILE_B + off, pAh + go);
            CPASYNC16(base + 1 * GTILE_B + off, pAl + go);
            CPASYNC16(base + 2 * GTILE_B + off, pBh + go);
            CPASYNC16(base + 3 * GTILE_B + off, pBl + go);
        }
        CPCOMMIT();
    };

    load_stage(0, 0);

    const int arow_in = (lane & 15);
    const int achk_hi = (lane >> 4);
    const int brow_in = (lane & 7);
    const int bchk_hi = ((lane >> 3) & 1);

    for (int ic = 0; ic < NCHUNK; ic++) {
        const int s = ic & 1;
        if (ic + 1 < NCHUNK) {
            load_stage(s ^ 1, ic + 1);
            CPWAIT1();
        } else {
            CPWAIT0();
        }
        __syncthreads();

        const uint32_t stb = sbase + (uint32_t)s * GSTAGE_B;
        #pragma unroll
        for (int ks = 0; ks < 2; ks++) {
            uint32_t ahf[4][4], alf[4][4];
            #pragma unroll
            for (int ms = 0; ms < 4; ms++) {
                int r = wm * 64 + ms * 16 + arow_in;
                uint32_t c = (uint32_t)((2 * ks + achk_hi) ^ (r & 3));
                uint32_t ad = stb + (uint32_t)(r * 64) + c * 16;
                LDSM4(ahf[ms][0], ahf[ms][1], ahf[ms][2], ahf[ms][3], ad + 0 * GTILE_B);
                LDSM4(alf[ms][0], alf[ms][1], alf[ms][2], alf[ms][3], ad + 1 * GTILE_B);
            }
            uint32_t bhf[4][2], blf[4][2];
            #pragma unroll
            for (int ns = 0; ns < 4; ns++) {
                int r = wn * 32 + ns * 8 + brow_in;
                uint32_t c = (uint32_t)((2 * ks + bchk_hi) ^ (r & 3));
                uint32_t bd = stb + (uint32_t)(r * 64) + c * 16;
                LDSM2(bhf[ns][0], bhf[ns][1], bd + 2 * GTILE_B);
                LDSM2(blf[ns][0], blf[ns][1], bd + 3 * GTILE_B);
            }
            #pragma unroll
            for (int ms = 0; ms < 4; ms++)
                #pragma unroll
                for (int ns = 0; ns < 4; ns++) {
                    MMA16816(acc[ms][ns], ahf[ms], bhf[ns]);
                    MMA16816(acc[ms][ns], ahf[ms], blf[ns]);
                    MMA16816(acc[ms][ns], alf[ms], bhf[ns]);
                }
        }
        __syncthreads();
    }

    #pragma unroll
    for (int ms = 0; ms < 4; ms++) {
        #pragma unroll
        for (int rh = 0; rh < 2; rh++) {
            int m = m0 + wm * 64 + ms * 16 + (lane >> 2) + rh * 8;
            #pragma unroll
            for (int ns = 0; ns < 4; ns++) {
                int n = n0 + wn * 32 + ns * 8 + 2 * (lane & 3);
                float va = rh ? acc[ms][ns][2] : acc[ms][ns][0];
                float vb = rh ? acc[ms][ns][3] : acc[ms][ns][1];
                if (mode == 1) {
                    *(float2*)(C + (size_t)m * DMODEL + n) = make_float2(va, vb);
                } else {
                    int b = m >> 11, si = m & 2047, h = n >> 7, d = n & 127;
                    size_t idx = (((size_t)(b * NHEADS + h) * SEQ) + si) * HDIM + d;
                    if (mode == 0) {
                        *(float2*)(C + idx) = make_float2(va, vb);
                    } else {
                        uint32_t hh, ll;
                        split2(va, vb, hh, ll);
                        *(uint32_t*)(Ch + idx) = hh;
                        *(uint32_t*)(Cl + idx) = ll;
                    }
                }
            }
        }
    }
}

// ---------------- RoPE + split: fp32 q,k -> bf16 hi/lo (q scaled) ----------------
__global__ __launch_bounds__(256) void rope_split(
    const float* __restrict__ q, const float* __restrict__ k,
    const float* __restrict__ fcos, const float* __restrict__ fsin,
    __nv_bfloat16* __restrict__ qh, __nv_bfloat16* __restrict__ ql,
    __nv_bfloat16* __restrict__ kh, __nv_bfloat16* __restrict__ kl)
{
    int p = blockIdx.x * blockDim.x + threadIdx.x;
    int d = p & 63;
    int s = (p >> 6) & 2047;
    int base = (p >> 6) * 128 + d;
    float c  = fcos[s * 64 + d];
    float si = fsin[s * 64 + d];
    const float qs = 0.08838834764831845f * 1.4426950408889634f;

    float q0 = q[base], q1 = q[base + 64];
    float a0 = (q0 * c - q1 * si) * qs;
    float a1 = (q1 * c + q0 * si) * qs;
    __nv_bfloat16 h0 = __float2bfloat16(a0), h1 = __float2bfloat16(a1);
    qh[base] = h0;      ql[base]      = __float2bfloat16(a0 - __bfloat162float(h0));
    qh[base + 64] = h1; ql[base + 64] = __float2bfloat16(a1 - __bfloat162float(h1));

    float k0 = k[base], k1 = k[base + 64];
    float b0 = k0 * c - k1 * si;
    float b1 = k1 * c + k0 * si;
    __nv_bfloat16 g0 = __float2bfloat16(b0), g1 = __float2bfloat16(b1);
    kh[base] = g0;      kl[base]      = __float2bfloat16(b0 - __bfloat162float(g0));
    kh[base + 64] = g1; kl[base + 64] = __float2bfloat16(b1 - __bfloat162float(g1));
}

// ---------------- HMMA flash attention, causal, split-bf16 ----------------
// CTA: 128 q rows, 8 warps x 16 rows. K/V 64-key tiles, double buffered.
// smem: Qh 32K | Ql 32K | 2 stages x (Kh 16K | Kl 16K | Vh 16K | Vl 16K)
#define FSM_Q   0
#define FSM_QL  32768
#define FSM_ST  65536
#define FSM_STG 65536
#define FSM_TOTAL (65536 + 2 * 65536)   // 196608

__global__ __launch_bounds__(256, 1) void flash_mma(
    const __nv_bfloat16* __restrict__ Qh, const __nv_bfloat16* __restrict__ Ql,
    const __nv_bfloat16* __restrict__ Kh, const __nv_bfloat16* __restrict__ Kl,
    const __nv_bfloat16* __restrict__ Vh, const __nv_bfloat16* __restrict__ Vl,
    __nv_bfloat16* __restrict__ Oh, __nv_bfloat16* __restrict__ Ol)
{
    extern __shared__ __align__(128) char smem[];
    const uint32_t sb = s2u(smem);
    const int t = threadIdx.x, lane = t & 31, wid = t >> 5;
    const int bh = blockIdx.y;
    const int m0 = blockIdx.x * 128;

    // load Q tile (128 rows x 256B, hi+lo)
    {
        const char* gqh = (const char*)(Qh + ((size_t)bh * SEQ + m0) * HDIM);
        const char* gql = (const char*)(Ql + ((size_t)bh * SEQ + m0) * HDIM);
        #pragma unroll
        for (int i = 0; i < 8; i++) {
            int u = t + i * 256;
            int r = u >> 4, g = u & 15;
            uint32_t off = (uint32_t)(r * 256 + ((g ^ (r & 7)) * 16));
            size_t go = (size_t)r * 256 + g * 16;
            CPASYNC16(sb + FSM_Q + off, gqh + go);
            CPASYNC16(sb + FSM_QL + off, gql + go);
        }
        CPCOMMIT();
    }

    const char* gkh = (const char*)(Kh + (size_t)bh * SEQ * HDIM);
    const char* gkl = (const char*)(Kl + (size_t)bh * SEQ * HDIM);
    const char* gvh = (const char*)(Vh + (size_t)bh * SEQ * HDIM);
    const char* gvl = (const char*)(Vl + (size_t)bh * SEQ * HDIM);

    auto load_kv = [&](int s, int jt) {
        uint32_t stb = sb + FSM_ST + (uint32_t)s * FSM_STG;
        size_t base = (size_t)jt * 64 * 256;
        #pragma unroll
        for (int i = 0; i < 4; i++) {
            int u = t + i * 256;
            int r = u >> 4, g = u & 15;
            uint32_t off = (uint32_t)(r * 256 + ((g ^ (r & 7)) * 16));
            size_t go = base + (size_t)r * 256 + g * 16;
            CPASYNC16(stb + 0     + off, gkh + go);
            CPASYNC16(stb + 16384 + off, gkl + go);
            CPASYNC16(stb + 32768 + off, gvh + go);
            CPASYNC16(stb + 49152 + off, gvl + go);
        }
        CPCOMMIT();
    };

    load_kv(0, 0);

    float oacc[16][4];
    #pragma unroll
    for (int i = 0; i < 16; i++)
        #pragma unroll
        for (int j = 0; j < 4; j++) oacc[i][j] = 0.f;
    float mrun0 = -1e30f, mrun1 = -1e30f, ls0 = 0.f, ls1 = 0.f;

    const int wrow = m0 + wid * 16;
    const int r0 = wrow + (lane >> 2), r1 = r0 + 8;
    const int ntiles = m0 / 64 + 2;

    for (int jt = 0; jt < ntiles; jt++) {
        const int s = jt & 1;
        if (jt + 1 < ntiles) { load_kv(s ^ 1, jt + 1); CPWAIT1(); }
        else                 { CPWAIT0(); }
        __syncthreads();

        const int k0 = jt * 64;
        if (k0 <= wrow + 15) {
            const uint32_t stb = sb + FSM_ST + (uint32_t)s * FSM_STG;
            float sacc[8][4];
            #pragma unroll
            for (int i = 0; i < 8; i++)
                #pragma unroll
                for (int j = 0; j < 4; j++) sacc[i][j] = 0.f;

            // ---- S = Q K^T (3-term split)
            const int rowA = wid * 16 + (lane & 15);
            const int rbB = (lane & 7) | ((lane >> 1) & 8);
            #pragma unroll
            for (int k8 = 0; k8 < 8; k8++) {
                int gA = 2 * k8 + (lane >> 4);
                uint32_t aoff = (uint32_t)(rowA * 256 + ((gA ^ (rowA & 7)) * 16));
                uint32_t ah[4], al[4];
                LDSM4(ah[0], ah[1], ah[2], ah[3], sb + FSM_Q + aoff);
                LDSM4(al[0], al[1], al[2], al[3], sb + FSM_QL + aoff);
                int gB = 2 * k8 + ((lane >> 3) & 1);
                #pragma unroll
                for (int np = 0; np < 4; np++) {
                    int rowB = np * 16 + rbB;
                    uint32_t boff = (uint32_t)(rowB * 256 + ((gB ^ (rowB & 7)) * 16));
                    uint32_t bh2[4], bl2[4];
                    LDSM4(bh2[0], bh2[1], bh2[2], bh2[3], stb + 0 + boff);
                    LDSM4(bl2[0], bl2[1], bl2[2], bl2[3], stb + 16384 + boff);
                    MMA16816(sacc[2 * np],     ah, &bh2[0]);
                    MMA16816(sacc[2 * np],     ah, &bl2[0]);
                    MMA16816(sacc[2 * np],     al, &bh2[0]);
                    MMA16816(sacc[2 * np + 1], ah, &bh2[2]);
                    MMA16816(sacc[2 * np + 1], ah, &bl2[2]);
                    MMA16816(sacc[2 * np + 1], al, &bh2[2]);
                }
            }

            // ---- causal mask
            if (k0 + 63 > wrow) {
                #pragma unroll
                for (int nt = 0; nt < 8; nt++) {
                    int c = k0 + nt * 8 + 2 * (lane & 3);
                    if (c     > r0) sacc[nt][0] = -1e30f;
                    if (c + 1 > r0) sacc[nt][1] = -1e30f;
                    if (c     > r1) sacc[nt][2] = -1e30f;
                    if (c + 1 > r1) sacc[nt][3] = -1e30f;
                }
            }

            // ---- online softmax (log2 domain; qscale*log2e already in Q)
            float ml0 = -1e30f, ml1 = -1e30f;
            #pragma unroll
            for (int nt = 0; nt < 8; nt++) {
                ml0 = fmaxf(ml0, fmaxf(sacc[nt][0], sacc[nt][1]));
                ml1 = fmaxf(ml1, fmaxf(sacc[nt][2], sacc[nt][3]));
            }
            ml0 = fmaxf(ml0, __shfl_xor_sync(0xffffffffu, ml0, 1));
            ml0 = fmaxf(ml0, __shfl_xor_sync(0xffffffffu, ml0, 2));
            ml1 = fmaxf(ml1, __shfl_xor_sync(0xffffffffu, ml1, 1));
            ml1 = fmaxf(ml1, __shfl_xor_sync(0xffffffffu, ml1, 2));
            float mn0 = fmaxf(mrun0, ml0), mn1 = fmaxf(mrun1, ml1);
            float c0 = exp2f(mrun0 - mn0), c1 = exp2f(mrun1 - mn1);
            mrun0 = mn0; mrun1 = mn1;
            ls0 *= c0; ls1 *= c1;
            #pragma unroll
            for (int nt = 0; nt < 16; nt++) {
                oacc[nt][0] *= c0; oacc[nt][1] *= c0;
                oacc[nt][2] *= c1; oacc[nt][3] *= c1;
            }
            float ps0 = 0.f, ps1 = 0.f;
            #pragma unroll
            for (int nt = 0; nt < 8; nt++) {
                sacc[nt][0] = exp2f(sacc[nt][0] - mn0);
                sacc[nt][1] = exp2f(sacc[nt][1] - mn0);
                sacc[nt][2] = exp2f(sacc[nt][2] - mn1);
                sacc[nt][3] = exp2f(sacc[nt][3] - mn1);
                ps0 += sacc[nt][0] + sacc[nt][1];
                ps1 += sacc[nt][2] + sacc[nt][3];
            }
            ls0 += ps0; ls1 += ps1;

            // ---- O += P V (3-term split); P C-frags repack as A-frags
            #pragma unroll
            for (int j = 0; j < 4; j++) {
                uint32_t pah[4], pal[4];
                split2(sacc[2 * j][0],     sacc[2 * j][1],     pah[0], pal[0]);
                split2(sacc[2 * j][2],     sacc[2 * j][3],     pah[1], pal[1]);
                split2(sacc[2 * j + 1][0], sacc[2 * j + 1][1], pah[2], pal[2]);
                split2(sacc[2 * j + 1][2], sacc[2 * j + 1][3], pah[3], pal[3]);
                int rv = 16 * j + (lane & 15);
                #pragma unroll
                for (int dp = 0; dp < 8; dp++) {
                    int gV = 2 * dp + (lane >> 4);
                    uint32_t voff = (uint32_t)(rv * 256 + ((gV ^ (rv & 7)) * 16));
                    uint32_t vh2[4], vl2[4];
                    LDSM4T(vh2, stb + 32768 + voff);
                    LDSM4T(vl2, stb + 49152 + voff);
                    MMA16816(oacc[2 * dp],     pah, &vh2[0]);
                    MMA16816(oacc[2 * dp],     pah, &vl2[0]);
                    MMA16816(oacc[2 * dp],     pal, &vh2[0]);
                    MMA16816(oacc[2 * dp + 1], pah, &vh2[2]);
                    MMA16816(oacc[2 * dp + 1], pah, &vl2[2]);
                    MMA16816(oacc[2 * dp + 1], pal, &vh2[2]);
                }
            }
        }
        __syncthreads();
    }

    // ---- epilogue: normalize, split to bf16 hi/lo, write att [B*S, H*hd]
    float lt0 = ls0 + __shfl_xor_sync(0xffffffffu, ls0, 1);
    lt0 += __shfl_xor_sync(0xffffffffu, lt0, 2);
    float lt1 = ls1 + __shfl_xor_sync(0xffffffffu, ls1, 1);
    lt1 += __shfl_xor_sync(0xffffffffu, lt1, 2);
    float inv0 = 1.f / lt0, inv1 = 1.f / lt1;

    const int b = bh >> 4, h = bh & 15;
    size_t base0 = ((size_t)(b * SEQ) + r0) * DMODEL + h * HDIM;
    size_t base1 = base0 + (size_t)8 * DMODEL;
    #pragma unroll
    for (int nt = 0; nt < 16; nt++) {
        int d = nt * 8 + 2 * (lane & 3);
        uint32_t hh, ll;
        split2(oacc[nt][0] * inv0, oacc[nt][1] * inv0, hh, ll);
        *(uint32_t*)(Oh + base0 + d) = hh;
        *(uint32_t*)(Ol + base0 + d) = ll;
        split2(oacc[nt][2] * inv1, oacc[nt][3] * inv1, hh, ll);
        *(uint32_t*)(Oh + base1 + d) = hh;
        *(uint32_t*)(Ol + base1 + d) = ll;
    }
}

// ---------------- launch ----------------
extern "C" void kernel_launch(void* const* d_in, const int* in_sizes, int n_in,
                              void* d_out, int out_size)
{
    (void)in_sizes; (void)n_in; (void)out_size;
    const float* x    = (const float*)d_in[0];
    const float* fcos = (const float*)d_in[1];
    const float* fsin = (const float*)d_in[2];
    const float* wq   = (const float*)d_in[3];
    const float* wk   = (const float*)d_in[4];
    const float* wv   = (const float*)d_in[5];
    const float* wo   = (const float*)d_in[6];
    float* out = (float*)d_out;

    float *q, *k;
    __nv_bfloat16 *xh, *xl, *ath, *atl, *qh, *ql, *kh, *kl, *vh, *vl;
    __nv_bfloat16 *wqh, *wql, *wkh, *wkl, *wvh, *wvl, *woh, *wol;
    cudaGetSymbolAddress((void**)&q,   g_q);
    cudaGetSymbolAddress((void**)&k,   g_k);
    cudaGetSymbolAddress((void**)&xh,  g_xh);
    cudaGetSymbolAddress((void**)&xl,  g_xl);
    cudaGetSymbolAddress((void**)&ath, g_ath);
    cudaGetSymbolAddress((void**)&atl, g_atl);
    cudaGetSymbolAddress((void**)&qh,  g_qh);
    cudaGetSymbolAddress((void**)&ql,  g_ql);
    cudaGetSymbolAddress((void**)&kh,  g_kh);
    cudaGetSymbolAddress((void**)&kl,  g_kl);
    cudaGetSymbolAddress((void**)&vh,  g_vh);
    cudaGetSymbolAddress((void**)&vl,  g_vl);
    cudaGetSymbolAddress((void**)&wqh, g_wqh);
    cudaGetSymbolAddress((void**)&wql, g_wql);
    cudaGetSymbolAddress((void**)&wkh, g_wkh);
    cudaGetSymbolAddress((void**)&wkl, g_wkl);
    cudaGetSymbolAddress((void**)&wvh, g_wvh);
    cudaGetSymbolAddress((void**)&wvl, g_wvl);
    cudaGetSymbolAddress((void**)&woh, g_woh);
    cudaGetSymbolAddress((void**)&wol, g_wol);

    cudaFuncSetAttribute(gemm_mma, cudaFuncAttributeMaxDynamicSharedMemorySize, GSMEM);
    cudaFuncSetAttribute(flash_mma, cudaFuncAttributeMaxDynamicSharedMemorySize, FSM_TOTAL);

    // conversions
    split_k<<<QKV_ELEMS / 4 / 256, 256>>>(x, xh, xl, QKV_ELEMS / 4);
    dim3 tg(DMODEL / 32, DMODEL / 32), tb(32, 8);
    splitT_k<<<tg, tb>>>(wq, wqh, wql);
    splitT_k<<<tg, tb>>>(wk, wkh, wkl);
    splitT_k<<<tg, tb>>>(wv, wvh, wvl);
    splitT_k<<<tg, tb>>>(wo, woh, wol);

    dim3 gg(DMODEL / 128, ROWS / 128);   // (16, 32)
    gemm_mma<<<gg, 256, GSMEM>>>(xh, xl, wqh, wql, q, nullptr, nullptr, 0);
    gemm_mma<<<gg, 256, GSMEM>>>(xh, xl, wkh, wkl, k, nullptr, nullptr, 0);
    gemm_mma<<<gg, 256, GSMEM>>>(xh, xl, wvh, wvl, nullptr, vh, vl, 2);

    rope_split<<<(BATCH * NHEADS * SEQ * 64) / 256, 256>>>(q, k, fcos, fsin,
                                                           qh, ql, kh, kl);

    flash_mma<<<dim3(SEQ / 128, BATCH * NHEADS), 256, FSM_TOTAL>>>(
        qh, ql, kh, kl, vh, vl, ath, atl);

    gemm_mma<<<gg, 256, GSMEM>>>(ath, atl, woh, wol, out, nullptr, nullptr, 1);
}

// round 8
// speedup vs baseline: 3.6662x; 1.1229x over previous
#include <cuda_runtime.h>
#include <cuda_bf16.h>
#include <cstdint>

// Problem constants
#define BATCH 2
#define SEQ   2048
#define DMODEL 2048
#define NHEADS 16
#define HDIM  128
#define ROWS  (BATCH * SEQ)          // 4096
#define QKV_ELEMS (ROWS * DMODEL)    // 8388608
#define WELEMS (DMODEL * DMODEL)     // 4194304

// ---------------- scratch (device globals; no allocation) ----------------
__device__ float g_q[QKV_ELEMS];     // fp32 [B,H,S,hd] (pre-rope)
__device__ float g_k[QKV_ELEMS];

__device__ __align__(256) __nv_bfloat16 g_xh[QKV_ELEMS];
__device__ __align__(256) __nv_bfloat16 g_xl[QKV_ELEMS];
__device__ __align__(256) __nv_bfloat16 g_ath[QKV_ELEMS];
__device__ __align__(256) __nv_bfloat16 g_atl[QKV_ELEMS];
__device__ __align__(256) __nv_bfloat16 g_qh[QKV_ELEMS], g_ql[QKV_ELEMS];
__device__ __align__(256) __nv_bfloat16 g_kh[QKV_ELEMS], g_kl[QKV_ELEMS];
__device__ __align__(256) __nv_bfloat16 g_vh[QKV_ELEMS], g_vl[QKV_ELEMS];
// transposed weights [N,K] hi/lo
__device__ __align__(256) __nv_bfloat16 g_wqh[WELEMS], g_wql[WELEMS];
__device__ __align__(256) __nv_bfloat16 g_wkh[WELEMS], g_wkl[WELEMS];
__device__ __align__(256) __nv_bfloat16 g_wvh[WELEMS], g_wvl[WELEMS];
__device__ __align__(256) __nv_bfloat16 g_woh[WELEMS], g_wol[WELEMS];

// ---------------- PTX helpers (sm_80-class only) ----------------
__device__ __forceinline__ uint32_t s2u(const void* p) {
    uint32_t a;
    asm("{ .reg .u64 t; cvta.to.shared.u64 t, %1; cvt.u32.u64 %0, t; }"
        : "=r"(a) : "l"(p));
    return a;
}
#define CPASYNC16(sa, g) asm volatile("cp.async.cg.shared.global [%0], [%1], 16;" :: "r"(sa), "l"(g))
#define CPCOMMIT()  asm volatile("cp.async.commit_group;" ::: "memory")
#define CPWAIT2()   asm volatile("cp.async.wait_group 2;" ::: "memory")
#define CPWAIT1()   asm volatile("cp.async.wait_group 1;" ::: "memory")
#define CPWAIT0()   asm volatile("cp.async.wait_group 0;" ::: "memory")

#define LDSM4(r0, r1, r2, r3, a) \
    asm volatile("ldmatrix.sync.aligned.m8n8.x4.shared.b16 {%0,%1,%2,%3}, [%4];" \
                 : "=r"(r0), "=r"(r1), "=r"(r2), "=r"(r3) : "r"(a))
#define LDSM2(r0, r1, a) \
    asm volatile("ldmatrix.sync.aligned.m8n8.x2.shared.b16 {%0,%1}, [%2];" \
                 : "=r"(r0), "=r"(r1) : "r"(a))
#define LDSM4T(r, a) \
    asm volatile("ldmatrix.sync.aligned.m8n8.x4.trans.shared.b16 {%0,%1,%2,%3}, [%4];" \
                 : "=r"((r)[0]), "=r"((r)[1]), "=r"((r)[2]), "=r"((r)[3]) : "r"(a))

#define MMA16816(c, a, b) \
    asm volatile("mma.sync.aligned.m16n8k16.row.col.f32.bf16.bf16.f32 " \
                 "{%0,%1,%2,%3}, {%4,%5,%6,%7}, {%8,%9}, {%0,%1,%2,%3};" \
                 : "+f"((c)[0]), "+f"((c)[1]), "+f"((c)[2]), "+f"((c)[3]) \
                 : "r"((a)[0]), "r"((a)[1]), "r"((a)[2]), "r"((a)[3]), \
                   "r"((b)[0]), "r"((b)[1]))

// pack two fp32 into hi-bf16x2 and lo-bf16x2 (lo = residual)
__device__ __forceinline__ void split2(float a, float b, uint32_t& h, uint32_t& l) {
    __nv_bfloat16 ha = __float2bfloat16(a), hb = __float2bfloat16(b);
    float la = a - __bfloat162float(ha), lb = b - __bfloat162float(hb);
    __nv_bfloat162 H(ha, hb), L(__float2bfloat16(la), __float2bfloat16(lb));
    h = *(uint32_t*)&H;
    l = *(uint32_t*)&L;
}

// ---------------- split conversion: fp32 -> bf16 hi/lo ----------------
__global__ __launch_bounds__(256) void split_k(
    const float* __restrict__ in, __nv_bfloat16* __restrict__ hi,
    __nv_bfloat16* __restrict__ lo, int n4)
{
    int i = blockIdx.x * blockDim.x + threadIdx.x;
    if (i >= n4) return;
    float4 v = ((const float4*)in)[i];
    uint32_t h0, l0, h1, l1;
    split2(v.x, v.y, h0, l0);
    split2(v.z, v.w, h1, l1);
    uint32_t* H = (uint32_t*)hi;
    uint32_t* L = (uint32_t*)lo;
    H[2 * i] = h0; H[2 * i + 1] = h1;
    L[2 * i] = l0; L[2 * i + 1] = l1;
}

// ---------------- split + transpose: W[K,N] fp32 -> [N,K] bf16 hi/lo ----------------
__global__ __launch_bounds__(256) void splitT_k(
    const float* __restrict__ W, __nv_bfloat16* __restrict__ Th,
    __nv_bfloat16* __restrict__ Tl)
{
    __shared__ float tile[32][33];
    int bx = blockIdx.x * 32, by = blockIdx.y * 32;
    int tx = threadIdx.x, ty = threadIdx.y;   // block (32,8)
    #pragma unroll
    for (int r = 0; r < 32; r += 8)
        tile[ty + r][tx] = W[(size_t)(by + ty + r) * DMODEL + bx + tx];
    __syncthreads();
    #pragma unroll
    for (int r = 0; r < 32; r += 8) {
        float v = tile[tx][ty + r];
        __nv_bfloat16 h = __float2bfloat16(v);
        __nv_bfloat16 l = __float2bfloat16(v - __bfloat162float(h));
        size_t o = (size_t)(bx + ty + r) * DMODEL + by + tx;
        Th[o] = h;
        Tl[o] = l;
    }
}

// ---------------- HMMA split-bf16 GEMM ----------------
// C[M,N] = A[M,K] @ B^T. CTA tile 128x256, BK=32, 3-stage cp.async pipeline.
// 8 warps as 2m x 4n, warp tile 64x64.
// mode 0: fp32 out, QKV layout. mode 1: fp32 out, row-major. mode 2: bf16 hi/lo out, QKV layout.
#define NCHUNK 64
// stage layout: Ah 8K | Al 8K | Bh 16K | Bl 16K = 48K
#define GS_AH 0
#define GS_AL 8192
#define GS_BH 16384
#define GS_BL 32768
#define GSTAGE_B 49152
#define GSMEM (3 * GSTAGE_B)      // 144 KB

__global__ __launch_bounds__(256, 1) void gemm_mma(
    const __nv_bfloat16* __restrict__ Ah, const __nv_bfloat16* __restrict__ Al,
    const __nv_bfloat16* __restrict__ Bh, const __nv_bfloat16* __restrict__ Bl,
    float* __restrict__ C, __nv_bfloat16* __restrict__ Ch,
    __nv_bfloat16* __restrict__ Cl, int mode)
{
    extern __shared__ __align__(128) char smem[];
    const uint32_t sbase = s2u(smem);

    const int t = threadIdx.x;
    const int lane = t & 31, wid = t >> 5;
    const int wm = wid >> 2;         // 0..1  (64 M rows)
    const int wn = wid & 3;          // 0..3  (64 N cols)
    const int n0 = blockIdx.x * 256;
    const int m0 = blockIdx.y * 128;

    const char* pAh = (const char*)(Ah + (size_t)m0 * DMODEL);
    const char* pAl = (const char*)(Al + (size_t)m0 * DMODEL);
    const char* pBh = (const char*)(Bh + (size_t)n0 * DMODEL);
    const char* pBl = (const char*)(Bl + (size_t)n0 * DMODEL);

    float acc[4][8][4];
    #pragma unroll
    for (int i = 0; i < 4; i++)
        #pragma unroll
        for (int j = 0; j < 8; j++)
            #pragma unroll
            for (int r = 0; r < 4; r++) acc[i][j][r] = 0.f;

    auto load_stage = [&](int s, int chunk) {
        uint32_t base = sbase + (uint32_t)s * GSTAGE_B;
        // A: 128 rows x 64B, hi+lo (512 16B-units each); 2 per thread
        #pragma unroll
        for (int i = 0; i < 2; i++) {
            int u = t + i * 256;
            int row = u >> 2, c = u & 3;
            uint32_t off = (uint32_t)(row * 64 + ((c ^ (row & 3)) * 16));
            size_t go = (size_t)row * 4096 + (size_t)chunk * 64 + c * 16;
            CPASYNC16(base + GS_AH + off, pAh + go);
            CPASYNC16(base + GS_AL + off, pAl + go);
        }
        // B: 256 rows x 64B, hi+lo; 4 per thread
        #pragma unroll
        for (int i = 0; i < 4; i++) {
            int u = t + i * 256;
            int row = u >> 2, c = u & 3;
            uint32_t off = (uint32_t)(row * 64 + ((c ^ (row & 3)) * 16));
            size_t go = (size_t)row * 4096 + (size_t)chunk * 64 + c * 16;
            CPASYNC16(base + GS_BH + off, pBh + go);
            CPASYNC16(base + GS_BL + off, pBl + go);
        }
        CPCOMMIT();
    };

    load_stage(0, 0);
    load_stage(1, 1);

    const int arow_in = (lane & 15);
    const int achk_hi = (lane >> 4);
    const int brow_in = (lane & 7);
    const int bchk_hi = ((lane >> 3) & 1);

    for (int ic = 0; ic < NCHUNK; ic++) {
        const int s = ic % 3;
        if (ic + 2 < NCHUNK) {
            load_stage((ic + 2) % 3, ic + 2);
            CPWAIT2();
        } else if (ic + 1 < NCHUNK) {
            CPWAIT1();
        } else {
            CPWAIT0();
        }
        __syncthreads();

        const uint32_t stb = sbase + (uint32_t)s * GSTAGE_B;
        #pragma unroll
        for (int ks = 0; ks < 2; ks++) {
            uint32_t ahf[4][4], alf[4][4];
            #pragma unroll
            for (int ms = 0; ms < 4; ms++) {
                int r = wm * 64 + ms * 16 + arow_in;
                uint32_t c = (uint32_t)((2 * ks + achk_hi) ^ (r & 3));
                uint32_t ad = stb + (uint32_t)(r * 64) + c * 16;
                LDSM4(ahf[ms][0], ahf[ms][1], ahf[ms][2], ahf[ms][3], ad + GS_AH);
                LDSM4(alf[ms][0], alf[ms][1], alf[ms][2], alf[ms][3], ad + GS_AL);
            }
            #pragma unroll
            for (int ns = 0; ns < 8; ns++) {
                int rb = wn * 64 + ns * 8 + brow_in;
                uint32_t cb = (uint32_t)((2 * ks + bchk_hi) ^ (rb & 3));
                uint32_t bd = stb + (uint32_t)(rb * 64) + cb * 16;
                uint32_t bh[2], bl[2];
                LDSM2(bh[0], bh[1], bd + GS_BH);
                LDSM2(bl[0], bl[1], bd + GS_BL);
                #pragma unroll
                for (int ms = 0; ms < 4; ms++) {
                    MMA16816(acc[ms][ns], ahf[ms], bh);
                    MMA16816(acc[ms][ns], ahf[ms], bl);
                    MMA16816(acc[ms][ns], alf[ms], bh);
                }
            }
        }
        __syncthreads();
    }

    #pragma unroll
    for (int ms = 0; ms < 4; ms++) {
        #pragma unroll
        for (int rh = 0; rh < 2; rh++) {
            int m = m0 + wm * 64 + ms * 16 + (lane >> 2) + rh * 8;
            #pragma unroll
            for (int ns = 0; ns < 8; ns++) {
                int n = n0 + wn * 64 + ns * 8 + 2 * (lane & 3);
                float va = rh ? acc[ms][ns][2] : acc[ms][ns][0];
                float vb = rh ? acc[ms][ns][3] : acc[ms][ns][1];
                if (mode == 1) {
                    *(float2*)(C + (size_t)m * DMODEL + n) = make_float2(va, vb);
                } else {
                    int b = m >> 11, si = m & 2047, h = n >> 7, d = n & 127;
                    size_t idx = (((size_t)(b * NHEADS + h) * SEQ) + si) * HDIM + d;
                    if (mode == 0) {
                        *(float2*)(C + idx) = make_float2(va, vb);
                    } else {
                        uint32_t hh, ll;
                        split2(va, vb, hh, ll);
                        *(uint32_t*)(Ch + idx) = hh;
                        *(uint32_t*)(Cl + idx) = ll;
                    }
                }
            }
        }
    }
}

// ---------------- RoPE + split: fp32 q,k -> bf16 hi/lo (q scaled) ----------------
__global__ __launch_bounds__(256) void rope_split(
    const float* __restrict__ q, const float* __restrict__ k,
    const float* __restrict__ fcos, const float* __restrict__ fsin,
    __nv_bfloat16* __restrict__ qh, __nv_bfloat16* __restrict__ ql,
    __nv_bfloat16* __restrict__ kh, __nv_bfloat16* __restrict__ kl)
{
    int p = blockIdx.x * blockDim.x + threadIdx.x;
    int d = p & 63;
    int s = (p >> 6) & 2047;
    int base = (p >> 6) * 128 + d;
    float c  = fcos[s * 64 + d];
    float si = fsin[s * 64 + d];
    const float qs = 0.08838834764831845f * 1.4426950408889634f;

    float q0 = q[base], q1 = q[base + 64];
    float a0 = (q0 * c - q1 * si) * qs;
    float a1 = (q1 * c + q0 * si) * qs;
    __nv_bfloat16 h0 = __float2bfloat16(a0), h1 = __float2bfloat16(a1);
    qh[base] = h0;      ql[base]      = __float2bfloat16(a0 - __bfloat162float(h0));
    qh[base + 64] = h1; ql[base + 64] = __float2bfloat16(a1 - __bfloat162float(h1));

    float k0 = k[base], k1 = k[base + 64];
    float b0 = k0 * c - k1 * si;
    float b1 = k1 * c + k0 * si;
    __nv_bfloat16 g0 = __float2bfloat16(b0), g1 = __float2bfloat16(b1);
    kh[base] = g0;      kl[base]      = __float2bfloat16(b0 - __bfloat162float(g0));
    kh[base + 64] = g1; kl[base + 64] = __float2bfloat16(b1 - __bfloat162float(g1));
}

// ---------------- HMMA flash attention, causal, split-bf16 ----------------
// CTA: 128 q rows, 8 warps x 16 rows. K/V 64-key tiles, double buffered.
// smem: Qh 32K | Ql 32K | 2 stages x (Kh 16K | Kl 16K | Vh 16K | Vl 16K)
#define FSM_Q   0
#define FSM_QL  32768
#define FSM_ST  65536
#define FSM_STG 65536
#define FSM_TOTAL (65536 + 2 * 65536)   // 196608

__global__ __launch_bounds__(256, 1) void flash_mma(
    const __nv_bfloat16* __restrict__ Qh, const __nv_bfloat16* __restrict__ Ql,
    const __nv_bfloat16* __restrict__ Kh, const __nv_bfloat16* __restrict__ Kl,
    const __nv_bfloat16* __restrict__ Vh, const __nv_bfloat16* __restrict__ Vl,
    __nv_bfloat16* __restrict__ Oh, __nv_bfloat16* __restrict__ Ol)
{
    extern __shared__ __align__(128) char smem[];
    const uint32_t sb = s2u(smem);
    const int t = threadIdx.x, lane = t & 31, wid = t >> 5;
    const int bh = blockIdx.y;
    const int m0 = blockIdx.x * 128;

    // load Q tile (128 rows x 256B, hi+lo)
    {
        const char* gqh = (const char*)(Qh + ((size_t)bh * SEQ + m0) * HDIM);
        const char* gql = (const char*)(Ql + ((size_t)bh * SEQ + m0) * HDIM);
        #pragma unroll
        for (int i = 0; i < 8; i++) {
            int u = t + i * 256;
            int r = u >> 4, g = u & 15;
            uint32_t off = (uint32_t)(r * 256 + ((g ^ (r & 7)) * 16));
            size_t go = (size_t)r * 256 + g * 16;
            CPASYNC16(sb + FSM_Q + off, gqh + go);
            CPASYNC16(sb + FSM_QL + off, gql + go);
        }
        CPCOMMIT();
    }

    const char* gkh = (const char*)(Kh + (size_t)bh * SEQ * HDIM);
    const char* gkl = (const char*)(Kl + (size_t)bh * SEQ * HDIM);
    const char* gvh = (const char*)(Vh + (size_t)bh * SEQ * HDIM);
    const char* gvl = (const char*)(Vl + (size_t)bh * SEQ * HDIM);

    auto load_kv = [&](int s, int jt) {
        uint32_t stb = sb + FSM_ST + (uint32_t)s * FSM_STG;
        size_t base = (size_t)jt * 64 * 256;
        #pragma unroll
        for (int i = 0; i < 4; i++) {
            int u = t + i * 256;
            int r = u >> 4, g = u & 15;
            uint32_t off = (uint32_t)(r * 256 + ((g ^ (r & 7)) * 16));
            size_t go = base + (size_t)r * 256 + g * 16;
            CPASYNC16(stb + 0     + off, gkh + go);
            CPASYNC16(stb + 16384 + off, gkl + go);
            CPASYNC16(stb + 32768 + off, gvh + go);
            CPASYNC16(stb + 49152 + off, gvl + go);
        }
        CPCOMMIT();
    };

    load_kv(0, 0);

    float oacc[16][4];
    #pragma unroll
    for (int i = 0; i < 16; i++)
        #pragma unroll
        for (int j = 0; j < 4; j++) oacc[i][j] = 0.f;
    float mrun0 = -1e30f, mrun1 = -1e30f, ls0 = 0.f, ls1 = 0.f;

    const int wrow = m0 + wid * 16;
    const int r0 = wrow + (lane >> 2), r1 = r0 + 8;
    const int ntiles = m0 / 64 + 2;

    for (int jt = 0; jt < ntiles; jt++) {
        const int s = jt & 1;
        if (jt + 1 < ntiles) { load_kv(s ^ 1, jt + 1); CPWAIT1(); }
        else                 { CPWAIT0(); }
        __syncthreads();

        const int k0 = jt * 64;
        if (k0 <= wrow + 15) {
            const uint32_t stb = sb + FSM_ST + (uint32_t)s * FSM_STG;
            float sacc[8][4];
            #pragma unroll
            for (int i = 0; i < 8; i++)
                #pragma unroll
                for (int j = 0; j < 4; j++) sacc[i][j] = 0.f;

            // ---- S = Q K^T (3-term split)
            const int rowA = wid * 16 + (lane & 15);
            const int rbB = (lane & 7) | ((lane >> 1) & 8);
            #pragma unroll
            for (int k8 = 0; k8 < 8; k8++) {
                int gA = 2 * k8 + (lane >> 4);
                uint32_t aoff = (uint32_t)(rowA * 256 + ((gA ^ (rowA & 7)) * 16));
                uint32_t ah[4], al[4];
                LDSM4(ah[0], ah[1], ah[2], ah[3], sb + FSM_Q + aoff);
                LDSM4(al[0], al[1], al[2], al[3], sb + FSM_QL + aoff);
                int gB = 2 * k8 + ((lane >> 3) & 1);
                #pragma unroll
                for (int np = 0; np < 4; np++) {
                    int rowB = np * 16 + rbB;
                    uint32_t boff = (uint32_t)(rowB * 256 + ((gB ^ (rowB & 7)) * 16));
                    uint32_t bh2[4], bl2[4];
                    LDSM4(bh2[0], bh2[1], bh2[2], bh2[3], stb + 0 + boff);
                    LDSM4(bl2[0], bl2[1], bl2[2], bl2[3], stb + 16384 + boff);
                    MMA16816(sacc[2 * np],     ah, &bh2[0]);
                    MMA16816(sacc[2 * np],     ah, &bl2[0]);
                    MMA16816(sacc[2 * np],     al, &bh2[0]);
                    MMA16816(sacc[2 * np + 1], ah, &bh2[2]);
                    MMA16816(sacc[2 * np + 1], ah, &bl2[2]);
                    MMA16816(sacc[2 * np + 1], al, &bh2[2]);
                }
            }

            // ---- causal mask
            if (k0 + 63 > wrow) {
                #pragma unroll
                for (int nt = 0; nt < 8; nt++) {
                    int c = k0 + nt * 8 + 2 * (lane & 3);
                    if (c     > r0) sacc[nt][0] = -1e30f;
                    if (c + 1 > r0) sacc[nt][1] = -1e30f;
                    if (c     > r1) sacc[nt][2] = -1e30f;
                    if (c + 1 > r1) sacc[nt][3] = -1e30f;
                }
            }

            // ---- online softmax (log2 domain; qscale*log2e already in Q)
            float ml0 = -1e30f, ml1 = -1e30f;
            #pragma unroll
            for (int nt = 0; nt < 8; nt++) {
                ml0 = fmaxf(ml0, fmaxf(sacc[nt][0], sacc[nt][1]));
                ml1 = fmaxf(ml1, fmaxf(sacc[nt][2], sacc[nt][3]));
            }
            ml0 = fmaxf(ml0, __shfl_xor_sync(0xffffffffu, ml0, 1));
            ml0 = fmaxf(ml0, __shfl_xor_sync(0xffffffffu, ml0, 2));
            ml1 = fmaxf(ml1, __shfl_xor_sync(0xffffffffu, ml1, 1));
            ml1 = fmaxf(ml1, __shfl_xor_sync(0xffffffffu, ml1, 2));
            float mn0 = fmaxf(mrun0, ml0), mn1 = fmaxf(mrun1, ml1);
            float c0 = exp2f(mrun0 - mn0), c1 = exp2f(mrun1 - mn1);
            mrun0 = mn0; mrun1 = mn1;
            ls0 *= c0; ls1 *= c1;
            #pragma unroll
            for (int nt = 0; nt < 16; nt++) {
                oacc[nt][0] *= c0; oacc[nt][1] *= c0;
                oacc[nt][2] *= c1; oacc[nt][3] *= c1;
            }
            float ps0 = 0.f, ps1 = 0.f;
            #pragma unroll
            for (int nt = 0; nt < 8; nt++) {
                sacc[nt][0] = exp2f(sacc[nt][0] - mn0);
                sacc[nt][1] = exp2f(sacc[nt][1] - mn0);
                sacc[nt][2] = exp2f(sacc[nt][2] - mn1);
                sacc[nt][3] = exp2f(sacc[nt][3] - mn1);
                ps0 += sacc[nt][0] + sacc[nt][1];
                ps1 += sacc[nt][2] + sacc[nt][3];
            }
            ls0 += ps0; ls1 += ps1;

            // ---- O += P V (3-term split); P C-frags repack as A-frags
            #pragma unroll
            for (int j = 0; j < 4; j++) {
                uint32_t pah[4], pal[4];
                split2(sacc[2 * j][0],     sacc[2 * j][1],     pah[0], pal[0]);
                split2(sacc[2 * j][2],     sacc[2 * j][3],     pah[1], pal[1]);
                split2(sacc[2 * j + 1][0], sacc[2 * j + 1][1], pah[2], pal[2]);
                split2(sacc[2 * j + 1][2], sacc[2 * j + 1][3], pah[3], pal[3]);
                int rv = 16 * j + (lane & 15);
                #pragma unroll
                for (int dp = 0; dp < 8; dp++) {
                    int gV = 2 * dp + (lane >> 4);
                    uint32_t voff = (uint32_t)(rv * 256 + ((gV ^ (rv & 7)) * 16));
                    uint32_t vh2[4], vl2[4];
                    LDSM4T(vh2, stb + 32768 + voff);
                    LDSM4T(vl2, stb + 49152 + voff);
                    MMA16816(oacc[2 * dp],     pah, &vh2[0]);
                    MMA16816(oacc[2 * dp],     pah, &vl2[0]);
                    MMA16816(oacc[2 * dp],     pal, &vh2[0]);
                    MMA16816(oacc[2 * dp + 1], pah, &vh2[2]);
                    MMA16816(oacc[2 * dp + 1], pah, &vl2[2]);
                    MMA16816(oacc[2 * dp + 1], pal, &vh2[2]);
                }
            }
        }
        __syncthreads();
    }

    // ---- epilogue: normalize, split to bf16 hi/lo, write att [B*S, H*hd]
    float lt0 = ls0 + __shfl_xor_sync(0xffffffffu, ls0, 1);
    lt0 += __shfl_xor_sync(0xffffffffu, lt0, 2);
    float lt1 = ls1 + __shfl_xor_sync(0xffffffffu, ls1, 1);
    lt1 += __shfl_xor_sync(0xffffffffu, lt1, 2);
    float inv0 = 1.f / lt0, inv1 = 1.f / lt1;

    const int b = bh >> 4, h = bh & 15;
    size_t base0 = ((size_t)(b * SEQ) + r0) * DMODEL + h * HDIM;
    size_t base1 = base0 + (size_t)8 * DMODEL;
    #pragma unroll
    for (int nt = 0; nt < 16; nt++) {
        int d = nt * 8 + 2 * (lane & 3);
        uint32_t hh, ll;
        split2(oacc[nt][0] * inv0, oacc[nt][1] * inv0, hh, ll);
        *(uint32_t*)(Oh + base0 + d) = hh;
        *(uint32_t*)(Ol + base0 + d) = ll;
        split2(oacc[nt][2] * inv1, oacc[nt][3] * inv1, hh, ll);
        *(uint32_t*)(Oh + base1 + d) = hh;
        *(uint32_t*)(Ol + base1 + d) = ll;
    }
}

// ---------------- launch ----------------
extern "C" void kernel_launch(void* const* d_in, const int* in_sizes, int n_in,
                              void* d_out, int out_size)
{
    (void)in_sizes; (void)n_in; (void)out_size;
    const float* x    = (const float*)d_in[0];
    const float* fcos = (const float*)d_in[1];
    const float* fsin = (const float*)d_in[2];
    const float* wq   = (const float*)d_in[3];
    const float* wk   = (const float*)d_in[4];
    const float* wv   = (const float*)d_in[5];
    const float* wo   = (const float*)d_in[6];
    float* out = (float*)d_out;

    float *q, *k;
    __nv_bfloat16 *xh, *xl, *ath, *atl, *qh, *ql, *kh, *kl, *vh, *vl;
    __nv_bfloat16 *wqh, *wql, *wkh, *wkl, *wvh, *wvl, *woh, *wol;
    cudaGetSymbolAddress((void**)&q,   g_q);
    cudaGetSymbolAddress((void**)&k,   g_k);
    cudaGetSymbolAddress((void**)&xh,  g_xh);
    cudaGetSymbolAddress((void**)&xl,  g_xl);
    cudaGetSymbolAddress((void**)&ath, g_ath);
    cudaGetSymbolAddress((void**)&atl, g_atl);
    cudaGetSymbolAddress((void**)&qh,  g_qh);
    cudaGetSymbolAddress((void**)&ql,  g_ql);
    cudaGetSymbolAddress((void**)&kh,  g_kh);
    cudaGetSymbolAddress((void**)&kl,  g_kl);
    cudaGetSymbolAddress((void**)&vh,  g_vh);
    cudaGetSymbolAddress((void**)&vl,  g_vl);
    cudaGetSymbolAddress((void**)&wqh, g_wqh);
    cudaGetSymbolAddress((void**)&wql, g_wql);
    cudaGetSymbolAddress((void**)&wkh, g_wkh);
    cudaGetSymbolAddress((void**)&wkl, g_wkl);
    cudaGetSymbolAddress((void**)&wvh, g_wvh);
    cudaGetSymbolAddress((void**)&wvl, g_wvl);
    cudaGetSymbolAddress((void**)&woh, g_woh);
    cudaGetSymbolAddress((void**)&wol, g_wol);

    cudaFuncSetAttribute(gemm_mma, cudaFuncAttributeMaxDynamicSharedMemorySize, GSMEM);
    cudaFuncSetAttribute(flash_mma, cudaFuncAttributeMaxDynamicSharedMemorySize, FSM_TOTAL);

    // conversions
    split_k<<<QKV_ELEMS / 4 / 256, 256>>>(x, xh, xl, QKV_ELEMS / 4);
    dim3 tg(DMODEL / 32, DMODEL / 32), tb(32, 8);
    splitT_k<<<tg, tb>>>(wq, wqh, wql);
    splitT_k<<<tg, tb>>>(wk, wkh, wkl);
    splitT_k<<<tg, tb>>>(wv, wvh, wvl);
    splitT_k<<<tg, tb>>>(wo, woh, wol);

    dim3 gg(DMODEL / 256, ROWS / 128);   // (8, 32)
    gemm_mma<<<gg, 256, GSMEM>>>(xh, xl, wqh, wql, q, nullptr, nullptr, 0);
    gemm_mma<<<gg, 256, GSMEM>>>(xh, xl, wkh, wkl, k, nullptr, nullptr, 0);
    gemm_mma<<<gg, 256, GSMEM>>>(xh, xl, wvh, wvl, nullptr, vh, vl, 2);

    rope_split<<<(BATCH * NHEADS * SEQ * 64) / 256, 256>>>(q, k, fcos, fsin,
                                                           qh, ql, kh, kl);

    flash_mma<<<dim3(SEQ / 128, BATCH * NHEADS), 256, FSM_TOTAL>>>(
        qh, ql, kh, kl, vh, vl, ath, atl);

    gemm_mma<<<gg, 256, GSMEM>>>(ath, atl, woh, wol, out, nullptr, nullptr, 1);
}

// round 9
// speedup vs baseline: 7.8666x; 2.1457x over previous
#include <cuda_runtime.h>
#include <cuda_fp16.h>
#include <cstdint>

// Problem constants
#define BATCH 2
#define SEQ   2048
#define DMODEL 2048
#define NHEADS 16
#define HDIM  128
#define ROWS  (BATCH * SEQ)          // 4096
#define QKV_ELEMS (ROWS * DMODEL)    // 8388608
#define WELEMS (DMODEL * DMODEL)     // 4194304

// ---------------- scratch (device globals; no allocation) ----------------
__device__ float g_q[QKV_ELEMS];     // fp32 [B,H,S,hd] (pre-rope)
__device__ float g_k[QKV_ELEMS];
__device__ __align__(256) __half g_xf[QKV_ELEMS];
__device__ __align__(256) __half g_attf[QKV_ELEMS];
__device__ __align__(256) __half g_qf[QKV_ELEMS], g_kf[QKV_ELEMS], g_vf[QKV_ELEMS];
__device__ __align__(256) __half g_wqT[WELEMS], g_wkT[WELEMS];
__device__ __align__(256) __half g_wvT[WELEMS], g_woT[WELEMS];

// ---------------- PTX helpers ----------------
__device__ __forceinline__ uint32_t s2u(const void* p) {
    uint32_t a;
    asm("{ .reg .u64 t; cvta.to.shared.u64 t, %1; cvt.u32.u64 %0, t; }"
        : "=r"(a) : "l"(p));
    return a;
}
#define CPASYNC16(sa, g) asm volatile("cp.async.cg.shared.global [%0], [%1], 16;" :: "r"(sa), "l"(g))
#define CPCOMMIT()  asm volatile("cp.async.commit_group;" ::: "memory")
#define CPWAIT2()   asm volatile("cp.async.wait_group 2;" ::: "memory")
#define CPWAIT1()   asm volatile("cp.async.wait_group 1;" ::: "memory")
#define CPWAIT0()   asm volatile("cp.async.wait_group 0;" ::: "memory")

#define LDSM4(r0, r1, r2, r3, a) \
    asm volatile("ldmatrix.sync.aligned.m8n8.x4.shared.b16 {%0,%1,%2,%3}, [%4];" \
                 : "=r"(r0), "=r"(r1), "=r"(r2), "=r"(r3) : "r"(a))
#define LDSM2(r0, r1, a) \
    asm volatile("ldmatrix.sync.aligned.m8n8.x2.shared.b16 {%0,%1}, [%2];" \
                 : "=r"(r0), "=r"(r1) : "r"(a))
#define LDSM4T(r, a) \
    asm volatile("ldmatrix.sync.aligned.m8n8.x4.trans.shared.b16 {%0,%1,%2,%3}, [%4];" \
                 : "=r"((r)[0]), "=r"((r)[1]), "=r"((r)[2]), "=r"((r)[3]) : "r"(a))

#define MMAF16(c, a, b) \
    asm volatile("mma.sync.aligned.m16n8k16.row.col.f32.f16.f16.f32 " \
                 "{%0,%1,%2,%3}, {%4,%5,%6,%7}, {%8,%9}, {%0,%1,%2,%3};" \
                 : "+f"((c)[0]), "+f"((c)[1]), "+f"((c)[2]), "+f"((c)[3]) \
                 : "r"((a)[0]), "r"((a)[1]), "r"((a)[2]), "r"((a)[3]), \
                   "r"((b)[0]), "r"((b)[1]))

__device__ __forceinline__ uint32_t packh2(float a, float b) {
    __half2 h = __floats2half2_rn(a, b);
    return *(uint32_t*)&h;
}

// ---------------- conversions ----------------
__global__ __launch_bounds__(256) void cvt_k(
    const float* __restrict__ in, __half* __restrict__ out, int n4)
{
    int i = blockIdx.x * blockDim.x + threadIdx.x;
    if (i >= n4) return;
    float4 v = ((const float4*)in)[i];
    uint32_t* O = (uint32_t*)out;
    O[2 * i]     = packh2(v.x, v.y);
    O[2 * i + 1] = packh2(v.z, v.w);
}

// W[K,N] fp32 -> [N,K] fp16
__global__ __launch_bounds__(256) void cvtT_k(
    const float* __restrict__ W, __half* __restrict__ T)
{
    __shared__ float tile[32][33];
    int bx = blockIdx.x * 32, by = blockIdx.y * 32;
    int tx = threadIdx.x, ty = threadIdx.y;   // block (32,8)
    #pragma unroll
    for (int r = 0; r < 32; r += 8)
        tile[ty + r][tx] = W[(size_t)(by + ty + r) * DMODEL + bx + tx];
    __syncthreads();
    #pragma unroll
    for (int r = 0; r < 32; r += 8)
        T[(size_t)(bx + ty + r) * DMODEL + by + tx] = __float2half(tile[tx][ty + r]);
}

// ---------------- fp16 HMMA GEMM core ----------------
// C[M,N] = A[M,K] @ B^T, A [M,K] fp16 K-major, B [N,K] fp16 K-major.
// CTA tile 128x256, BK=32, 4-stage cp.async, single sync per chunk.
// 8 warps as 2m x 4n, warp tile 64x64.
#define NCHUNK 64
#define GS_A 0
#define GS_B 8192
#define GSTAGE 24576
#define GNST 4
#define GSMEM (GNST * GSTAGE)     // 98304

__device__ __forceinline__ void gemm_core(
    const __half* __restrict__ A, const __half* __restrict__ B,
    int m0, int n0, float (&acc)[4][8][4])
{
    extern __shared__ __align__(128) char smem[];
    const uint32_t sbase = s2u(smem);
    const int t = threadIdx.x;
    const int lane = t & 31, wid = t >> 5;
    const int wm = wid >> 2, wn = wid & 3;

    const char* pA = (const char*)(A + (size_t)m0 * DMODEL);
    const char* pB = (const char*)(B + (size_t)n0 * DMODEL);

    #pragma unroll
    for (int i = 0; i < 4; i++)
        #pragma unroll
        for (int j = 0; j < 8; j++)
            #pragma unroll
            for (int r = 0; r < 4; r++) acc[i][j][r] = 0.f;

    auto load_stage = [&](int s, int chunk) {
        uint32_t base = sbase + (uint32_t)s * GSTAGE;
        #pragma unroll
        for (int i = 0; i < 2; i++) {          // A: 128 rows x 64B
            int u = t + i * 256;
            int row = u >> 2, c = u & 3;
            uint32_t off = (uint32_t)(row * 64 + ((c ^ (row & 3)) * 16));
            CPASYNC16(base + GS_A + off,
                      pA + (size_t)row * 4096 + (size_t)chunk * 64 + c * 16);
        }
        #pragma unroll
        for (int i = 0; i < 4; i++) {          // B: 256 rows x 64B
            int u = t + i * 256;
            int row = u >> 2, c = u & 3;
            uint32_t off = (uint32_t)(row * 64 + ((c ^ (row & 3)) * 16));
            CPASYNC16(base + GS_B + off,
                      pB + (size_t)row * 4096 + (size_t)chunk * 64 + c * 16);
        }
        CPCOMMIT();
    };

    load_stage(0, 0);
    load_stage(1, 1);
    load_stage(2, 2);

    for (int ic = 0; ic < NCHUNK; ic++) {
        int rem = NCHUNK - 1 - ic;
        if (rem >= 2)      CPWAIT2();
        else if (rem == 1) CPWAIT1();
        else               CPWAIT0();
        __syncthreads();
        if (ic + 3 < NCHUNK) load_stage((ic + 3) % GNST, ic + 3);

        const uint32_t stb = sbase + (uint32_t)(ic % GNST) * GSTAGE;
        #pragma unroll
        for (int ks = 0; ks < 2; ks++) {
            uint32_t af[4][4];
            #pragma unroll
            for (int ms = 0; ms < 4; ms++) {
                int r = wm * 64 + ms * 16 + (lane & 15);
                uint32_t c = (uint32_t)((2 * ks + (lane >> 4)) ^ (r & 3));
                LDSM4(af[ms][0], af[ms][1], af[ms][2], af[ms][3],
                      stb + GS_A + (uint32_t)(r * 64) + c * 16);
            }
            #pragma unroll
            for (int ns = 0; ns < 8; ns++) {
                int rb = wn * 64 + ns * 8 + (lane & 7);
                uint32_t cb = (uint32_t)((2 * ks + ((lane >> 3) & 1)) ^ (rb & 3));
                uint32_t bf[2];
                LDSM2(bf[0], bf[1], stb + GS_B + (uint32_t)(rb * 64) + cb * 16);
                #pragma unroll
                for (int ms = 0; ms < 4; ms++)
                    MMAF16(acc[ms][ns], af[ms], bf);
            }
        }
    }
}

// QKV fused: z=0 -> q fp32, z=1 -> k fp32, z=2 -> vf fp16 (all QKV layout)
__global__ __launch_bounds__(256, 1) void gemm_qkv(
    const __half* __restrict__ xf,
    const __half* __restrict__ wqT, const __half* __restrict__ wkT,
    const __half* __restrict__ wvT,
    float* __restrict__ q, float* __restrict__ k, __half* __restrict__ vf)
{
    const int z = blockIdx.z;
    const __half* B = (z == 0) ? wqT : (z == 1) ? wkT : wvT;
    const int n0 = blockIdx.x * 256;
    const int m0 = blockIdx.y * 128;
    float acc[4][8][4];
    gemm_core(xf, B, m0, n0, acc);

    const int lane = threadIdx.x & 31, wid = threadIdx.x >> 5;
    const int wm = wid >> 2, wn = wid & 3;
    float* Cf = (z == 0) ? q : k;
    #pragma unroll
    for (int ms = 0; ms < 4; ms++) {
        #pragma unroll
        for (int rh = 0; rh < 2; rh++) {
            int m = m0 + wm * 64 + ms * 16 + (lane >> 2) + rh * 8;
            int b = m >> 11, si = m & 2047;
            #pragma unroll
            for (int ns = 0; ns < 8; ns++) {
                int n = n0 + wn * 64 + ns * 8 + 2 * (lane & 3);
                int h = n >> 7, d = n & 127;
                size_t idx = (((size_t)(b * NHEADS + h) * SEQ) + si) * HDIM + d;
                float va = rh ? acc[ms][ns][2] : acc[ms][ns][0];
                float vb = rh ? acc[ms][ns][3] : acc[ms][ns][1];
                if (z < 2) *(float2*)(Cf + idx) = make_float2(va, vb);
                else       *(uint32_t*)(vf + idx) = packh2(va, vb);
            }
        }
    }
}

// WO: fp32 row-major out
__global__ __launch_bounds__(256, 1) void gemm_wo(
    const __half* __restrict__ attf, const __half* __restrict__ woT,
    float* __restrict__ out)
{
    const int n0 = blockIdx.x * 256;
    const int m0 = blockIdx.y * 128;
    float acc[4][8][4];
    gemm_core(attf, woT, m0, n0, acc);

    const int lane = threadIdx.x & 31, wid = threadIdx.x >> 5;
    const int wm = wid >> 2, wn = wid & 3;
    #pragma unroll
    for (int ms = 0; ms < 4; ms++) {
        #pragma unroll
        for (int rh = 0; rh < 2; rh++) {
            int m = m0 + wm * 64 + ms * 16 + (lane >> 2) + rh * 8;
            #pragma unroll
            for (int ns = 0; ns < 8; ns++) {
                int n = n0 + wn * 64 + ns * 8 + 2 * (lane & 3);
                float va = rh ? acc[ms][ns][2] : acc[ms][ns][0];
                float vb = rh ? acc[ms][ns][3] : acc[ms][ns][1];
                *(float2*)(out + (size_t)m * DMODEL + n) = make_float2(va, vb);
            }
        }
    }
}

// ---------------- RoPE + convert: fp32 q,k -> fp16 (q scaled) ----------------
__global__ __launch_bounds__(256) void rope_cvt(
    const float* __restrict__ q, const float* __restrict__ k,
    const float* __restrict__ fcos, const float* __restrict__ fsin,
    __half* __restrict__ qf, __half* __restrict__ kf)
{
    int p = blockIdx.x * blockDim.x + threadIdx.x;
    int d = p & 63;
    int s = (p >> 6) & 2047;
    int base = (p >> 6) * 128 + d;
    float c  = fcos[s * 64 + d];
    float si = fsin[s * 64 + d];
    const float qs = 0.08838834764831845f * 1.4426950408889634f;

    float q0 = q[base], q1 = q[base + 64];
    qf[base]      = __float2half((q0 * c - q1 * si) * qs);
    qf[base + 64] = __float2half((q1 * c + q0 * si) * qs);
    float k0 = k[base], k1 = k[base + 64];
    kf[base]      = __float2half(k0 * c - k1 * si);
    kf[base + 64] = __float2half(k1 * c + k0 * si);
}

// ---------------- fp16 HMMA flash attention, causal ----------------
// CTA: 128 q rows, 8 warps x 16 rows. K/V 128-key tiles, double buffered.
// smem: Q 32K | 2 stages x (K 32K | V 32K)
#define FQ 0
#define FST 32768
#define FSTG 65536
#define FK 0
#define FV 32768
#define FSMEM (32768 + 2 * 65536)   // 163840

__global__ __launch_bounds__(256, 1) void flash_f16(
    const __half* __restrict__ Qf, const __half* __restrict__ Kf,
    const __half* __restrict__ Vf, __half* __restrict__ Oatt)
{
    extern __shared__ __align__(128) char smem[];
    const uint32_t sb = s2u(smem);
    const int t = threadIdx.x, lane = t & 31, wid = t >> 5;
    const int bh = blockIdx.y;
    const int m0 = blockIdx.x * 128;
    const int ntiles = blockIdx.x + 1;

    // Q tile: 128 rows x 256B
    {
        const char* gq = (const char*)(Qf + ((size_t)bh * SEQ + m0) * HDIM);
        #pragma unroll
        for (int i = 0; i < 8; i++) {
            int u = t + i * 256;
            int r = u >> 4, g = u & 15;
            uint32_t off = (uint32_t)(r * 256 + ((g ^ (r & 7)) * 16));
            CPASYNC16(sb + FQ + off, gq + (size_t)r * 256 + g * 16);
        }
        CPCOMMIT();
    }

    const char* gk = (const char*)(Kf + (size_t)bh * SEQ * HDIM);
    const char* gv = (const char*)(Vf + (size_t)bh * SEQ * HDIM);

    auto load_kv = [&](int s, int jt) {
        uint32_t stb = sb + FST + (uint32_t)s * FSTG;
        size_t base = (size_t)jt * 128 * 256;
        #pragma unroll
        for (int i = 0; i < 8; i++) {
            int u = t + i * 256;
            int r = u >> 4, g = u & 15;
            uint32_t off = (uint32_t)(r * 256 + ((g ^ (r & 7)) * 16));
            size_t go = base + (size_t)r * 256 + g * 16;
            CPASYNC16(stb + FK + off, gk + go);
            CPASYNC16(stb + FV + off, gv + go);
        }
        CPCOMMIT();
    };

    load_kv(0, 0);

    float oacc[16][4];
    #pragma unroll
    for (int i = 0; i < 16; i++)
        #pragma unroll
        for (int j = 0; j < 4; j++) oacc[i][j] = 0.f;
    float mrun0 = -1e30f, mrun1 = -1e30f, ls0 = 0.f, ls1 = 0.f;

    const int r0 = m0 + wid * 16 + (lane >> 2), r1 = r0 + 8;
    const int rowA = wid * 16 + (lane & 15);
    const int rbB = (lane & 7) | ((lane >> 1) & 8);

    for (int jt = 0; jt < ntiles; jt++) {
        const int s = jt & 1;
        CPWAIT0();
        __syncthreads();
        if (jt + 1 < ntiles) load_kv(s ^ 1, jt + 1);

        const uint32_t stb = sb + FST + (uint32_t)s * FSTG;
        float sacc[16][4];
        #pragma unroll
        for (int i = 0; i < 16; i++)
            #pragma unroll
            for (int j = 0; j < 4; j++) sacc[i][j] = 0.f;

        // ---- S = Q K^T
        #pragma unroll
        for (int k8 = 0; k8 < 8; k8++) {
            int gA = 2 * k8 + (lane >> 4);
            uint32_t aq[4];
            LDSM4(aq[0], aq[1], aq[2], aq[3],
                  sb + FQ + (uint32_t)(rowA * 256 + ((gA ^ (rowA & 7)) * 16)));
            int gB = 2 * k8 + ((lane >> 3) & 1);
            #pragma unroll
            for (int np = 0; np < 8; np++) {
                int rowB = np * 16 + rbB;
                uint32_t bk[4];
                LDSM4(bk[0], bk[1], bk[2], bk[3],
                      stb + FK + (uint32_t)(rowB * 256 + ((gB ^ (rowB & 7)) * 16)));
                MMAF16(sacc[2 * np],     aq, &bk[0]);
                MMAF16(sacc[2 * np + 1], aq, &bk[2]);
            }
        }

        // ---- causal mask (diagonal tile only)
        if (jt == ntiles - 1) {
            const int k0 = jt * 128;
            #pragma unroll
            for (int nt = 0; nt < 16; nt++) {
                int c = k0 + nt * 8 + 2 * (lane & 3);
                if (c     > r0) sacc[nt][0] = -1e30f;
                if (c + 1 > r0) sacc[nt][1] = -1e30f;
                if (c     > r1) sacc[nt][2] = -1e30f;
                if (c + 1 > r1) sacc[nt][3] = -1e30f;
            }
        }

        // ---- online softmax (log2 domain; scale*log2e folded into Q)
        float ml0 = -1e30f, ml1 = -1e30f;
        #pragma unroll
        for (int nt = 0; nt < 16; nt++) {
            ml0 = fmaxf(ml0, fmaxf(sacc[nt][0], sacc[nt][1]));
            ml1 = fmaxf(ml1, fmaxf(sacc[nt][2], sacc[nt][3]));
        }
        ml0 = fmaxf(ml0, __shfl_xor_sync(0xffffffffu, ml0, 1));
        ml0 = fmaxf(ml0, __shfl_xor_sync(0xffffffffu, ml0, 2));
        ml1 = fmaxf(ml1, __shfl_xor_sync(0xffffffffu, ml1, 1));
        ml1 = fmaxf(ml1, __shfl_xor_sync(0xffffffffu, ml1, 2));
        float mn0 = fmaxf(mrun0, ml0), mn1 = fmaxf(mrun1, ml1);
        float c0 = exp2f(mrun0 - mn0), c1 = exp2f(mrun1 - mn1);
        mrun0 = mn0; mrun1 = mn1;
        ls0 *= c0; ls1 *= c1;
        #pragma unroll
        for (int nt = 0; nt < 16; nt++) {
            oacc[nt][0] *= c0; oacc[nt][1] *= c0;
            oacc[nt][2] *= c1; oacc[nt][3] *= c1;
        }
        float ps0 = 0.f, ps1 = 0.f;
        #pragma unroll
        for (int nt = 0; nt < 16; nt++) {
            sacc[nt][0] = exp2f(sacc[nt][0] - mn0);
            sacc[nt][1] = exp2f(sacc[nt][1] - mn0);
            sacc[nt][2] = exp2f(sacc[nt][2] - mn1);
            sacc[nt][3] = exp2f(sacc[nt][3] - mn1);
            ps0 += sacc[nt][0] + sacc[nt][1];
            ps1 += sacc[nt][2] + sacc[nt][3];
        }
        ls0 += ps0; ls1 += ps1;

        // ---- O += P V ; P C-frags repack as fp16 A-frags
        #pragma unroll
        for (int kp = 0; kp < 8; kp++) {
            uint32_t pa[4];
            pa[0] = packh2(sacc[2 * kp][0],     sacc[2 * kp][1]);
            pa[1] = packh2(sacc[2 * kp][2],     sacc[2 * kp][3]);
            pa[2] = packh2(sacc[2 * kp + 1][0], sacc[2 * kp + 1][1]);
            pa[3] = packh2(sacc[2 * kp + 1][2], sacc[2 * kp + 1][3]);
            int rv = kp * 16 + (lane & 15);
            #pragma unroll
            for (int dp = 0; dp < 8; dp++) {
                int gV = 2 * dp + (lane >> 4);
                uint32_t vv[4];
                LDSM4T(vv, stb + FV + (uint32_t)(rv * 256 + ((gV ^ (rv & 7)) * 16)));
                MMAF16(oacc[2 * dp],     pa, &vv[0]);
                MMAF16(oacc[2 * dp + 1], pa, &vv[2]);
            }
        }
    }

    // ---- epilogue: normalize, fp16, write att [B*S, H*hd]
    float lt0 = ls0 + __shfl_xor_sync(0xffffffffu, ls0, 1);
    lt0 += __shfl_xor_sync(0xffffffffu, lt0, 2);
    float lt1 = ls1 + __shfl_xor_sync(0xffffffffu, ls1, 1);
    lt1 += __shfl_xor_sync(0xffffffffu, lt1, 2);
    float inv0 = 1.f / lt0, inv1 = 1.f / lt1;

    const int b = bh >> 4, h = bh & 15;
    size_t base0 = ((size_t)(b * SEQ) + r0) * DMODEL + h * HDIM;
    size_t base1 = base0 + (size_t)8 * DMODEL;
    #pragma unroll
    for (int nt = 0; nt < 16; nt++) {
        int d = nt * 8 + 2 * (lane & 3);
        *(uint32_t*)(Oatt + base0 + d) = packh2(oacc[nt][0] * inv0, oacc[nt][1] * inv0);
        *(uint32_t*)(Oatt + base1 + d) = packh2(oacc[nt][2] * inv1, oacc[nt][3] * inv1);
    }
}

// ---------------- launch ----------------
extern "C" void kernel_launch(void* const* d_in, const int* in_sizes, int n_in,
                              void* d_out, int out_size)
{
    (void)in_sizes; (void)n_in; (void)out_size;
    const float* x    = (const float*)d_in[0];
    const float* fcos = (const float*)d_in[1];
    const float* fsin = (const float*)d_in[2];
    const float* wq   = (const float*)d_in[3];
    const float* wk   = (const float*)d_in[4];
    const float* wv   = (const float*)d_in[5];
    const float* wo   = (const float*)d_in[6];
    float* out = (float*)d_out;

    float *q, *k;
    __half *xf, *attf, *qf, *kf, *vf, *wqT, *wkT, *wvT, *woT;
    cudaGetSymbolAddress((void**)&q,    g_q);
    cudaGetSymbolAddress((void**)&k,    g_k);
    cudaGetSymbolAddress((void**)&xf,   g_xf);
    cudaGetSymbolAddress((void**)&attf, g_attf);
    cudaGetSymbolAddress((void**)&qf,   g_qf);
    cudaGetSymbolAddress((void**)&kf,   g_kf);
    cudaGetSymbolAddress((void**)&vf,   g_vf);
    cudaGetSymbolAddress((void**)&wqT,  g_wqT);
    cudaGetSymbolAddress((void**)&wkT,  g_wkT);
    cudaGetSymbolAddress((void**)&wvT,  g_wvT);
    cudaGetSymbolAddress((void**)&woT,  g_woT);

    cudaFuncSetAttribute(gemm_qkv, cudaFuncAttributeMaxDynamicSharedMemorySize, GSMEM);
    cudaFuncSetAttribute(gemm_wo,  cudaFuncAttributeMaxDynamicSharedMemorySize, GSMEM);
    cudaFuncSetAttribute(flash_f16, cudaFuncAttributeMaxDynamicSharedMemorySize, FSMEM);

    // conversions
    cvt_k<<<QKV_ELEMS / 4 / 256, 256>>>(x, xf, QKV_ELEMS / 4);
    dim3 tg(DMODEL / 32, DMODEL / 32), tb(32, 8);
    cvtT_k<<<tg, tb>>>(wq, wqT);
    cvtT_k<<<tg, tb>>>(wk, wkT);
    cvtT_k<<<tg, tb>>>(wv, wvT);
    cvtT_k<<<tg, tb>>>(wo, woT);

    // fused QKV GEMM
    dim3 gq3(DMODEL / 256, ROWS / 128, 3);   // (8, 32, 3)
    gemm_qkv<<<gq3, 256, GSMEM>>>(xf, wqT, wkT, wvT, q, k, vf);

    rope_cvt<<<(BATCH * NHEADS * SEQ * 64) / 256, 256>>>(q, k, fcos, fsin, qf, kf);

    flash_f16<<<dim3(SEQ / 128, BATCH * NHEADS), 256, FSMEM>>>(qf, kf, vf, attf);

    gemm_wo<<<dim3(DMODEL / 256, ROWS / 128), 256, GSMEM>>>(attf, woT, out);
}

// round 10
// speedup vs baseline: 8.1786x; 1.0397x over previous
#include <cuda_runtime.h>
#include <cuda_fp16.h>
#include <cstdint>

// Problem constants
#define BATCH 2
#define SEQ   2048
#define DMODEL 2048
#define NHEADS 16
#define HDIM  128
#define ROWS  (BATCH * SEQ)          // 4096
#define QKV_ELEMS (ROWS * DMODEL)    // 8388608
#define WELEMS (DMODEL * DMODEL)     // 4194304

// ---------------- scratch (device globals; no allocation) ----------------
__device__ __align__(256) __half g_xf[QKV_ELEMS];
__device__ __align__(256) __half g_attf[QKV_ELEMS];
__device__ __align__(256) __half g_qf[QKV_ELEMS], g_kf[QKV_ELEMS], g_vf[QKV_ELEMS];
__device__ __align__(256) __half g_wqT[WELEMS], g_wkT[WELEMS];
__device__ __align__(256) __half g_wvT[WELEMS], g_woT[WELEMS];

// ---------------- PTX helpers ----------------
__device__ __forceinline__ uint32_t s2u(const void* p) {
    uint32_t a;
    asm("{ .reg .u64 t; cvta.to.shared.u64 t, %1; cvt.u32.u64 %0, t; }"
        : "=r"(a) : "l"(p));
    return a;
}
#define CPASYNC16(sa, g) asm volatile("cp.async.cg.shared.global [%0], [%1], 16;" :: "r"(sa), "l"(g))
#define CPCOMMIT()  asm volatile("cp.async.commit_group;" ::: "memory")
#define CPWAIT2()   asm volatile("cp.async.wait_group 2;" ::: "memory")
#define CPWAIT1()   asm volatile("cp.async.wait_group 1;" ::: "memory")
#define CPWAIT0()   asm volatile("cp.async.wait_group 0;" ::: "memory")

#define LDSM4(r0, r1, r2, r3, a) \
    asm volatile("ldmatrix.sync.aligned.m8n8.x4.shared.b16 {%0,%1,%2,%3}, [%4];" \
                 : "=r"(r0), "=r"(r1), "=r"(r2), "=r"(r3) : "r"(a))
#define LDSM2(r0, r1, a) \
    asm volatile("ldmatrix.sync.aligned.m8n8.x2.shared.b16 {%0,%1}, [%2];" \
                 : "=r"(r0), "=r"(r1) : "r"(a))
#define LDSM4T(r, a) \
    asm volatile("ldmatrix.sync.aligned.m8n8.x4.trans.shared.b16 {%0,%1,%2,%3}, [%4];" \
                 : "=r"((r)[0]), "=r"((r)[1]), "=r"((r)[2]), "=r"((r)[3]) : "r"(a))

#define MMAF16(c, a, b) \
    asm volatile("mma.sync.aligned.m16n8k16.row.col.f32.f16.f16.f32 " \
                 "{%0,%1,%2,%3}, {%4,%5,%6,%7}, {%8,%9}, {%0,%1,%2,%3};" \
                 : "+f"((c)[0]), "+f"((c)[1]), "+f"((c)[2]), "+f"((c)[3]) \
                 : "r"((a)[0]), "r"((a)[1]), "r"((a)[2]), "r"((a)[3]), \
                   "r"((b)[0]), "r"((b)[1]))

__device__ __forceinline__ uint32_t packh2(float a, float b) {
    __half2 h = __floats2half2_rn(a, b);
    return *(uint32_t*)&h;
}

// ---------------- conversions ----------------
__global__ __launch_bounds__(256) void cvt_k(
    const float* __restrict__ in, __half* __restrict__ out, int n4)
{
    int i = blockIdx.x * blockDim.x + threadIdx.x;
    if (i >= n4) return;
    float4 v = ((const float4*)in)[i];
    uint32_t* O = (uint32_t*)out;
    O[2 * i]     = packh2(v.x, v.y);
    O[2 * i + 1] = packh2(v.z, v.w);
}

// 4 weights W[K,N] fp32 -> [N,K] fp16, one launch (z selects matrix)
__global__ __launch_bounds__(256) void cvtT4_k(
    const float* __restrict__ wq, const float* __restrict__ wk,
    const float* __restrict__ wv, const float* __restrict__ wo,
    __half* __restrict__ tq, __half* __restrict__ tk,
    __half* __restrict__ tv, __half* __restrict__ to_)
{
    const float* W;
    __half* T;
    switch (blockIdx.z) {
        case 0:  W = wq; T = tq;  break;
        case 1:  W = wk; T = tk;  break;
        case 2:  W = wv; T = tv;  break;
        default: W = wo; T = to_; break;
    }
    __shared__ float tile[32][33];
    int bx = blockIdx.x * 32, by = blockIdx.y * 32;
    int tx = threadIdx.x, ty = threadIdx.y;   // block (32,8)
    #pragma unroll
    for (int r = 0; r < 32; r += 8)
        tile[ty + r][tx] = W[(size_t)(by + ty + r) * DMODEL + bx + tx];
    __syncthreads();
    #pragma unroll
    for (int r = 0; r < 32; r += 8)
        T[(size_t)(bx + ty + r) * DMODEL + by + tx] = __float2half(tile[tx][ty + r]);
}

// ---------------- fp16 HMMA GEMM core ----------------
// C[M,N] = A[M,K] @ B^T, A [M,K] fp16 K-major, B [N,K] fp16 K-major.
// CTA tile 128x256, BK=32, 4-stage cp.async. 8 warps as 2m x 4n, warp tile 64x64.
#define NCHUNK 64
#define GS_A 0
#define GS_B 8192
#define GSTAGE 24576
#define GNST 4
#define GSMEM (GNST * GSTAGE)     // 98304

__device__ __forceinline__ void gemm_core(
    const __half* __restrict__ A, const __half* __restrict__ B,
    int m0, int n0, float (&acc)[4][8][4])
{
    extern __shared__ __align__(128) char smem[];
    const uint32_t sbase = s2u(smem);
    const int t = threadIdx.x;
    const int lane = t & 31, wid = t >> 5;
    const int wm = wid >> 2, wn = wid & 3;

    const char* pA = (const char*)(A + (size_t)m0 * DMODEL);
    const char* pB = (const char*)(B + (size_t)n0 * DMODEL);

    #pragma unroll
    for (int i = 0; i < 4; i++)
        #pragma unroll
        for (int j = 0; j < 8; j++)
            #pragma unroll
            for (int r = 0; r < 4; r++) acc[i][j][r] = 0.f;

    auto load_stage = [&](int s, int chunk) {
        uint32_t base = sbase + (uint32_t)s * GSTAGE;
        #pragma unroll
        for (int i = 0; i < 2; i++) {          // A: 128 rows x 64B
            int u = t + i * 256;
            int row = u >> 2, c = u & 3;
            uint32_t off = (uint32_t)(row * 64 + ((c ^ (row & 3)) * 16));
            CPASYNC16(base + GS_A + off,
                      pA + (size_t)row * 4096 + (size_t)chunk * 64 + c * 16);
        }
        #pragma unroll
        for (int i = 0; i < 4; i++) {          // B: 256 rows x 64B
            int u = t + i * 256;
            int row = u >> 2, c = u & 3;
            uint32_t off = (uint32_t)(row * 64 + ((c ^ (row & 3)) * 16));
            CPASYNC16(base + GS_B + off,
                      pB + (size_t)row * 4096 + (size_t)chunk * 64 + c * 16);
        }
        CPCOMMIT();
    };

    load_stage(0, 0);
    load_stage(1, 1);
    load_stage(2, 2);

    for (int ic = 0; ic < NCHUNK; ic++) {
        int rem = NCHUNK - 1 - ic;
        if (rem >= 2)      CPWAIT2();
        else if (rem == 1) CPWAIT1();
        else               CPWAIT0();
        __syncthreads();
        if (ic + 3 < NCHUNK) load_stage((ic + 3) % GNST, ic + 3);

        const uint32_t stb = sbase + (uint32_t)(ic % GNST) * GSTAGE;
        #pragma unroll
        for (int ks = 0; ks < 2; ks++) {
            uint32_t af[4][4];
            #pragma unroll
            for (int ms = 0; ms < 4; ms++) {
                int r = wm * 64 + ms * 16 + (lane & 15);
                uint32_t c = (uint32_t)((2 * ks + (lane >> 4)) ^ (r & 3));
                LDSM4(af[ms][0], af[ms][1], af[ms][2], af[ms][3],
                      stb + GS_A + (uint32_t)(r * 64) + c * 16);
            }
            #pragma unroll
            for (int ns = 0; ns < 8; ns++) {
                int rb = wn * 64 + ns * 8 + (lane & 7);
                uint32_t cb = (uint32_t)((2 * ks + ((lane >> 3) & 1)) ^ (rb & 3));
                uint32_t bf[2];
                LDSM2(bf[0], bf[1], stb + GS_B + (uint32_t)(rb * 64) + cb * 16);
                #pragma unroll
                for (int ms = 0; ms < 4; ms++)
                    MMAF16(acc[ms][ns], af[ms], bf);
            }
        }
    }
}

// QKV fused; z=0/1: rope fused in epilogue -> qf/kf fp16; z=2: vf fp16.
#define RS 272   // smem row stride (floats) for rope exchange buffer

__global__ __launch_bounds__(256, 1) void gemm_qkv(
    const __half* __restrict__ xf,
    const __half* __restrict__ wqT, const __half* __restrict__ wkT,
    const __half* __restrict__ wvT,
    const float* __restrict__ fcos, const float* __restrict__ fsin,
    __half* __restrict__ qf, __half* __restrict__ kf, __half* __restrict__ vf)
{
    const int z = blockIdx.z;
    const __half* B = (z == 0) ? wqT : (z == 1) ? wkT : wvT;
    const int n0 = blockIdx.x * 256;
    const int m0 = blockIdx.y * 128;
    float acc[4][8][4];
    gemm_core(xf, B, m0, n0, acc);

    const int lane = threadIdx.x & 31, wid = threadIdx.x >> 5;
    const int wm = wid >> 2, wn = wid & 3;

    if (z == 2) {
        #pragma unroll
        for (int ms = 0; ms < 4; ms++) {
            #pragma unroll
            for (int rh = 0; rh < 2; rh++) {
                int m = m0 + wm * 64 + ms * 16 + (lane >> 2) + rh * 8;
                int b = m >> 11, si = m & 2047;
                #pragma unroll
                for (int ns = 0; ns < 8; ns++) {
                    int n = n0 + wn * 64 + ns * 8 + 2 * (lane & 3);
                    int h = n >> 7, d = n & 127;
                    size_t idx = (((size_t)(b * NHEADS + h) * SEQ) + si) * HDIM + d;
                    float va = rh ? acc[ms][ns][2] : acc[ms][ns][0];
                    float vb = rh ? acc[ms][ns][3] : acc[ms][ns][1];
                    *(uint32_t*)(vf + idx) = packh2(va, vb);
                }
            }
        }
        return;
    }

    // ---- rope-fused epilogue for q/k ----
    extern __shared__ __align__(128) char smem[];
    float* sm = (float*)smem;          // [32][RS]
    const float qs = (z == 0) ? (0.08838834764831845f * 1.4426950408889634f) : 1.0f;
    __half* dst = (z == 0) ? qf : kf;
    const int h0 = n0 >> 7;

    #pragma unroll
    for (int ms = 0; ms < 4; ms++) {
        __syncthreads();   // buffer free (prev readers done / gemm stages unused region)
        #pragma unroll
        for (int rh = 0; rh < 2; rh++) {
            int lr = wm * 16 + (lane >> 2) + rh * 8;
            #pragma unroll
            for (int ns = 0; ns < 8; ns++) {
                int lc = wn * 64 + ns * 8 + 2 * (lane & 3);
                float va = rh ? acc[ms][ns][2] : acc[ms][ns][0];
                float vb = rh ? acc[ms][ns][3] : acc[ms][ns][1];
                *(float2*)&sm[lr * RS + lc] = make_float2(va, vb);
            }
        }
        __syncthreads();
        // 64 groups (row, head-block); warp handles 8; lane covers d = 2*lane, 2*lane+1
        #pragma unroll
        for (int i = 0; i < 8; i++) {
            int g = wid * 8 + i;        // 0..63
            int lr = g >> 1, blk = g & 1;
            int m = m0 + (lr >> 4) * 64 + ms * 16 + (lr & 15);
            int b = m >> 11, si = m & 2047;
            int d = 2 * lane;
            int col = blk * 128 + d;
            float2 v0 = *(float2*)&sm[lr * RS + col];        // d, d+1
            float2 v1 = *(float2*)&sm[lr * RS + col + 64];   // d+64, d+65
            float2 cc = *(const float2*)&fcos[si * 64 + d];
            float2 ss = *(const float2*)&fsin[si * 64 + d];
            float o0 = (v0.x * cc.x - v1.x * ss.x) * qs;
            float o1 = (v0.y * cc.y - v1.y * ss.y) * qs;
            float o2 = (v1.x * cc.x + v0.x * ss.x) * qs;
            float o3 = (v1.y * cc.y + v0.y * ss.y) * qs;
            int h = h0 + blk;
            size_t idx = (((size_t)(b * NHEADS + h) * SEQ) + si) * HDIM + d;
            *(uint32_t*)(dst + idx)      = packh2(o0, o1);
            *(uint32_t*)(dst + idx + 64) = packh2(o2, o3);
        }
    }
}

// WO: fp32 row-major out
__global__ __launch_bounds__(256, 1) void gemm_wo(
    const __half* __restrict__ attf, const __half* __restrict__ woT,
    float* __restrict__ out)
{
    const int n0 = blockIdx.x * 256;
    const int m0 = blockIdx.y * 128;
    float acc[4][8][4];
    gemm_core(attf, woT, m0, n0, acc);

    const int lane = threadIdx.x & 31, wid = threadIdx.x >> 5;
    const int wm = wid >> 2, wn = wid & 3;
    #pragma unroll
    for (int ms = 0; ms < 4; ms++) {
        #pragma unroll
        for (int rh = 0; rh < 2; rh++) {
            int m = m0 + wm * 64 + ms * 16 + (lane >> 2) + rh * 8;
            #pragma unroll
            for (int ns = 0; ns < 8; ns++) {
                int n = n0 + wn * 64 + ns * 8 + 2 * (lane & 3);
                float va = rh ? acc[ms][ns][2] : acc[ms][ns][0];
                float vb = rh ? acc[ms][ns][3] : acc[ms][ns][1];
                *(float2*)(out + (size_t)m * DMODEL + n) = make_float2(va, vb);
            }
        }
    }
}

// ---------------- fp16 HMMA flash attention, causal ----------------
// CTA: 128 q rows, 8 warps x 16 rows. K/V 128-key tiles, double buffered.
// LPT: heaviest q-tiles mapped to earliest-launched CTAs.
#define FQ 0
#define FST 32768
#define FSTG 65536
#define FK 0
#define FV 32768
#define FSMEM (32768 + 2 * 65536)   // 163840

__global__ __launch_bounds__(256, 1) void flash_f16(
    const __half* __restrict__ Qf, const __half* __restrict__ Kf,
    const __half* __restrict__ Vf, __half* __restrict__ Oatt)
{
    extern __shared__ __align__(128) char smem[];
    const uint32_t sb = s2u(smem);
    const int t = threadIdx.x, lane = t & 31, wid = t >> 5;
    const int bh = blockIdx.y;
    const int qt = gridDim.x - 1 - blockIdx.x;   // LPT: longest first
    const int m0 = qt * 128;
    const int ntiles = qt + 1;

    // Q tile: 128 rows x 256B
    {
        const char* gq = (const char*)(Qf + ((size_t)bh * SEQ + m0) * HDIM);
        #pragma unroll
        for (int i = 0; i < 8; i++) {
            int u = t + i * 256;
            int r = u >> 4, g = u & 15;
            uint32_t off = (uint32_t)(r * 256 + ((g ^ (r & 7)) * 16));
            CPASYNC16(sb + FQ + off, gq + (size_t)r * 256 + g * 16);
        }
        CPCOMMIT();
    }

    const char* gk = (const char*)(Kf + (size_t)bh * SEQ * HDIM);
    const char* gv = (const char*)(Vf + (size_t)bh * SEQ * HDIM);

    auto load_kv = [&](int s, int jt) {
        uint32_t stb = sb + FST + (uint32_t)s * FSTG;
        size_t base = (size_t)jt * 128 * 256;
        #pragma unroll
        for (int i = 0; i < 8; i++) {
            int u = t + i * 256;
            int r = u >> 4, g = u & 15;
            uint32_t off = (uint32_t)(r * 256 + ((g ^ (r & 7)) * 16));
            size_t go = base + (size_t)r * 256 + g * 16;
            CPASYNC16(stb + FK + off, gk + go);
            CPASYNC16(stb + FV + off, gv + go);
        }
        CPCOMMIT();
    };

    load_kv(0, 0);

    float oacc[16][4];
    #pragma unroll
    for (int i = 0; i < 16; i++)
        #pragma unroll
        for (int j = 0; j < 4; j++) oacc[i][j] = 0.f;
    float mrun0 = -1e30f, mrun1 = -1e30f, ls0 = 0.f, ls1 = 0.f;

    const int r0 = m0 + wid * 16 + (lane >> 2), r1 = r0 + 8;
    const int rowA = wid * 16 + (lane & 15);
    const int rbB = (lane & 7) | ((lane >> 1) & 8);

    for (int jt = 0; jt < ntiles; jt++) {
        const int s = jt & 1;
        CPWAIT0();
        __syncthreads();
        if (jt + 1 < ntiles) load_kv(s ^ 1, jt + 1);

        const uint32_t stb = sb + FST + (uint32_t)s * FSTG;
        float sacc[16][4];
        #pragma unroll
        for (int i = 0; i < 16; i++)
            #pragma unroll
            for (int j = 0; j < 4; j++) sacc[i][j] = 0.f;

        // ---- S = Q K^T
        #pragma unroll
        for (int k8 = 0; k8 < 8; k8++) {
            int gA = 2 * k8 + (lane >> 4);
            uint32_t aq[4];
            LDSM4(aq[0], aq[1], aq[2], aq[3],
                  sb + FQ + (uint32_t)(rowA * 256 + ((gA ^ (rowA & 7)) * 16)));
            int gB = 2 * k8 + ((lane >> 3) & 1);
            #pragma unroll
            for (int np = 0; np < 8; np++) {
                int rowB = np * 16 + rbB;
                uint32_t bk[4];
                LDSM4(bk[0], bk[1], bk[2], bk[3],
                      stb + FK + (uint32_t)(rowB * 256 + ((gB ^ (rowB & 7)) * 16)));
                MMAF16(sacc[2 * np],     aq, &bk[0]);
                MMAF16(sacc[2 * np + 1], aq, &bk[2]);
            }
        }

        // ---- causal mask (diagonal tile only)
        if (jt == ntiles - 1) {
            const int k0 = jt * 128;
            #pragma unroll
            for (int nt = 0; nt < 16; nt++) {
                int c = k0 + nt * 8 + 2 * (lane & 3);
                if (c     > r0) sacc[nt][0] = -1e30f;
                if (c + 1 > r0) sacc[nt][1] = -1e30f;
                if (c     > r1) sacc[nt][2] = -1e30f;
                if (c + 1 > r1) sacc[nt][3] = -1e30f;
            }
        }

        // ---- online softmax (log2 domain; scale*log2e folded into Q)
        float ml0 = -1e30f, ml1 = -1e30f;
        #pragma unroll
        for (int nt = 0; nt < 16; nt++) {
            ml0 = fmaxf(ml0, fmaxf(sacc[nt][0], sacc[nt][1]));
            ml1 = fmaxf(ml1, fmaxf(sacc[nt][2], sacc[nt][3]));
        }
        ml0 = fmaxf(ml0, __shfl_xor_sync(0xffffffffu, ml0, 1));
        ml0 = fmaxf(ml0, __shfl_xor_sync(0xffffffffu, ml0, 2));
        ml1 = fmaxf(ml1, __shfl_xor_sync(0xffffffffu, ml1, 1));
        ml1 = fmaxf(ml1, __shfl_xor_sync(0xffffffffu, ml1, 2));
        float mn0 = fmaxf(mrun0, ml0), mn1 = fmaxf(mrun1, ml1);
        float c0 = exp2f(mrun0 - mn0), c1 = exp2f(mrun1 - mn1);
        mrun0 = mn0; mrun1 = mn1;
        ls0 *= c0; ls1 *= c1;
        #pragma unroll
        for (int nt = 0; nt < 16; nt++) {
            oacc[nt][0] *= c0; oacc[nt][1] *= c0;
            oacc[nt][2] *= c1; oacc[nt][3] *= c1;
        }
        float ps0 = 0.f, ps1 = 0.f;
        #pragma unroll
        for (int nt = 0; nt < 16; nt++) {
            sacc[nt][0] = exp2f(sacc[nt][0] - mn0);
            sacc[nt][1] = exp2f(sacc[nt][1] - mn0);
            sacc[nt][2] = exp2f(sacc[nt][2] - mn1);
            sacc[nt][3] = exp2f(sacc[nt][3] - mn1);
            ps0 += sacc[nt][0] + sacc[nt][1];
            ps1 += sacc[nt][2] + sacc[nt][3];
        }
        ls0 += ps0; ls1 += ps1;

        // ---- O += P V ; P C-frags repack as fp16 A-frags
        #pragma unroll
        for (int kp = 0; kp < 8; kp++) {
            uint32_t pa[4];
            pa[0] = packh2(sacc[2 * kp][0],     sacc[2 * kp][1]);
            pa[1] = packh2(sacc[2 * kp][2],     sacc[2 * kp][3]);
            pa[2] = packh2(sacc[2 * kp + 1][0], sacc[2 * kp + 1][1]);
            pa[3] = packh2(sacc[2 * kp + 1][2], sacc[2 * kp + 1][3]);
            int rv = kp * 16 + (lane & 15);
            #pragma unroll
            for (int dp = 0; dp < 8; dp++) {
                int gV = 2 * dp + (lane >> 4);
                uint32_t vv[4];
                LDSM4T(vv, stb + FV + (uint32_t)(rv * 256 + ((gV ^ (rv & 7)) * 16)));
                MMAF16(oacc[2 * dp],     pa, &vv[0]);
                MMAF16(oacc[2 * dp + 1], pa, &vv[2]);
            }
        }
    }

    // ---- epilogue: normalize, fp16, write att [B*S, H*hd]
    float lt0 = ls0 + __shfl_xor_sync(0xffffffffu, ls0, 1);
    lt0 += __shfl_xor_sync(0xffffffffu, lt0, 2);
    float lt1 = ls1 + __shfl_xor_sync(0xffffffffu, ls1, 1);
    lt1 += __shfl_xor_sync(0xffffffffu, lt1, 2);
    float inv0 = 1.f / lt0, inv1 = 1.f / lt1;

    const int b = bh >> 4, h = bh & 15;
    size_t base0 = ((size_t)(b * SEQ) + r0) * DMODEL + h * HDIM;
    size_t base1 = base0 + (size_t)8 * DMODEL;
    #pragma unroll
    for (int nt = 0; nt < 16; nt++) {
        int d = nt * 8 + 2 * (lane & 3);
        *(uint32_t*)(Oatt + base0 + d) = packh2(oacc[nt][0] * inv0, oacc[nt][1] * inv0);
        *(uint32_t*)(Oatt + base1 + d) = packh2(oacc[nt][2] * inv1, oacc[nt][3] * inv1);
    }
}

// ---------------- launch ----------------
extern "C" void kernel_launch(void* const* d_in, const int* in_sizes, int n_in,
                              void* d_out, int out_size)
{
    (void)in_sizes; (void)n_in; (void)out_size;
    const float* x    = (const float*)d_in[0];
    const float* fcos = (const float*)d_in[1];
    const float* fsin = (const float*)d_in[2];
    const float* wq   = (const float*)d_in[3];
    const float* wk   = (const float*)d_in[4];
    const float* wv   = (const float*)d_in[5];
    const float* wo   = (const float*)d_in[6];
    float* out = (float*)d_out;

    __half *xf, *attf, *qf, *kf, *vf, *wqT, *wkT, *wvT, *woT;
    cudaGetSymbolAddress((void**)&xf,   g_xf);
    cudaGetSymbolAddress((void**)&attf, g_attf);
    cudaGetSymbolAddress((void**)&qf,   g_qf);
    cudaGetSymbolAddress((void**)&kf,   g_kf);
    cudaGetSymbolAddress((void**)&vf,   g_vf);
    cudaGetSymbolAddress((void**)&wqT,  g_wqT);
    cudaGetSymbolAddress((void**)&wkT,  g_wkT);
    cudaGetSymbolAddress((void**)&wvT,  g_wvT);
    cudaGetSymbolAddress((void**)&woT,  g_woT);

    cudaFuncSetAttribute(gemm_qkv, cudaFuncAttributeMaxDynamicSharedMemorySize, GSMEM);
    cudaFuncSetAttribute(gemm_wo,  cudaFuncAttributeMaxDynamicSharedMemorySize, GSMEM);
    cudaFuncSetAttribute(flash_f16, cudaFuncAttributeMaxDynamicSharedMemorySize, FSMEM);

    // conversions
    cvt_k<<<QKV_ELEMS / 4 / 256, 256>>>(x, xf, QKV_ELEMS / 4);
    cvtT4_k<<<dim3(DMODEL / 32, DMODEL / 32, 4), dim3(32, 8)>>>(
        wq, wk, wv, wo, wqT, wkT, wvT, woT);

    // fused QKV GEMM with rope-fused epilogue
    dim3 gq3(DMODEL / 256, ROWS / 128, 3);   // (8, 32, 3)
    gemm_qkv<<<gq3, 256, GSMEM>>>(xf, wqT, wkT, wvT, fcos, fsin, qf, kf, vf);

    flash_f16<<<dim3(SEQ / 128, BATCH * NHEADS), 256, FSMEM>>>(qf, kf, vf, attf);

    gemm_wo<<<dim3(DMODEL / 256, ROWS / 128), 256, GSMEM>>>(attf, woT, out);
}

// round 11
// speedup vs baseline: 9.2255x; 1.1280x over previous
#include <cuda_runtime.h>
#include <cuda_fp16.h>
#include <cstdint>

// Problem constants
#define BATCH 2
#define SEQ   2048
#define DMODEL 2048
#define NHEADS 16
#define HDIM  128
#define ROWS  (BATCH * SEQ)          // 4096
#define QKV_ELEMS (ROWS * DMODEL)    // 8388608
#define WELEMS (DMODEL * DMODEL)     // 4194304

// ---------------- scratch (device globals; no allocation) ----------------
// All intermediates stored as contiguous pre-swizzled tile images:
//  A-image  : 8KB block per (m-panel128, k-chunk32): row*64 + ((u^(row&3))*16), u=kk>>3
//  B-image  : 16KB block per (n-panel256, k-chunk32): row*64 + ((u^(row&3))*16)
//  F-image  : 32KB block per (head, seq-tile128): row*256 + ((g^(row&7))*16), g=d>>3
__device__ __align__(256) __half g_xb[QKV_ELEMS];                  // A-image
__device__ __align__(256) __half g_attb[QKV_ELEMS];                // A-image
__device__ __align__(256) __half g_qb[QKV_ELEMS], g_kb[QKV_ELEMS], g_vb[QKV_ELEMS]; // F-image
__device__ __align__(256) __half g_wqT[WELEMS], g_wkT[WELEMS];     // B-image
__device__ __align__(256) __half g_wvT[WELEMS], g_woT[WELEMS];     // B-image

// ---------------- PTX helpers ----------------
__device__ __forceinline__ uint32_t s2u(const void* p) {
    uint32_t a;
    asm("{ .reg .u64 t; cvta.to.shared.u64 t, %1; cvt.u32.u64 %0, t; }"
        : "=r"(a) : "l"(p));
    return a;
}
#define MBINIT(a, c) asm volatile("mbarrier.init.shared.b64 [%0], %1;" :: "r"(a), "r"(c) : "memory")
#define MBEXPECT(a, tx) asm volatile("mbarrier.arrive.expect_tx.shared.b64 _, [%0], %1;" :: "r"(a), "r"(tx) : "memory")
#define MBWAIT(a, ph) do { \
    uint32_t _m = (a), _p = (ph), _d; \
    asm volatile("{ .reg .pred p; mbarrier.try_wait.parity.acquire.cta.shared::cta.b64 p, [%1], %2; selp.b32 %0,1,0,p; }" \
                 : "=r"(_d) : "r"(_m), "r"(_p) : "memory"); \
    if (!_d) { \
        asm volatile("{ .reg .pred P1; WL%=: mbarrier.try_wait.parity.acquire.cta.shared::cta.b64 P1, [%0], %1, 0x989680; @P1 bra.uni WD%=; bra.uni WL%=; WD%=: }" \
                     :: "r"(_m), "r"(_p) : "memory"); \
    } } while (0)
#define BULKG2S(dst, src, bytes, mbar) \
    asm volatile("cp.async.bulk.shared::cluster.global.mbarrier::complete_tx::bytes [%0], [%1], %2, [%3];" \
                 :: "r"(dst), "l"(src), "r"(bytes), "r"(mbar) : "memory")

#define LDSM4(r0, r1, r2, r3, a) \
    asm volatile("ldmatrix.sync.aligned.m8n8.x4.shared.b16 {%0,%1,%2,%3}, [%4];" \
                 : "=r"(r0), "=r"(r1), "=r"(r2), "=r"(r3) : "r"(a))
#define LDSM2(r0, r1, a) \
    asm volatile("ldmatrix.sync.aligned.m8n8.x2.shared.b16 {%0,%1}, [%2];" \
                 : "=r"(r0), "=r"(r1) : "r"(a))
#define LDSM4T(r, a) \
    asm volatile("ldmatrix.sync.aligned.m8n8.x4.trans.shared.b16 {%0,%1,%2,%3}, [%4];" \
                 : "=r"((r)[0]), "=r"((r)[1]), "=r"((r)[2]), "=r"((r)[3]) : "r"(a))

#define MMAF16(c, a, b) \
    asm volatile("mma.sync.aligned.m16n8k16.row.col.f32.f16.f16.f32 " \
                 "{%0,%1,%2,%3}, {%4,%5,%6,%7}, {%8,%9}, {%0,%1,%2,%3};" \
                 : "+f"((c)[0]), "+f"((c)[1]), "+f"((c)[2]), "+f"((c)[3]) \
                 : "r"((a)[0]), "r"((a)[1]), "r"((a)[2]), "r"((a)[3]), \
                   "r"((b)[0]), "r"((b)[1]))

__device__ __forceinline__ uint32_t packh2(float a, float b) {
    __half2 h = __floats2half2_rn(a, b);
    return *(uint32_t*)&h;
}

// ---------------- conversions ----------------
// x fp32 [4096,2048] -> A-image blocks. One CTA per 8KB block.
__global__ __launch_bounds__(256) void cvt_x(
    const float* __restrict__ x, __half* __restrict__ xb)
{
    int blk = blockIdx.x;                 // p*64 + ch
    int p = blk >> 6, ch = blk & 63;
    const float* src = x + (size_t)p * 128 * 2048 + ch * 32;
    char* dst = (char*)(xb + (size_t)blk * 4096);
    int t = threadIdx.x;
    #pragma unroll
    for (int i = 0; i < 2; i++) {
        int u = t + i * 256;              // 0..511
        int row = u >> 2, c16 = u & 3;
        const float4* s4 = (const float4*)(src + (size_t)row * 2048 + c16 * 8);
        float4 a = s4[0], b = s4[1];
        uint4 o;
        o.x = packh2(a.x, a.y); o.y = packh2(a.z, a.w);
        o.z = packh2(b.x, b.y); o.w = packh2(b.z, b.w);
        *(uint4*)(dst + row * 64 + ((c16 ^ (row & 3)) * 16)) = o;
    }
}

// 4 weights W[K,N] fp32 -> B-image blocks, one launch (z selects matrix)
__global__ __launch_bounds__(256) void cvtT4_k(
    const float* __restrict__ wq, const float* __restrict__ wk,
    const float* __restrict__ wv, const float* __restrict__ wo,
    __half* __restrict__ tq, __half* __restrict__ tk,
    __half* __restrict__ tv, __half* __restrict__ to_)
{
    const float* W;
    __half* T;
    switch (blockIdx.z) {
        case 0:  W = wq; T = tq;  break;
        case 1:  W = wk; T = tk;  break;
        case 2:  W = wv; T = tv;  break;
        default: W = wo; T = to_; break;
    }
    __shared__ float tile[32][33];
    int bx = blockIdx.x * 32, by = blockIdx.y * 32;
    int tx = threadIdx.x, ty = threadIdx.y;   // block (32,8)
    #pragma unroll
    for (int r = 0; r < 32; r += 8)
        tile[ty + r][tx] = W[(size_t)(by + ty + r) * DMODEL + bx + tx];
    __syncthreads();
    #pragma unroll
    for (int r = 0; r < 32; r += 8) {
        int rr = bx + ty + r;       // n index
        int kk = by + tx;           // k index
        size_t blk = (size_t)((rr >> 8) * 64 + (kk >> 5));
        uint32_t off = (uint32_t)((rr & 255) * 64 +
                       ((((kk & 31) >> 3) ^ (rr & 3)) * 16) + (kk & 7) * 2);
        *(__half*)((char*)T + blk * 16384 + off) = __float2half(tile[tx][ty + r]);
    }
}

// ---------------- fp16 HMMA GEMM core (bulk-copy pipeline) ----------------
// CTA tile 128x256, BK=32, 4-stage. 8 warps as 2m x 4n, warp tile 64x64.
#define NCHUNK 64
#define GS_A 0
#define GS_B 8192
#define GSTAGE 24576
#define GNST 4
#define GBAR (GNST * GSTAGE)       // 98304
#define GSMEM (GBAR + 64)

__device__ __forceinline__ void gemm_core(
    const char* __restrict__ pA,   // A-image block base for this m-panel
    const char* __restrict__ pB,   // B-image block base for this n-panel
    float (&acc)[4][8][4])
{
    extern __shared__ __align__(128) char smem[];
    const uint32_t sbase = s2u(smem);
    const uint32_t mb = sbase + GBAR;
    const int t = threadIdx.x;
    const int lane = t & 31, wid = t >> 5;
    const int wm = wid >> 2, wn = wid & 3;

    #pragma unroll
    for (int i = 0; i < 4; i++)
        #pragma unroll
        for (int j = 0; j < 8; j++)
            #pragma unroll
            for (int r = 0; r < 4; r++) acc[i][j][r] = 0.f;

    if (t == 0) {
        #pragma unroll
        for (int s = 0; s < GNST; s++) MBINIT(mb + s * 8, 1);
    }
    __syncthreads();
    if (t == 0) {
        #pragma unroll
        for (int s = 0; s < 3; s++) {
            MBEXPECT(mb + s * 8, 24576u);
            BULKG2S(sbase + s * GSTAGE + GS_A, pA + (size_t)s * 8192,  8192u,  mb + s * 8);
            BULKG2S(sbase + s * GSTAGE + GS_B, pB + (size_t)s * 16384, 16384u, mb + s * 8);
        }
    }

    for (int ic = 0; ic < NCHUNK; ic++) {
        const int s = ic & 3;
        if (ic > 0) __syncthreads();    // all warps done with stage (ic-1)&3
        if (t == 0 && ic + 3 < NCHUNK) {
            int c = ic + 3, ss = c & 3;
            MBEXPECT(mb + ss * 8, 24576u);
            BULKG2S(sbase + ss * GSTAGE + GS_A, pA + (size_t)c * 8192,  8192u,  mb + ss * 8);
            BULKG2S(sbase + ss * GSTAGE + GS_B, pB + (size_t)c * 16384, 16384u, mb + ss * 8);
        }
        MBWAIT(mb + s * 8, (ic >> 2) & 1);

        const uint32_t stb = sbase + (uint32_t)s * GSTAGE;
        #pragma unroll
        for (int ks = 0; ks < 2; ks++) {
            uint32_t af[4][4];
            #pragma unroll
            for (int ms = 0; ms < 4; ms++) {
                int r = wm * 64 + ms * 16 + (lane & 15);
                uint32_t c = (uint32_t)((2 * ks + (lane >> 4)) ^ (r & 3));
                LDSM4(af[ms][0], af[ms][1], af[ms][2], af[ms][3],
                      stb + GS_A + (uint32_t)(r * 64) + c * 16);
            }
            #pragma unroll
            for (int ns = 0; ns < 8; ns++) {
                int rb = wn * 64 + ns * 8 + (lane & 7);
                uint32_t cb = (uint32_t)((2 * ks + ((lane >> 3) & 1)) ^ (rb & 3));
                uint32_t bf[2];
                LDSM2(bf[0], bf[1], stb + GS_B + (uint32_t)(rb * 64) + cb * 16);
                #pragma unroll
                for (int ms = 0; ms < 4; ms++)
                    MMAF16(acc[ms][ns], af[ms], bf);
            }
        }
    }
    __syncthreads();
}

// QKV fused; z=0/1: rope fused -> qb/kb (F-image); z=2: vb (F-image).
#define RS 272   // smem row stride (floats) for rope exchange buffer

__global__ __launch_bounds__(256, 1) void gemm_qkv(
    const __half* __restrict__ xb,
    const __half* __restrict__ wqT, const __half* __restrict__ wkT,
    const __half* __restrict__ wvT,
    const float* __restrict__ fcos, const float* __restrict__ fsin,
    __half* __restrict__ qb, __half* __restrict__ kb, __half* __restrict__ vb)
{
    const int z = blockIdx.z;
    const __half* B = (z == 0) ? wqT : (z == 1) ? wkT : wvT;
    const int n0 = blockIdx.x * 256;
    const int m0 = blockIdx.y * 128;
    float acc[4][8][4];
    gemm_core((const char*)xb + (size_t)(m0 >> 7) * 64 * 8192,
              (const char*)B  + (size_t)(n0 >> 8) * 64 * 16384, acc);

    const int lane = threadIdx.x & 31, wid = threadIdx.x >> 5;
    const int wm = wid >> 2, wn = wid & 3;

    if (z == 2) {
        #pragma unroll
        for (int ms = 0; ms < 4; ms++) {
            #pragma unroll
            for (int rh = 0; rh < 2; rh++) {
                int m = m0 + wm * 64 + ms * 16 + (lane >> 2) + rh * 8;
                int b = m >> 11, si = m & 2047;
                #pragma unroll
                for (int ns = 0; ns < 8; ns++) {
                    int n = n0 + wn * 64 + ns * 8 + 2 * (lane & 3);
                    int h = n >> 7, d = n & 127;
                    float va = rh ? acc[ms][ns][2] : acc[ms][ns][0];
                    float vb_ = rh ? acc[ms][ns][3] : acc[ms][ns][1];
                    size_t blk = (size_t)((b * 16 + h) * 16 + (si >> 7));
                    uint32_t off = (uint32_t)((si & 127) * 256 +
                                   (((d >> 3) ^ (si & 7)) * 16) + (d & 7) * 2);
                    *(uint32_t*)((char*)vb + blk * 32768 + off) = packh2(va, vb_);
                }
            }
        }
        return;
    }

    // ---- rope-fused epilogue for q/k -> F-image ----
    extern __shared__ __align__(128) char smem[];
    float* sm = (float*)smem;          // [32][RS] (stages no longer in use)
    const float qs = (z == 0) ? (0.08838834764831845f * 1.4426950408889634f) : 1.0f;
    __half* dst = (z == 0) ? qb : kb;
    const int h0 = n0 >> 7;

    #pragma unroll
    for (int ms = 0; ms < 4; ms++) {
        __syncthreads();
        #pragma unroll
        for (int rh = 0; rh < 2; rh++) {
            int lr = wm * 16 + (lane >> 2) + rh * 8;
            #pragma unroll
            for (int ns = 0; ns < 8; ns++) {
                int lc = wn * 64 + ns * 8 + 2 * (lane & 3);
                float va = rh ? acc[ms][ns][2] : acc[ms][ns][0];
                float vb_ = rh ? acc[ms][ns][3] : acc[ms][ns][1];
                *(float2*)&sm[lr * RS + lc] = make_float2(va, vb_);
            }
        }
        __syncthreads();
        #pragma unroll
        for (int i = 0; i < 8; i++) {
            int g = wid * 8 + i;        // 0..63
            int lr = g >> 1, blkh = g & 1;
            int m = m0 + (lr >> 4) * 64 + ms * 16 + (lr & 15);
            int b = m >> 11, si = m & 2047;
            int d = 2 * lane;           // 0..62
            int col = blkh * 128 + d;
            float2 v0 = *(float2*)&sm[lr * RS + col];
            float2 v1 = *(float2*)&sm[lr * RS + col + 64];
            float2 cc = *(const float2*)&fcos[si * 64 + d];
            float2 ss = *(const float2*)&fsin[si * 64 + d];
            float o0 = (v0.x * cc.x - v1.x * ss.x) * qs;
            float o1 = (v0.y * cc.y - v1.y * ss.y) * qs;
            float o2 = (v1.x * cc.x + v0.x * ss.x) * qs;
            float o3 = (v1.y * cc.y + v0.y * ss.y) * qs;
            int h = h0 + blkh;
            size_t blk = (size_t)((b * 16 + h) * 16 + (si >> 7));
            char* bp = (char*)dst + blk * 32768;
            uint32_t r = (uint32_t)(si & 127);
            uint32_t off0 = r * 256 + (((d >> 3) ^ (r & 7)) * 16) + (d & 7) * 2;
            uint32_t off1 = r * 256 + ((((d + 64) >> 3) ^ (r & 7)) * 16) + (d & 7) * 2;
            *(uint32_t*)(bp + off0) = packh2(o0, o1);
            *(uint32_t*)(bp + off1) = packh2(o2, o3);
        }
    }
}

// WO: fp32 row-major out
__global__ __launch_bounds__(256, 1) void gemm_wo(
    const __half* __restrict__ attb, const __half* __restrict__ woT,
    float* __restrict__ out)
{
    const int n0 = blockIdx.x * 256;
    const int m0 = blockIdx.y * 128;
    float acc[4][8][4];
    gemm_core((const char*)attb + (size_t)(m0 >> 7) * 64 * 8192,
              (const char*)woT  + (size_t)(n0 >> 8) * 64 * 16384, acc);

    const int lane = threadIdx.x & 31, wid = threadIdx.x >> 5;
    const int wm = wid >> 2, wn = wid & 3;
    #pragma unroll
    for (int ms = 0; ms < 4; ms++) {
        #pragma unroll
        for (int rh = 0; rh < 2; rh++) {
            int m = m0 + wm * 64 + ms * 16 + (lane >> 2) + rh * 8;
            #pragma unroll
            for (int ns = 0; ns < 8; ns++) {
                int n = n0 + wn * 64 + ns * 8 + 2 * (lane & 3);
                float va = rh ? acc[ms][ns][2] : acc[ms][ns][0];
                float vb = rh ? acc[ms][ns][3] : acc[ms][ns][1];
                *(float2*)(out + (size_t)m * DMODEL + n) = make_float2(va, vb);
            }
        }
    }
}

// ---------------- fp16 HMMA flash attention, causal (bulk-copy) ----------------
#define FQ 0
#define FST 32768
#define FSTG 65536
#define FK 0
#define FV 32768
#define FBAR (32768 + 2 * 65536)   // 163840
#define FSMEM (FBAR + 64)

__global__ __launch_bounds__(256, 1) void flash_f16(
    const __half* __restrict__ Qb, const __half* __restrict__ Kb,
    const __half* __restrict__ Vb, __half* __restrict__ Ob)
{
    extern __shared__ __align__(128) char smem[];
    const uint32_t sb = s2u(smem);
    const uint32_t mbQ = sb + FBAR, mbKV = sb + FBAR + 8;  // +8*s
    const int t = threadIdx.x, lane = t & 31, wid = t >> 5;
    const int bh = blockIdx.y;
    const int qt = gridDim.x - 1 - blockIdx.x;   // LPT: longest first
    const int m0 = qt * 128;
    const int ntiles = qt + 1;

    const char* gq = (const char*)Qb + (size_t)(bh * 16 + qt) * 32768;
    const char* gk = (const char*)Kb + (size_t)(bh * 16) * 32768;
    const char* gv = (const char*)Vb + (size_t)(bh * 16) * 32768;

    if (t == 0) { MBINIT(mbQ, 1); MBINIT(mbKV, 1); MBINIT(mbKV + 8, 1); }
    __syncthreads();
    if (t == 0) {
        MBEXPECT(mbQ, 32768u);
        BULKG2S(sb + FQ, gq, 32768u, mbQ);
        MBEXPECT(mbKV, 65536u);
        BULKG2S(sb + FST + FK, gk, 32768u, mbKV);
        BULKG2S(sb + FST + FV, gv, 32768u, mbKV);
    }
    MBWAIT(mbQ, 0);

    float oacc[16][4];
    #pragma unroll
    for (int i = 0; i < 16; i++)
        #pragma unroll
        for (int j = 0; j < 4; j++) oacc[i][j] = 0.f;
    float mrun0 = -1e30f, mrun1 = -1e30f, ls0 = 0.f, ls1 = 0.f;

    const int r0 = m0 + wid * 16 + (lane >> 2), r1 = r0 + 8;
    const int rowA = wid * 16 + (lane & 15);
    const int rbB = (lane & 7) | ((lane >> 1) & 8);

    for (int jt = 0; jt < ntiles; jt++) {
        const int s = jt & 1;
        if (jt > 0) __syncthreads();   // all warps done with stage s^1 (used at jt-1)
        if (t == 0 && jt + 1 < ntiles) {
            uint32_t mbn = mbKV + (uint32_t)(s ^ 1) * 8;
            MBEXPECT(mbn, 65536u);
            BULKG2S(sb + FST + (uint32_t)(s ^ 1) * FSTG + FK,
                    gk + (size_t)(jt + 1) * 32768, 32768u, mbn);
            BULKG2S(sb + FST + (uint32_t)(s ^ 1) * FSTG + FV,
                    gv + (size_t)(jt + 1) * 32768, 32768u, mbn);
        }
        MBWAIT(mbKV + (uint32_t)s * 8, (jt >> 1) & 1);

        const uint32_t stb = sb + FST + (uint32_t)s * FSTG;
        float sacc[16][4];
        #pragma unroll
        for (int i = 0; i < 16; i++)
            #pragma unroll
            for (int j = 0; j < 4; j++) sacc[i][j] = 0.f;

        // ---- S = Q K^T
        #pragma unroll
        for (int k8 = 0; k8 < 8; k8++) {
            int gA = 2 * k8 + (lane >> 4);
            uint32_t aq[4];
            LDSM4(aq[0], aq[1], aq[2], aq[3],
                  sb + FQ + (uint32_t)(rowA * 256 + ((gA ^ (rowA & 7)) * 16)));
            int gB = 2 * k8 + ((lane >> 3) & 1);
            #pragma unroll
            for (int np = 0; np < 8; np++) {
                int rowB = np * 16 + rbB;
                uint32_t bk[4];
                LDSM4(bk[0], bk[1], bk[2], bk[3],
                      stb + FK + (uint32_t)(rowB * 256 + ((gB ^ (rowB & 7)) * 16)));
                MMAF16(sacc[2 * np],     aq, &bk[0]);
                MMAF16(sacc[2 * np + 1], aq, &bk[2]);
            }
        }

        // ---- causal mask (diagonal tile only)
        if (jt == ntiles - 1) {
            const int k0 = jt * 128;
            #pragma unroll
            for (int nt = 0; nt < 16; nt++) {
                int c = k0 + nt * 8 + 2 * (lane & 3);
                if (c     > r0) sacc[nt][0] = -1e30f;
                if (c + 1 > r0) sacc[nt][1] = -1e30f;
                if (c     > r1) sacc[nt][2] = -1e30f;
                if (c + 1 > r1) sacc[nt][3] = -1e30f;
            }
        }

        // ---- online softmax (log2 domain; scale*log2e folded into Q)
        float ml0 = -1e30f, ml1 = -1e30f;
        #pragma unroll
        for (int nt = 0; nt < 16; nt++) {
            ml0 = fmaxf(ml0, fmaxf(sacc[nt][0], sacc[nt][1]));
            ml1 = fmaxf(ml1, fmaxf(sacc[nt][2], sacc[nt][3]));
        }
        ml0 = fmaxf(ml0, __shfl_xor_sync(0xffffffffu, ml0, 1));
        ml0 = fmaxf(ml0, __shfl_xor_sync(0xffffffffu, ml0, 2));
        ml1 = fmaxf(ml1, __shfl_xor_sync(0xffffffffu, ml1, 1));
        ml1 = fmaxf(ml1, __shfl_xor_sync(0xffffffffu, ml1, 2));
        float mn0 = fmaxf(mrun0, ml0), mn1 = fmaxf(mrun1, ml1);
        float c0 = exp2f(mrun0 - mn0), c1 = exp2f(mrun1 - mn1);
        mrun0 = mn0; mrun1 = mn1;
        ls0 *= c0; ls1 *= c1;
        #pragma unroll
        for (int nt = 0; nt < 16; nt++) {
            oacc[nt][0] *= c0; oacc[nt][1] *= c0;
            oacc[nt][2] *= c1; oacc[nt][3] *= c1;
        }
        float ps0 = 0.f, ps1 = 0.f;
        #pragma unroll
        for (int nt = 0; nt < 16; nt++) {
            sacc[nt][0] = exp2f(sacc[nt][0] - mn0);
            sacc[nt][1] = exp2f(sacc[nt][1] - mn0);
            sacc[nt][2] = exp2f(sacc[nt][2] - mn1);
            sacc[nt][3] = exp2f(sacc[nt][3] - mn1);
            ps0 += sacc[nt][0] + sacc[nt][1];
            ps1 += sacc[nt][2] + sacc[nt][3];
        }
        ls0 += ps0; ls1 += ps1;

        // ---- O += P V ; P C-frags repack as fp16 A-frags
        #pragma unroll
        for (int kp = 0; kp < 8; kp++) {
            uint32_t pa[4];
            pa[0] = packh2(sacc[2 * kp][0],     sacc[2 * kp][1]);
            pa[1] = packh2(sacc[2 * kp][2],     sacc[2 * kp][3]);
            pa[2] = packh2(sacc[2 * kp + 1][0], sacc[2 * kp + 1][1]);
            pa[3] = packh2(sacc[2 * kp + 1][2], sacc[2 * kp + 1][3]);
            int rv = kp * 16 + (lane & 15);
            #pragma unroll
            for (int dp = 0; dp < 8; dp++) {
                int gV = 2 * dp + (lane >> 4);
                uint32_t vv[4];
                LDSM4T(vv, stb + FV + (uint32_t)(rv * 256 + ((gV ^ (rv & 7)) * 16)));
                MMAF16(oacc[2 * dp],     pa, &vv[0]);
                MMAF16(oacc[2 * dp + 1], pa, &vv[2]);
            }
        }
    }

    // ---- epilogue: normalize, write att as A-image blocks
    float lt0 = ls0 + __shfl_xor_sync(0xffffffffu, ls0, 1);
    lt0 += __shfl_xor_sync(0xffffffffu, lt0, 2);
    float lt1 = ls1 + __shfl_xor_sync(0xffffffffu, ls1, 1);
    lt1 += __shfl_xor_sync(0xffffffffu, lt1, 2);
    float inv0 = 1.f / lt0, inv1 = 1.f / lt1;

    const int b = bh >> 4, h = bh & 15;
    // att row m = b*2048 + s; panel = b*16 + (s>>7); col = h*128 + d
    const size_t pbase = (size_t)((b * 16 + (r0 >> 7)) * 64) * 8192;
    #pragma unroll
    for (int nt = 0; nt < 16; nt++) {
        int d = nt * 8 + 2 * (lane & 3);
        int col = h * 128 + d;
        size_t blk = pbase + (size_t)(col >> 5) * 8192;
        uint32_t u = (uint32_t)((d & 31) >> 3);
        uint32_t rA = (uint32_t)(r0 & 127), rB = (uint32_t)(r1 & 127);
        uint32_t offA = rA * 64 + ((u ^ (rA & 3)) * 16) + (d & 7) * 2;
        uint32_t offB = rB * 64 + ((u ^ (rB & 3)) * 16) + (d & 7) * 2;
        *(uint32_t*)((char*)Ob + blk + offA) = packh2(oacc[nt][0] * inv0, oacc[nt][1] * inv0);
        *(uint32_t*)((char*)Ob + blk + offB) = packh2(oacc[nt][2] * inv1, oacc[nt][3] * inv1);
    }
}

// ---------------- launch ----------------
extern "C" void kernel_launch(void* const* d_in, const int* in_sizes, int n_in,
                              void* d_out, int out_size)
{
    (void)in_sizes; (void)n_in; (void)out_size;
    const float* x    = (const float*)d_in[0];
    const float* fcos = (const float*)d_in[1];
    const float* fsin = (const float*)d_in[2];
    const float* wq   = (const float*)d_in[3];
    const float* wk   = (const float*)d_in[4];
    const float* wv   = (const float*)d_in[5];
    const float* wo   = (const float*)d_in[6];
    float* out = (float*)d_out;

    __half *xb, *attb, *qb, *kb, *vb, *wqT, *wkT, *wvT, *woT;
    cudaGetSymbolAddress((void**)&xb,   g_xb);
    cudaGetSymbolAddress((void**)&attb, g_attb);
    cudaGetSymbolAddress((void**)&qb,   g_qb);
    cudaGetSymbolAddress((void**)&kb,   g_kb);
    cudaGetSymbolAddress((void**)&vb,   g_vb);
    cudaGetSymbolAddress((void**)&wqT,  g_wqT);
    cudaGetSymbolAddress((void**)&wkT,  g_wkT);
    cudaGetSymbolAddress((void**)&wvT,  g_wvT);
    cudaGetSymbolAddress((void**)&woT,  g_woT);

    cudaFuncSetAttribute(gemm_qkv, cudaFuncAttributeMaxDynamicSharedMemorySize, GSMEM);
    cudaFuncSetAttribute(gemm_wo,  cudaFuncAttributeMaxDynamicSharedMemorySize, GSMEM);
    cudaFuncSetAttribute(flash_f16, cudaFuncAttributeMaxDynamicSharedMemorySize, FSMEM);

    // conversions into tile-image layouts
    cvt_x<<<2048, 256>>>(x, xb);
    cvtT4_k<<<dim3(DMODEL / 32, DMODEL / 32, 4), dim3(32, 8)>>>(
        wq, wk, wv, wo, wqT, wkT, wvT, woT);

    // fused QKV GEMM with rope-fused epilogue
    dim3 gq3(DMODEL / 256, ROWS / 128, 3);   // (8, 32, 3)
    gemm_qkv<<<gq3, 256, GSMEM>>>(xb, wqT, wkT, wvT, fcos, fsin, qb, kb, vb);

    flash_f16<<<dim3(SEQ / 128, BATCH * NHEADS), 256, FSMEM>>>(qb, kb, vb, attb);

    gemm_wo<<<dim3(DMODEL / 256, ROWS / 128), 256, GSMEM>>>(attb, woT, out);
}

// round 12
// speedup vs baseline: 10.5590x; 1.1445x over previous
#include <cuda_runtime.h>
#include <cuda_fp16.h>
#include <cstdint>

// Problem constants
#define BATCH 2
#define SEQ   2048
#define DMODEL 2048
#define NHEADS 16
#define HDIM  128
#define ROWS  (BATCH * SEQ)          // 4096
#define QKV_ELEMS (ROWS * DMODEL)    // 8388608
#define WELEMS (DMODEL * DMODEL)     // 4194304

// ---------------- scratch (device globals; no allocation) ----------------
//  A-image : 8KB block per (m-panel128, k-chunk32): row*64 + ((u^(row&3))*16)
//  B-image : 8KB block per (n-panel128, k-chunk32): row*64 + ((u^(row&3))*16)
//  F-image : 32KB block per (head, seq-tile128): row*256 + ((g^(row&7))*16)
__device__ __align__(256) __half g_xb[QKV_ELEMS];                  // A-image
__device__ __align__(256) __half g_attb[QKV_ELEMS];                // A-image
__device__ __align__(256) __half g_qb[QKV_ELEMS], g_kb[QKV_ELEMS], g_vb[QKV_ELEMS]; // F-image
__device__ __align__(256) __half g_wqT[WELEMS], g_wkT[WELEMS];     // B-image
__device__ __align__(256) __half g_wvT[WELEMS], g_woT[WELEMS];     // B-image

// ---------------- PTX helpers ----------------
__device__ __forceinline__ uint32_t s2u(const void* p) {
    uint32_t a;
    asm("{ .reg .u64 t; cvta.to.shared.u64 t, %1; cvt.u32.u64 %0, t; }"
        : "=r"(a) : "l"(p));
    return a;
}
#define MBINIT(a, c) asm volatile("mbarrier.init.shared.b64 [%0], %1;" :: "r"(a), "r"(c) : "memory")
#define MBEXPECT(a, tx) asm volatile("mbarrier.arrive.expect_tx.shared.b64 _, [%0], %1;" :: "r"(a), "r"(tx) : "memory")
#define MBWAIT(a, ph) do { \
    uint32_t _m = (a), _p = (ph), _d; \
    asm volatile("{ .reg .pred p; mbarrier.try_wait.parity.acquire.cta.shared::cta.b64 p, [%1], %2; selp.b32 %0,1,0,p; }" \
                 : "=r"(_d) : "r"(_m), "r"(_p) : "memory"); \
    if (!_d) { \
        asm volatile("{ .reg .pred P1; WL%=: mbarrier.try_wait.parity.acquire.cta.shared::cta.b64 P1, [%0], %1, 0x989680; @P1 bra.uni WD%=; bra.uni WL%=; WD%=: }" \
                     :: "r"(_m), "r"(_p) : "memory"); \
    } } while (0)
#define BULKG2S(dst, src, bytes, mbar) \
    asm volatile("cp.async.bulk.shared::cluster.global.mbarrier::complete_tx::bytes [%0], [%1], %2, [%3];" \
                 :: "r"(dst), "l"(src), "r"(bytes), "r"(mbar) : "memory")

#define LDSM4(r0, r1, r2, r3, a) \
    asm volatile("ldmatrix.sync.aligned.m8n8.x4.shared.b16 {%0,%1,%2,%3}, [%4];" \
                 : "=r"(r0), "=r"(r1), "=r"(r2), "=r"(r3) : "r"(a))
#define LDSM2(r0, r1, a) \
    asm volatile("ldmatrix.sync.aligned.m8n8.x2.shared.b16 {%0,%1}, [%2];" \
                 : "=r"(r0), "=r"(r1) : "r"(a))
#define LDSM4T(r, a) \
    asm volatile("ldmatrix.sync.aligned.m8n8.x4.trans.shared.b16 {%0,%1,%2,%3}, [%4];" \
                 : "=r"((r)[0]), "=r"((r)[1]), "=r"((r)[2]), "=r"((r)[3]) : "r"(a))

#define MMAF16(c, a, b) \
    asm volatile("mma.sync.aligned.m16n8k16.row.col.f32.f16.f16.f32 " \
                 "{%0,%1,%2,%3}, {%4,%5,%6,%7}, {%8,%9}, {%0,%1,%2,%3};" \
                 : "+f"((c)[0]), "+f"((c)[1]), "+f"((c)[2]), "+f"((c)[3]) \
                 : "r"((a)[0]), "r"((a)[1]), "r"((a)[2]), "r"((a)[3]), \
                   "r"((b)[0]), "r"((b)[1]))

__device__ __forceinline__ uint32_t packh2(float a, float b) {
    __half2 h = __floats2half2_rn(a, b);
    return *(uint32_t*)&h;
}

// ---------------- conversions ----------------
// x fp32 [4096,2048] -> A-image blocks. One CTA per 8KB block.
__global__ __launch_bounds__(256) void cvt_x(
    const float* __restrict__ x, __half* __restrict__ xb)
{
    int blk = blockIdx.x;                 // p*64 + ch
    int p = blk >> 6, ch = blk & 63;
    const float* src = x + (size_t)p * 128 * 2048 + ch * 32;
    char* dst = (char*)(xb + (size_t)blk * 4096);
    int t = threadIdx.x;
    #pragma unroll
    for (int i = 0; i < 2; i++) {
        int u = t + i * 256;              // 0..511
        int row = u >> 2, c16 = u & 3;
        const float4* s4 = (const float4*)(src + (size_t)row * 2048 + c16 * 8);
        float4 a = s4[0], b = s4[1];
        uint4 o;
        o.x = packh2(a.x, a.y); o.y = packh2(a.z, a.w);
        o.z = packh2(b.x, b.y); o.w = packh2(b.z, b.w);
        *(uint4*)(dst + row * 64 + ((c16 ^ (row & 3)) * 16)) = o;
    }
}

// 4 weights W[K,N] fp32 -> B-image (128-row panels), one launch
__global__ __launch_bounds__(256) void cvtT4_k(
    const float* __restrict__ wq, const float* __restrict__ wk,
    const float* __restrict__ wv, const float* __restrict__ wo,
    __half* __restrict__ tq, __half* __restrict__ tk,
    __half* __restrict__ tv, __half* __restrict__ to_)
{
    const float* W;
    __half* T;
    switch (blockIdx.z) {
        case 0:  W = wq; T = tq;  break;
        case 1:  W = wk; T = tk;  break;
        case 2:  W = wv; T = tv;  break;
        default: W = wo; T = to_; break;
    }
    __shared__ float tile[32][33];
    int bx = blockIdx.x * 32, by = blockIdx.y * 32;
    int tx = threadIdx.x, ty = threadIdx.y;   // block (32,8)
    #pragma unroll
    for (int r = 0; r < 32; r += 8)
        tile[ty + r][tx] = W[(size_t)(by + ty + r) * DMODEL + bx + tx];
    __syncthreads();
    #pragma unroll
    for (int r = 0; r < 32; r += 8) {
        int rr = bx + ty + r;       // n index
        int kk = by + tx;           // k index
        size_t blk = (size_t)((rr >> 7) * 64 + (kk >> 5));
        uint32_t off = (uint32_t)((rr & 127) * 64 +
                       ((((kk & 31) >> 3) ^ (rr & 3)) * 16) + (kk & 7) * 2);
        *(__half*)((char*)T + blk * 8192 + off) = __float2half(tile[tx][ty + r]);
    }
}

// ---------------- fp16 HMMA GEMM core (bulk-copy pipeline) ----------------
// CTA tile 128x128, BK=32, 4-stage, 128 threads (4 warps 2m x 2n, warp 64x64).
#define NCHUNK 64
#define GS_A 0
#define GS_B 8192
#define GSTAGE 16384
#define GNST 4
#define GBAR (GNST * GSTAGE)       // 65536
#define GSMEM (GBAR + 64)

__device__ __forceinline__ void gemm_core(
    const char* __restrict__ pA,   // A-image panel base (8KB per chunk)
    const char* __restrict__ pB,   // B-image panel base (8KB per chunk)
    float (&acc)[4][8][4])
{
    extern __shared__ __align__(128) char smem[];
    const uint32_t sbase = s2u(smem);
    const uint32_t mb = sbase + GBAR;
    const int t = threadIdx.x;
    const int lane = t & 31, wid = t >> 5;
    const int wm = wid >> 1, wn = wid & 1;

    #pragma unroll
    for (int i = 0; i < 4; i++)
        #pragma unroll
        for (int j = 0; j < 8; j++)
            #pragma unroll
            for (int r = 0; r < 4; r++) acc[i][j][r] = 0.f;

    if (t == 0) {
        #pragma unroll
        for (int s = 0; s < GNST; s++) MBINIT(mb + s * 8, 1);
    }
    __syncthreads();
    if (t == 0) {
        #pragma unroll
        for (int s = 0; s < 3; s++) {
            MBEXPECT(mb + s * 8, 16384u);
            BULKG2S(sbase + s * GSTAGE + GS_A, pA + (size_t)s * 8192, 8192u, mb + s * 8);
            BULKG2S(sbase + s * GSTAGE + GS_B, pB + (size_t)s * 8192, 8192u, mb + s * 8);
        }
    }

    for (int ic = 0; ic < NCHUNK; ic++) {
        const int s = ic & 3;
        if (ic > 0) __syncthreads();    // all warps done with stage (ic-1)&3
        if (t == 0 && ic + 3 < NCHUNK) {
            int c = ic + 3, ss = c & 3;
            MBEXPECT(mb + ss * 8, 16384u);
            BULKG2S(sbase + ss * GSTAGE + GS_A, pA + (size_t)c * 8192, 8192u, mb + ss * 8);
            BULKG2S(sbase + ss * GSTAGE + GS_B, pB + (size_t)c * 8192, 8192u, mb + ss * 8);
        }
        MBWAIT(mb + s * 8, (ic >> 2) & 1);

        const uint32_t stb = sbase + (uint32_t)s * GSTAGE;
        #pragma unroll
        for (int ks = 0; ks < 2; ks++) {
            uint32_t af[4][4];
            #pragma unroll
            for (int ms = 0; ms < 4; ms++) {
                int r = wm * 64 + ms * 16 + (lane & 15);
                uint32_t c = (uint32_t)((2 * ks + (lane >> 4)) ^ (r & 3));
                LDSM4(af[ms][0], af[ms][1], af[ms][2], af[ms][3],
                      stb + GS_A + (uint32_t)(r * 64) + c * 16);
            }
            #pragma unroll
            for (int ns = 0; ns < 8; ns++) {
                int rb = wn * 64 + ns * 8 + (lane & 7);
                uint32_t cb = (uint32_t)((2 * ks + ((lane >> 3) & 1)) ^ (rb & 3));
                uint32_t bf[2];
                LDSM2(bf[0], bf[1], stb + GS_B + (uint32_t)(rb * 64) + cb * 16);
                #pragma unroll
                for (int ms = 0; ms < 4; ms++)
                    MMAF16(acc[ms][ns], af[ms], bf);
            }
        }
    }
    __syncthreads();
}

// QKV fused; z=0/1: rope fused -> qb/kb (F-image); z=2: vb (F-image).
#define RS 136   // smem row stride (floats) for rope exchange buffer

__global__ __launch_bounds__(128, 2) void gemm_qkv(
    const __half* __restrict__ xb,
    const __half* __restrict__ wqT, const __half* __restrict__ wkT,
    const __half* __restrict__ wvT,
    const float* __restrict__ fcos, const float* __restrict__ fsin,
    __half* __restrict__ qb, __half* __restrict__ kb, __half* __restrict__ vb)
{
    const int z = blockIdx.z;
    const __half* B = (z == 0) ? wqT : (z == 1) ? wkT : wvT;
    const int n0 = blockIdx.x * 128;
    const int m0 = blockIdx.y * 128;
    float acc[4][8][4];
    gemm_core((const char*)xb + (size_t)(m0 >> 7) * 64 * 8192,
              (const char*)B  + (size_t)(n0 >> 7) * 64 * 8192, acc);

    const int lane = threadIdx.x & 31, wid = threadIdx.x >> 5;
    const int wm = wid >> 1, wn = wid & 1;
    const int h = n0 >> 7;                 // single head per CTA

    if (z == 2) {
        #pragma unroll
        for (int ms = 0; ms < 4; ms++) {
            #pragma unroll
            for (int rh = 0; rh < 2; rh++) {
                int m = m0 + wm * 64 + ms * 16 + (lane >> 2) + rh * 8;
                int b = m >> 11, si = m & 2047;
                size_t blk = (size_t)((b * 16 + h) * 16 + (si >> 7));
                #pragma unroll
                for (int ns = 0; ns < 8; ns++) {
                    int d = wn * 64 + ns * 8 + 2 * (lane & 3);
                    float va = rh ? acc[ms][ns][2] : acc[ms][ns][0];
                    float vb_ = rh ? acc[ms][ns][3] : acc[ms][ns][1];
                    uint32_t off = (uint32_t)((si & 127) * 256 +
                                   (((d >> 3) ^ (si & 7)) * 16) + (d & 7) * 2);
                    *(uint32_t*)((char*)vb + blk * 32768 + off) = packh2(va, vb_);
                }
            }
        }
        return;
    }

    // ---- rope-fused epilogue for q/k -> F-image ----
    extern __shared__ __align__(128) char smem[];
    float* sm = (float*)smem;          // [32][RS] (stages no longer in use)
    const float qs = (z == 0) ? (0.08838834764831845f * 1.4426950408889634f) : 1.0f;
    __half* dst = (z == 0) ? qb : kb;

    #pragma unroll
    for (int ms = 0; ms < 4; ms++) {
        __syncthreads();
        #pragma unroll
        for (int rh = 0; rh < 2; rh++) {
            int lr = wm * 16 + (lane >> 2) + rh * 8;
            #pragma unroll
            for (int ns = 0; ns < 8; ns++) {
                int lc = wn * 64 + ns * 8 + 2 * (lane & 3);
                float va = rh ? acc[ms][ns][2] : acc[ms][ns][0];
                float vb_ = rh ? acc[ms][ns][3] : acc[ms][ns][1];
                *(float2*)&sm[lr * RS + lc] = make_float2(va, vb_);
            }
        }
        __syncthreads();
        // 32 rows; 4 warps x 8; lane covers rope pairs (d, d+64), d = 2*lane
        #pragma unroll
        for (int i = 0; i < 8; i++) {
            int lr = wid * 8 + i;       // 0..31
            int m = m0 + (lr >> 4) * 64 + ms * 16 + (lr & 15);
            int b = m >> 11, si = m & 2047;
            int d = 2 * lane;           // 0..62
            float2 v0 = *(float2*)&sm[lr * RS + d];
            float2 v1 = *(float2*)&sm[lr * RS + d + 64];
            float2 cc = *(const float2*)&fcos[si * 64 + d];
            float2 ss = *(const float2*)&fsin[si * 64 + d];
            float o0 = (v0.x * cc.x - v1.x * ss.x) * qs;
            float o1 = (v0.y * cc.y - v1.y * ss.y) * qs;
            float o2 = (v1.x * cc.x + v0.x * ss.x) * qs;
            float o3 = (v1.y * cc.y + v0.y * ss.y) * qs;
            size_t blk = (size_t)((b * 16 + h) * 16 + (si >> 7));
            char* bp = (char*)dst + blk * 32768;
            uint32_t r = (uint32_t)(si & 127);
            uint32_t off0 = r * 256 + (((d >> 3) ^ (r & 7)) * 16) + (d & 7) * 2;
            uint32_t off1 = r * 256 + ((((d + 64) >> 3) ^ (r & 7)) * 16) + (d & 7) * 2;
            *(uint32_t*)(bp + off0) = packh2(o0, o1);
            *(uint32_t*)(bp + off1) = packh2(o2, o3);
        }
    }
}

// WO: fp32 row-major out
__global__ __launch_bounds__(128, 2) void gemm_wo(
    const __half* __restrict__ attb, const __half* __restrict__ woT,
    float* __restrict__ out)
{
    const int n0 = blockIdx.x * 128;
    const int m0 = blockIdx.y * 128;
    float acc[4][8][4];
    gemm_core((const char*)attb + (size_t)(m0 >> 7) * 64 * 8192,
              (const char*)woT  + (size_t)(n0 >> 7) * 64 * 8192, acc);

    const int lane = threadIdx.x & 31, wid = threadIdx.x >> 5;
    const int wm = wid >> 1, wn = wid & 1;
    #pragma unroll
    for (int ms = 0; ms < 4; ms++) {
        #pragma unroll
        for (int rh = 0; rh < 2; rh++) {
            int m = m0 + wm * 64 + ms * 16 + (lane >> 2) + rh * 8;
            #pragma unroll
            for (int ns = 0; ns < 8; ns++) {
                int n = n0 + wn * 64 + ns * 8 + 2 * (lane & 3);
                float va = rh ? acc[ms][ns][2] : acc[ms][ns][0];
                float vb = rh ? acc[ms][ns][3] : acc[ms][ns][1];
                *(float2*)(out + (size_t)m * DMODEL + n) = make_float2(va, vb);
            }
        }
    }
}

// ---------------- fp16 HMMA flash attention, causal (bulk-copy) ----------------
// CTA: 64 q rows, 4 warps x 16 rows, 64-key KV tiles double buffered. 80KB smem.
#define FQ 0
#define FST 16384
#define FSTG 32768
#define FK 0
#define FV 16384
#define FBAR (16384 + 2 * 32768)   // 81920
#define FSMEM (FBAR + 64)

__global__ __launch_bounds__(128, 2) void flash_f16(
    const __half* __restrict__ Qb, const __half* __restrict__ Kb,
    const __half* __restrict__ Vb, __half* __restrict__ Ob)
{
    extern __shared__ __align__(128) char smem[];
    const uint32_t sb = s2u(smem);
    const uint32_t mbQ = sb + FBAR, mbKV = sb + FBAR + 8;  // +8*s
    const int t = threadIdx.x, lane = t & 31, wid = t >> 5;
    const int bh = blockIdx.y;
    const int qt = gridDim.x - 1 - blockIdx.x;   // LPT: longest first
    const int m0 = qt * 64;
    const int ntiles = qt + 1;                   // 64-key tiles

    const char* gq = (const char*)Qb + (size_t)(bh * 16 + (qt >> 1)) * 32768
                     + (size_t)(qt & 1) * 16384;
    const char* gk = (const char*)Kb + (size_t)(bh * 16) * 32768;
    const char* gv = (const char*)Vb + (size_t)(bh * 16) * 32768;

    if (t == 0) { MBINIT(mbQ, 1); MBINIT(mbKV, 1); MBINIT(mbKV + 8, 1); }
    __syncthreads();
    if (t == 0) {
        MBEXPECT(mbQ, 16384u);
        BULKG2S(sb + FQ, gq, 16384u, mbQ);
        MBEXPECT(mbKV, 32768u);
        BULKG2S(sb + FST + FK, gk, 16384u, mbKV);
        BULKG2S(sb + FST + FV, gv, 16384u, mbKV);
    }
    MBWAIT(mbQ, 0);

    float oacc[16][4];
    #pragma unroll
    for (int i = 0; i < 16; i++)
        #pragma unroll
        for (int j = 0; j < 4; j++) oacc[i][j] = 0.f;
    float mrun0 = -1e30f, mrun1 = -1e30f, ls0 = 0.f, ls1 = 0.f;

    const int r0 = m0 + wid * 16 + (lane >> 2), r1 = r0 + 8;
    const int rowA = wid * 16 + (lane & 15);
    const int rbB = (lane & 7) | ((lane >> 1) & 8);

    for (int jt = 0; jt < ntiles; jt++) {
        const int s = jt & 1;
        if (jt > 0) __syncthreads();   // all warps done with stage s^1
        if (t == 0 && jt + 1 < ntiles) {
            uint32_t mbn = mbKV + (uint32_t)(s ^ 1) * 8;
            MBEXPECT(mbn, 32768u);
            BULKG2S(sb + FST + (uint32_t)(s ^ 1) * FSTG + FK,
                    gk + (size_t)(jt + 1) * 16384, 16384u, mbn);
            BULKG2S(sb + FST + (uint32_t)(s ^ 1) * FSTG + FV,
                    gv + (size_t)(jt + 1) * 16384, 16384u, mbn);
        }
        MBWAIT(mbKV + (uint32_t)s * 8, (jt >> 1) & 1);

        const uint32_t stb = sb + FST + (uint32_t)s * FSTG;
        float sacc[8][4];
        #pragma unroll
        for (int i = 0; i < 8; i++)
            #pragma unroll
            for (int j = 0; j < 4; j++) sacc[i][j] = 0.f;

        // ---- S = Q K^T (64 keys)
        #pragma unroll
        for (int k8 = 0; k8 < 8; k8++) {
            int gA = 2 * k8 + (lane >> 4);
            uint32_t aq[4];
            LDSM4(aq[0], aq[1], aq[2], aq[3],
                  sb + FQ + (uint32_t)(rowA * 256 + ((gA ^ (rowA & 7)) * 16)));
            int gB = 2 * k8 + ((lane >> 3) & 1);
            #pragma unroll
            for (int np = 0; np < 4; np++) {
                int rowB = np * 16 + rbB;
                uint32_t bk[4];
                LDSM4(bk[0], bk[1], bk[2], bk[3],
                      stb + FK + (uint32_t)(rowB * 256 + ((gB ^ (rowB & 7)) * 16)));
                MMAF16(sacc[2 * np],     aq, &bk[0]);
                MMAF16(sacc[2 * np + 1], aq, &bk[2]);
            }
        }

        // ---- causal mask (diagonal tile only; k0 == m0 there)
        if (jt == ntiles - 1) {
            const int k0 = jt * 64;
            #pragma unroll
            for (int nt = 0; nt < 8; nt++) {
                int c = k0 + nt * 8 + 2 * (lane & 3);
                if (c     > r0) sacc[nt][0] = -1e30f;
                if (c + 1 > r0) sacc[nt][1] = -1e30f;
                if (c     > r1) sacc[nt][2] = -1e30f;
                if (c + 1 > r1) sacc[nt][3] = -1e30f;
            }
        }

        // ---- online softmax (log2 domain; scale*log2e folded into Q)
        float ml0 = -1e30f, ml1 = -1e30f;
        #pragma unroll
        for (int nt = 0; nt < 8; nt++) {
            ml0 = fmaxf(ml0, fmaxf(sacc[nt][0], sacc[nt][1]));
            ml1 = fmaxf(ml1, fmaxf(sacc[nt][2], sacc[nt][3]));
        }
        ml0 = fmaxf(ml0, __shfl_xor_sync(0xffffffffu, ml0, 1));
        ml0 = fmaxf(ml0, __shfl_xor_sync(0xffffffffu, ml0, 2));
        ml1 = fmaxf(ml1, __shfl_xor_sync(0xffffffffu, ml1, 1));
        ml1 = fmaxf(ml1, __shfl_xor_sync(0xffffffffu, ml1, 2));
        float mn0 = fmaxf(mrun0, ml0), mn1 = fmaxf(mrun1, ml1);
        float c0 = exp2f(mrun0 - mn0), c1 = exp2f(mrun1 - mn1);
        mrun0 = mn0; mrun1 = mn1;
        ls0 *= c0; ls1 *= c1;
        #pragma unroll
        for (int nt = 0; nt < 16; nt++) {
            oacc[nt][0] *= c0; oacc[nt][1] *= c0;
            oacc[nt][2] *= c1; oacc[nt][3] *= c1;
        }
        float ps0 = 0.f, ps1 = 0.f;
        #pragma unroll
        for (int nt = 0; nt < 8; nt++) {
            sacc[nt][0] = exp2f(sacc[nt][0] - mn0);
            sacc[nt][1] = exp2f(sacc[nt][1] - mn0);
            sacc[nt][2] = exp2f(sacc[nt][2] - mn1);
            sacc[nt][3] = exp2f(sacc[nt][3] - mn1);
            ps0 += sacc[nt][0] + sacc[nt][1];
            ps1 += sacc[nt][2] + sacc[nt][3];
        }
        ls0 += ps0; ls1 += ps1;

        // ---- O += P V ; P C-frags repack as fp16 A-frags
        #pragma unroll
        for (int kp = 0; kp < 4; kp++) {
            uint32_t pa[4];
            pa[0] = packh2(sacc[2 * kp][0],     sacc[2 * kp][1]);
            pa[1] = packh2(sacc[2 * kp][2],     sacc[2 * kp][3]);
            pa[2] = packh2(sacc[2 * kp + 1][0], sacc[2 * kp + 1][1]);
            pa[3] = packh2(sacc[2 * kp + 1][2], sacc[2 * kp + 1][3]);
            int rv = kp * 16 + (lane & 15);
            #pragma unroll
            for (int dp = 0; dp < 8; dp++) {
                int gV = 2 * dp + (lane >> 4);
                uint32_t vv[4];
                LDSM4T(vv, stb + FV + (uint32_t)(rv * 256 + ((gV ^ (rv & 7)) * 16)));
                MMAF16(oacc[2 * dp],     pa, &vv[0]);
                MMAF16(oacc[2 * dp + 1], pa, &vv[2]);
            }
        }
    }

    // ---- epilogue: normalize, write att as A-image blocks
    float lt0 = ls0 + __shfl_xor_sync(0xffffffffu, ls0, 1);
    lt0 += __shfl_xor_sync(0xffffffffu, lt0, 2);
    float lt1 = ls1 + __shfl_xor_sync(0xffffffffu, ls1, 1);
    lt1 += __shfl_xor_sync(0xffffffffu, lt1, 2);
    float inv0 = 1.f / lt0, inv1 = 1.f / lt1;

    const int b = bh >> 4, h = bh & 15;
    const size_t pbase = (size_t)((b * 16 + (r0 >> 7)) * 64) * 8192;
    #pragma unroll
    for (int nt = 0; nt < 16; nt++) {
        int d = nt * 8 + 2 * (lane & 3);
        int col = h * 128 + d;
        size_t blk = pbase + (size_t)(col >> 5) * 8192;
        uint32_t u = (uint32_t)((d & 31) >> 3);
        uint32_t rA = (uint32_t)(r0 & 127), rB = (uint32_t)(r1 & 127);
        uint32_t offA = rA * 64 + ((u ^ (rA & 3)) * 16) + (d & 7) * 2;
        uint32_t offB = rB * 64 + ((u ^ (rB & 3)) * 16) + (d & 7) * 2;
        *(uint32_t*)((char*)Ob + blk + offA) = packh2(oacc[nt][0] * inv0, oacc[nt][1] * inv0);
        *(uint32_t*)((char*)Ob + blk + offB) = packh2(oacc[nt][2] * inv1, oacc[nt][3] * inv1);
    }
}

// ---------------- launch ----------------
extern "C" void kernel_launch(void* const* d_in, const int* in_sizes, int n_in,
                              void* d_out, int out_size)
{
    (void)in_sizes; (void)n_in; (void)out_size;
    const float* x    = (const float*)d_in[0];
    const float* fcos = (const float*)d_in[1];
    const float* fsin = (const float*)d_in[2];
    const float* wq   = (const float*)d_in[3];
    const float* wk   = (const float*)d_in[4];
    const float* wv   = (const float*)d_in[5];
    const float* wo   = (const float*)d_in[6];
    float* out = (float*)d_out;

    __half *xb, *attb, *qb, *kb, *vb, *wqT, *wkT, *wvT, *woT;
    cudaGetSymbolAddress((void**)&xb,   g_xb);
    cudaGetSymbolAddress((void**)&attb, g_attb);
    cudaGetSymbolAddress((void**)&qb,   g_qb);
    cudaGetSymbolAddress((void**)&kb,   g_kb);
    cudaGetSymbolAddress((void**)&vb,   g_vb);
    cudaGetSymbolAddress((void**)&wqT,  g_wqT);
    cudaGetSymbolAddress((void**)&wkT,  g_wkT);
    cudaGetSymbolAddress((void**)&wvT,  g_wvT);
    cudaGetSymbolAddress((void**)&woT,  g_woT);

    cudaFuncSetAttribute(gemm_qkv, cudaFuncAttributeMaxDynamicSharedMemorySize, GSMEM);
    cudaFuncSetAttribute(gemm_wo,  cudaFuncAttributeMaxDynamicSharedMemorySize, GSMEM);
    cudaFuncSetAttribute(flash_f16, cudaFuncAttributeMaxDynamicSharedMemorySize, FSMEM);

    // conversions into tile-image layouts
    cvt_x<<<2048, 256>>>(x, xb);
    cvtT4_k<<<dim3(DMODEL / 32, DMODEL / 32, 4), dim3(32, 8)>>>(
        wq, wk, wv, wo, wqT, wkT, wvT, woT);

    // fused QKV GEMM with rope-fused epilogue (128x128 tiles, 2 CTAs/SM)
    dim3 gq3(DMODEL / 128, ROWS / 128, 3);   // (16, 32, 3)
    gemm_qkv<<<gq3, 128, GSMEM>>>(xb, wqT, wkT, wvT, fcos, fsin, qb, kb, vb);

    flash_f16<<<dim3(SEQ / 64, BATCH * NHEADS), 128, FSMEM>>>(qb, kb, vb, attb);

    gemm_wo<<<dim3(DMODEL / 128, ROWS / 128), 128, GSMEM>>>(attb, woT, out);
}

// round 13
// speedup vs baseline: 11.8589x; 1.1231x over previous
#include <cuda_runtime.h>
#include <cuda_fp16.h>
#include <cstdint>

// Problem constants
#define BATCH 2
#define SEQ   2048
#define DMODEL 2048
#define NHEADS 16
#define HDIM  128
#define ROWS  (BATCH * SEQ)          // 4096
#define QKV_ELEMS (ROWS * DMODEL)    // 8388608
#define WELEMS (DMODEL * DMODEL)     // 4194304

// ---------------- scratch (device globals; no allocation) ----------------
//  A-image : 8KB block per (m-panel128, k-chunk32): row*64 + ((u^(row&3))*16)
//  B-image : 8KB block per (n-panel128, k-chunk32): row*64 + ((u^(row&3))*16)
//  F-image : 32KB block per (head, seq-tile128): row*256 + ((g^(row&7))*16)
__device__ __align__(256) __half g_xb[QKV_ELEMS];                  // A-image
__device__ __align__(256) __half g_attb[QKV_ELEMS];                // A-image
__device__ __align__(256) __half g_qb[QKV_ELEMS], g_kb[QKV_ELEMS], g_vb[QKV_ELEMS]; // F-image
__device__ __align__(256) __half g_wqT[WELEMS], g_wkT[WELEMS];     // B-image
__device__ __align__(256) __half g_wvT[WELEMS], g_woT[WELEMS];     // B-image

// ---------------- PTX helpers ----------------
__device__ __forceinline__ uint32_t s2u(const void* p) {
    uint32_t a;
    asm("{ .reg .u64 t; cvta.to.shared.u64 t, %1; cvt.u32.u64 %0, t; }"
        : "=r"(a) : "l"(p));
    return a;
}
#define MBINIT(a, c) asm volatile("mbarrier.init.shared.b64 [%0], %1;" :: "r"(a), "r"(c) : "memory")
#define MBEXPECT(a, tx) asm volatile("mbarrier.arrive.expect_tx.shared.b64 _, [%0], %1;" :: "r"(a), "r"(tx) : "memory")
#define MBWAIT(a, ph) do { \
    uint32_t _m = (a), _p = (ph), _d; \
    asm volatile("{ .reg .pred p; mbarrier.try_wait.parity.acquire.cta.shared::cta.b64 p, [%1], %2; selp.b32 %0,1,0,p; }" \
                 : "=r"(_d) : "r"(_m), "r"(_p) : "memory"); \
    if (!_d) { \
        asm volatile("{ .reg .pred P1; WL%=: mbarrier.try_wait.parity.acquire.cta.shared::cta.b64 P1, [%0], %1, 0x989680; @P1 bra.uni WD%=; bra.uni WL%=; WD%=: }" \
                     :: "r"(_m), "r"(_p) : "memory"); \
    } } while (0)
#define BULKG2S(dst, src, bytes, mbar) \
    asm volatile("cp.async.bulk.shared::cluster.global.mbarrier::complete_tx::bytes [%0], [%1], %2, [%3];" \
                 :: "r"(dst), "l"(src), "r"(bytes), "r"(mbar) : "memory")

#define LDSM4(r0, r1, r2, r3, a) \
    asm volatile("ldmatrix.sync.aligned.m8n8.x4.shared.b16 {%0,%1,%2,%3}, [%4];" \
                 : "=r"(r0), "=r"(r1), "=r"(r2), "=r"(r3) : "r"(a))
#define LDSM2(r0, r1, a) \
    asm volatile("ldmatrix.sync.aligned.m8n8.x2.shared.b16 {%0,%1}, [%2];" \
                 : "=r"(r0), "=r"(r1) : "r"(a))
#define LDSM4T(r, a) \
    asm volatile("ldmatrix.sync.aligned.m8n8.x4.trans.shared.b16 {%0,%1,%2,%3}, [%4];" \
                 : "=r"((r)[0]), "=r"((r)[1]), "=r"((r)[2]), "=r"((r)[3]) : "r"(a))

#define MMAF16(c, a, b) \
    asm volatile("mma.sync.aligned.m16n8k16.row.col.f32.f16.f16.f32 " \
                 "{%0,%1,%2,%3}, {%4,%5,%6,%7}, {%8,%9}, {%0,%1,%2,%3};" \
                 : "+f"((c)[0]), "+f"((c)[1]), "+f"((c)[2]), "+f"((c)[3]) \
                 : "r"((a)[0]), "r"((a)[1]), "r"((a)[2]), "r"((a)[3]), \
                   "r"((b)[0]), "r"((b)[1]))

__device__ __forceinline__ uint32_t packh2(float a, float b) {
    __half2 h = __floats2half2_rn(a, b);
    return *(uint32_t*)&h;
}

// ---------------- conversions ----------------
// x fp32 [4096,2048] -> A-image blocks. One CTA per 8KB block.
__global__ __launch_bounds__(256) void cvt_x(
    const float* __restrict__ x, __half* __restrict__ xb)
{
    int blk = blockIdx.x;                 // p*64 + ch
    int p = blk >> 6, ch = blk & 63;
    const float* src = x + (size_t)p * 128 * 2048 + ch * 32;
    char* dst = (char*)(xb + (size_t)blk * 4096);
    int t = threadIdx.x;
    #pragma unroll
    for (int i = 0; i < 2; i++) {
        int u = t + i * 256;              // 0..511
        int row = u >> 2, c16 = u & 3;
        const float4* s4 = (const float4*)(src + (size_t)row * 2048 + c16 * 8);
        float4 a = s4[0], b = s4[1];
        uint4 o;
        o.x = packh2(a.x, a.y); o.y = packh2(a.z, a.w);
        o.z = packh2(b.x, b.y); o.w = packh2(b.z, b.w);
        *(uint4*)(dst + row * 64 + ((c16 ^ (row & 3)) * 16)) = o;
    }
}

// 4 weights W[K,N] fp32 -> B-image (128-row panels), one launch
__global__ __launch_bounds__(256) void cvtT4_k(
    const float* __restrict__ wq, const float* __restrict__ wk,
    const float* __restrict__ wv, const float* __restrict__ wo,
    __half* __restrict__ tq, __half* __restrict__ tk,
    __half* __restrict__ tv, __half* __restrict__ to_)
{
    const float* W;
    __half* T;
    switch (blockIdx.z) {
        case 0:  W = wq; T = tq;  break;
        case 1:  W = wk; T = tk;  break;
        case 2:  W = wv; T = tv;  break;
        default: W = wo; T = to_; break;
    }
    __shared__ float tile[32][33];
    int bx = blockIdx.x * 32, by = blockIdx.y * 32;
    int tx = threadIdx.x, ty = threadIdx.y;   // block (32,8)
    #pragma unroll
    for (int r = 0; r < 32; r += 8)
        tile[ty + r][tx] = W[(size_t)(by + ty + r) * DMODEL + bx + tx];
    __syncthreads();
    #pragma unroll
    for (int r = 0; r < 32; r += 8) {
        int rr = bx + ty + r;       // n index
        int kk = by + tx;           // k index
        size_t blk = (size_t)((rr >> 7) * 64 + (kk >> 5));
        uint32_t off = (uint32_t)((rr & 127) * 64 +
                       ((((kk & 31) >> 3) ^ (rr & 3)) * 16) + (kk & 7) * 2);
        *(__half*)((char*)T + blk * 8192 + off) = __float2half(tile[tx][ty + r]);
    }
}

// ---------------- fp16 HMMA GEMM core (bulk-copy pipeline, BK=64) ----------------
// CTA tile 128x128, 32 pipeline steps x 64-K, 3 stages x 32KB, 128 threads.
#define NITER 32
#define GS_A 0
#define GS_B 16384
#define GSTAGE 32768
#define GNST 3
#define GBAR (GNST * GSTAGE)       // 98304
#define GSMEM (GBAR + 64)

__device__ __forceinline__ void gemm_core(
    const char* __restrict__ pA,   // A-image panel base (16KB per step)
    const char* __restrict__ pB,   // B-image panel base (16KB per step)
    float (&acc)[4][8][4])
{
    extern __shared__ __align__(128) char smem[];
    const uint32_t sbase = s2u(smem);
    const uint32_t mb = sbase + GBAR;
    const int t = threadIdx.x;
    const int lane = t & 31, wid = t >> 5;
    const int wm = wid >> 1, wn = wid & 1;

    #pragma unroll
    for (int i = 0; i < 4; i++)
        #pragma unroll
        for (int j = 0; j < 8; j++)
            #pragma unroll
            for (int r = 0; r < 4; r++) acc[i][j][r] = 0.f;

    if (t == 0) {
        #pragma unroll
        for (int s = 0; s < GNST; s++) MBINIT(mb + s * 8, 1);
    }
    __syncthreads();
    if (t == 0) {
        #pragma unroll
        for (int s = 0; s < 2; s++) {
            MBEXPECT(mb + s * 8, 32768u);
            BULKG2S(sbase + s * GSTAGE + GS_A, pA + (size_t)s * 16384, 16384u, mb + s * 8);
            BULKG2S(sbase + s * GSTAGE + GS_B, pB + (size_t)s * 16384, 16384u, mb + s * 8);
        }
    }

    for (int ic = 0; ic < NITER; ic++) {
        const int s = ic % 3;
        if (ic > 0) __syncthreads();    // all warps done with stage (ic-1)%3
        if (t == 0 && ic + 2 < NITER) {
            int c = ic + 2, ss = c % 3;
            MBEXPECT(mb + ss * 8, 32768u);
            BULKG2S(sbase + ss * GSTAGE + GS_A, pA + (size_t)c * 16384, 16384u, mb + ss * 8);
            BULKG2S(sbase + ss * GSTAGE + GS_B, pB + (size_t)c * 16384, 16384u, mb + ss * 8);
        }
        MBWAIT(mb + s * 8, (ic / 3) & 1);

        const uint32_t stb = sbase + (uint32_t)s * GSTAGE;
        #pragma unroll
        for (int ksub = 0; ksub < 4; ksub++) {
            const uint32_t boff = (uint32_t)(ksub >> 1) * 8192;
            const int kp = ksub & 1;
            uint32_t af[4][4];
            #pragma unroll
            for (int ms = 0; ms < 4; ms++) {
                int r = wm * 64 + ms * 16 + (lane & 15);
                uint32_t c = (uint32_t)((2 * kp + (lane >> 4)) ^ (r & 3));
                LDSM4(af[ms][0], af[ms][1], af[ms][2], af[ms][3],
                      stb + GS_A + boff + (uint32_t)(r * 64) + c * 16);
            }
            #pragma unroll
            for (int ns = 0; ns < 8; ns++) {
                int rb = wn * 64 + ns * 8 + (lane & 7);
                uint32_t cb = (uint32_t)((2 * kp + ((lane >> 3) & 1)) ^ (rb & 3));
                uint32_t bf[2];
                LDSM2(bf[0], bf[1], stb + GS_B + boff + (uint32_t)(rb * 64) + cb * 16);
                #pragma unroll
                for (int ms = 0; ms < 4; ms++)
                    MMAF16(acc[ms][ns], af[ms], bf);
            }
        }
    }
    __syncthreads();
}

// QKV fused; z=0/1: rope fused -> qb/kb (F-image); z=2: vb (F-image).
#define RS 136   // smem row stride (floats) for rope exchange buffer

__global__ __launch_bounds__(128, 2) void gemm_qkv(
    const __half* __restrict__ xb,
    const __half* __restrict__ wqT, const __half* __restrict__ wkT,
    const __half* __restrict__ wvT,
    const float* __restrict__ fcos, const float* __restrict__ fsin,
    __half* __restrict__ qb, __half* __restrict__ kb, __half* __restrict__ vb)
{
    const int z = blockIdx.z;
    const __half* B = (z == 0) ? wqT : (z == 1) ? wkT : wvT;
    const int n0 = blockIdx.x * 128;
    const int m0 = blockIdx.y * 128;
    float acc[4][8][4];
    gemm_core((const char*)xb + (size_t)(m0 >> 7) * 64 * 8192,
              (const char*)B  + (size_t)(n0 >> 7) * 64 * 8192, acc);

    const int lane = threadIdx.x & 31, wid = threadIdx.x >> 5;
    const int wm = wid >> 1, wn = wid & 1;
    const int h = n0 >> 7;                 // single head per CTA

    if (z == 2) {
        #pragma unroll
        for (int ms = 0; ms < 4; ms++) {
            #pragma unroll
            for (int rh = 0; rh < 2; rh++) {
                int m = m0 + wm * 64 + ms * 16 + (lane >> 2) + rh * 8;
                int b = m >> 11, si = m & 2047;
                size_t blk = (size_t)((b * 16 + h) * 16 + (si >> 7));
                #pragma unroll
                for (int ns = 0; ns < 8; ns++) {
                    int d = wn * 64 + ns * 8 + 2 * (lane & 3);
                    float va = rh ? acc[ms][ns][2] : acc[ms][ns][0];
                    float vb_ = rh ? acc[ms][ns][3] : acc[ms][ns][1];
                    uint32_t off = (uint32_t)((si & 127) * 256 +
                                   (((d >> 3) ^ (si & 7)) * 16) + (d & 7) * 2);
                    *(uint32_t*)((char*)vb + blk * 32768 + off) = packh2(va, vb_);
                }
            }
        }
        return;
    }

    // ---- rope-fused epilogue for q/k -> F-image ----
    extern __shared__ __align__(128) char smem[];
    float* sm = (float*)smem;          // [32][RS] (stages no longer in use)
    const float qs = (z == 0) ? (0.08838834764831845f * 1.4426950408889634f) : 1.0f;
    __half* dst = (z == 0) ? qb : kb;

    #pragma unroll
    for (int ms = 0; ms < 4; ms++) {
        __syncthreads();
        #pragma unroll
        for (int rh = 0; rh < 2; rh++) {
            int lr = wm * 16 + (lane >> 2) + rh * 8;
            #pragma unroll
            for (int ns = 0; ns < 8; ns++) {
                int lc = wn * 64 + ns * 8 + 2 * (lane & 3);
                float va = rh ? acc[ms][ns][2] : acc[ms][ns][0];
                float vb_ = rh ? acc[ms][ns][3] : acc[ms][ns][1];
                *(float2*)&sm[lr * RS + lc] = make_float2(va, vb_);
            }
        }
        __syncthreads();
        // 32 rows; 4 warps x 8; lane covers rope pairs (d, d+64), d = 2*lane
        #pragma unroll
        for (int i = 0; i < 8; i++) {
            int lr = wid * 8 + i;       // 0..31
            int m = m0 + (lr >> 4) * 64 + ms * 16 + (lr & 15);
            int b = m >> 11, si = m & 2047;
            int d = 2 * lane;           // 0..62
            float2 v0 = *(float2*)&sm[lr * RS + d];
            float2 v1 = *(float2*)&sm[lr * RS + d + 64];
            float2 cc = *(const float2*)&fcos[si * 64 + d];
            float2 ss = *(const float2*)&fsin[si * 64 + d];
            float o0 = (v0.x * cc.x - v1.x * ss.x) * qs;
            float o1 = (v0.y * cc.y - v1.y * ss.y) * qs;
            float o2 = (v1.x * cc.x + v0.x * ss.x) * qs;
            float o3 = (v1.y * cc.y + v0.y * ss.y) * qs;
            size_t blk = (size_t)((b * 16 + h) * 16 + (si >> 7));
            char* bp = (char*)dst + blk * 32768;
            uint32_t r = (uint32_t)(si & 127);
            uint32_t off0 = r * 256 + (((d >> 3) ^ (r & 7)) * 16) + (d & 7) * 2;
            uint32_t off1 = r * 256 + ((((d + 64) >> 3) ^ (r & 7)) * 16) + (d & 7) * 2;
            *(uint32_t*)(bp + off0) = packh2(o0, o1);
            *(uint32_t*)(bp + off1) = packh2(o2, o3);
        }
    }
}

// WO: fp32 row-major out
__global__ __launch_bounds__(128, 2) void gemm_wo(
    const __half* __restrict__ attb, const __half* __restrict__ woT,
    float* __restrict__ out)
{
    const int n0 = blockIdx.x * 128;
    const int m0 = blockIdx.y * 128;
    float acc[4][8][4];
    gemm_core((const char*)attb + (size_t)(m0 >> 7) * 64 * 8192,
              (const char*)woT  + (size_t)(n0 >> 7) * 64 * 8192, acc);

    const int lane = threadIdx.x & 31, wid = threadIdx.x >> 5;
    const int wm = wid >> 1, wn = wid & 1;
    #pragma unroll
    for (int ms = 0; ms < 4; ms++) {
        #pragma unroll
        for (int rh = 0; rh < 2; rh++) {
            int m = m0 + wm * 64 + ms * 16 + (lane >> 2) + rh * 8;
            #pragma unroll
            for (int ns = 0; ns < 8; ns++) {
                int n = n0 + wn * 64 + ns * 8 + 2 * (lane & 3);
                float va = rh ? acc[ms][ns][2] : acc[ms][ns][0];
                float vb = rh ? acc[ms][ns][3] : acc[ms][ns][1];
                *(float2*)(out + (size_t)m * DMODEL + n) = make_float2(va, vb);
            }
        }
    }
}

// ---------------- fp16 HMMA flash attention, causal (bulk-copy) ----------------
// CTA: 64 q rows, 4 warps x 16 rows, 64-key KV tiles double buffered. 80KB smem.
// Q fragments hoisted to registers (loaded once).
#define FQ 0
#define FST 16384
#define FSTG 32768
#define FK 0
#define FV 16384
#define FBAR (16384 + 2 * 32768)   // 81920
#define FSMEM (FBAR + 64)

__global__ __launch_bounds__(128, 2) void flash_f16(
    const __half* __restrict__ Qb, const __half* __restrict__ Kb,
    const __half* __restrict__ Vb, __half* __restrict__ Ob)
{
    extern __shared__ __align__(128) char smem[];
    const uint32_t sb = s2u(smem);
    const uint32_t mbQ = sb + FBAR, mbKV = sb + FBAR + 8;  // +8*s
    const int t = threadIdx.x, lane = t & 31, wid = t >> 5;
    const int bh = blockIdx.y;
    const int qt = gridDim.x - 1 - blockIdx.x;   // LPT: longest first
    const int m0 = qt * 64;
    const int ntiles = qt + 1;                   // 64-key tiles

    const char* gq = (const char*)Qb + (size_t)(bh * 16 + (qt >> 1)) * 32768
                     + (size_t)(qt & 1) * 16384;
    const char* gk = (const char*)Kb + (size_t)(bh * 16) * 32768;
    const char* gv = (const char*)Vb + (size_t)(bh * 16) * 32768;

    if (t == 0) { MBINIT(mbQ, 1); MBINIT(mbKV, 1); MBINIT(mbKV + 8, 1); }
    __syncthreads();
    if (t == 0) {
        MBEXPECT(mbQ, 16384u);
        BULKG2S(sb + FQ, gq, 16384u, mbQ);
        MBEXPECT(mbKV, 32768u);
        BULKG2S(sb + FST + FK, gk, 16384u, mbKV);
        BULKG2S(sb + FST + FV, gv, 16384u, mbKV);
    }
    MBWAIT(mbQ, 0);

    const int rowA = wid * 16 + (lane & 15);
    const int rbB = (lane & 7) | ((lane >> 1) & 8);

    // hoist Q fragments (constant across KV tiles)
    uint32_t qfr[8][4];
    #pragma unroll
    for (int k8 = 0; k8 < 8; k8++) {
        int gA = 2 * k8 + (lane >> 4);
        LDSM4(qfr[k8][0], qfr[k8][1], qfr[k8][2], qfr[k8][3],
              sb + FQ + (uint32_t)(rowA * 256 + ((gA ^ (rowA & 7)) * 16)));
    }

    float oacc[16][4];
    #pragma unroll
    for (int i = 0; i < 16; i++)
        #pragma unroll
        for (int j = 0; j < 4; j++) oacc[i][j] = 0.f;
    float mrun0 = -1e30f, mrun1 = -1e30f, ls0 = 0.f, ls1 = 0.f;

    const int r0 = m0 + wid * 16 + (lane >> 2), r1 = r0 + 8;

    for (int jt = 0; jt < ntiles; jt++) {
        const int s = jt & 1;
        if (jt > 0) __syncthreads();   // all warps done with stage s^1
        if (t == 0 && jt + 1 < ntiles) {
            uint32_t mbn = mbKV + (uint32_t)(s ^ 1) * 8;
            MBEXPECT(mbn, 32768u);
            BULKG2S(sb + FST + (uint32_t)(s ^ 1) * FSTG + FK,
                    gk + (size_t)(jt + 1) * 16384, 16384u, mbn);
            BULKG2S(sb + FST + (uint32_t)(s ^ 1) * FSTG + FV,
                    gv + (size_t)(jt + 1) * 16384, 16384u, mbn);
        }
        MBWAIT(mbKV + (uint32_t)s * 8, (jt >> 1) & 1);

        const uint32_t stb = sb + FST + (uint32_t)s * FSTG;
        float sacc[8][4];
        #pragma unroll
        for (int i = 0; i < 8; i++)
            #pragma unroll
            for (int j = 0; j < 4; j++) sacc[i][j] = 0.f;

        // ---- S = Q K^T (64 keys)
        #pragma unroll
        for (int k8 = 0; k8 < 8; k8++) {
            int gB = 2 * k8 + ((lane >> 3) & 1);
            #pragma unroll
            for (int np = 0; np < 4; np++) {
                int rowB = np * 16 + rbB;
                uint32_t bk[4];
                LDSM4(bk[0], bk[1], bk[2], bk[3],
                      stb + FK + (uint32_t)(rowB * 256 + ((gB ^ (rowB & 7)) * 16)));
                MMAF16(sacc[2 * np],     qfr[k8], &bk[0]);
                MMAF16(sacc[2 * np + 1], qfr[k8], &bk[2]);
            }
        }

        // ---- causal mask (diagonal tile only; k0 == m0 there)
        if (jt == ntiles - 1) {
            const int k0 = jt * 64;
            #pragma unroll
            for (int nt = 0; nt < 8; nt++) {
                int c = k0 + nt * 8 + 2 * (lane & 3);
                if (c     > r0) sacc[nt][0] = -1e30f;
                if (c + 1 > r0) sacc[nt][1] = -1e30f;
                if (c     > r1) sacc[nt][2] = -1e30f;
                if (c + 1 > r1) sacc[nt][3] = -1e30f;
            }
        }

        // ---- online softmax (log2 domain; scale*log2e folded into Q)
        float ml0 = -1e30f, ml1 = -1e30f;
        #pragma unroll
        for (int nt = 0; nt < 8; nt++) {
            ml0 = fmaxf(ml0, fmaxf(sacc[nt][0], sacc[nt][1]));
            ml1 = fmaxf(ml1, fmaxf(sacc[nt][2], sacc[nt][3]));
        }
        ml0 = fmaxf(ml0, __shfl_xor_sync(0xffffffffu, ml0, 1));
        ml0 = fmaxf(ml0, __shfl_xor_sync(0xffffffffu, ml0, 2));
        ml1 = fmaxf(ml1, __shfl_xor_sync(0xffffffffu, ml1, 1));
        ml1 = fmaxf(ml1, __shfl_xor_sync(0xffffffffu, ml1, 2));
        float mn0 = fmaxf(mrun0, ml0), mn1 = fmaxf(mrun1, ml1);
        float c0 = exp2f(mrun0 - mn0), c1 = exp2f(mrun1 - mn1);
        mrun0 = mn0; mrun1 = mn1;
        ls0 *= c0; ls1 *= c1;
        #pragma unroll
        for (int nt = 0; nt < 16; nt++) {
            oacc[nt][0] *= c0; oacc[nt][1] *= c0;
            oacc[nt][2] *= c1; oacc[nt][3] *= c1;
        }
        float ps0 = 0.f, ps1 = 0.f;
        #pragma unroll
        for (int nt = 0; nt < 8; nt++) {
            sacc[nt][0] = exp2f(sacc[nt][0] - mn0);
            sacc[nt][1] = exp2f(sacc[nt][1] - mn0);
            sacc[nt][2] = exp2f(sacc[nt][2] - mn1);
            sacc[nt][3] = exp2f(sacc[nt][3] - mn1);
            ps0 += sacc[nt][0] + sacc[nt][1];
            ps1 += sacc[nt][2] + sacc[nt][3];
        }
        ls0 += ps0; ls1 += ps1;

        // ---- O += P V ; P C-frags repack as fp16 A-frags
        #pragma unroll
        for (int kp = 0; kp < 4; kp++) {
            uint32_t pa[4];
            pa[0] = packh2(sacc[2 * kp][0],     sacc[2 * kp][1]);
            pa[1] = packh2(sacc[2 * kp][2],     sacc[2 * kp][3]);
            pa[2] = packh2(sacc[2 * kp + 1][0], sacc[2 * kp + 1][1]);
            pa[3] = packh2(sacc[2 * kp + 1][2], sacc[2 * kp + 1][3]);
            int rv = kp * 16 + (lane & 15);
            #pragma unroll
            for (int dp = 0; dp < 8; dp++) {
                int gV = 2 * dp + (lane >> 4);
                uint32_t vv[4];
                LDSM4T(vv, stb + FV + (uint32_t)(rv * 256 + ((gV ^ (rv & 7)) * 16)));
                MMAF16(oacc[2 * dp],     pa, &vv[0]);
                MMAF16(oacc[2 * dp + 1], pa, &vv[2]);
            }
        }
    }

    // ---- epilogue: normalize, write att as A-image blocks
    float lt0 = ls0 + __shfl_xor_sync(0xffffffffu, ls0, 1);
    lt0 += __shfl_xor_sync(0xffffffffu, lt0, 2);
    float lt1 = ls1 + __shfl_xor_sync(0xffffffffu, ls1, 1);
    lt1 += __shfl_xor_sync(0xffffffffu, lt1, 2);
    float inv0 = 1.f / lt0, inv1 = 1.f / lt1;

    const int b = bh >> 4, h = bh & 15;
    const size_t pbase = (size_t)((b * 16 + (r0 >> 7)) * 64) * 8192;
    #pragma unroll
    for (int nt = 0; nt < 16; nt++) {
        int d = nt * 8 + 2 * (lane & 3);
        int col = h * 128 + d;
        size_t blk = pbase + (size_t)(col >> 5) * 8192;
        uint32_t u = (uint32_t)((d & 31) >> 3);
        uint32_t rA = (uint32_t)(r0 & 127), rB = (uint32_t)(r1 & 127);
        uint32_t offA = rA * 64 + ((u ^ (rA & 3)) * 16) + (d & 7) * 2;
        uint32_t offB = rB * 64 + ((u ^ (rB & 3)) * 16) + (d & 7) * 2;
        *(uint32_t*)((char*)Ob + blk + offA) = packh2(oacc[nt][0] * inv0, oacc[nt][1] * inv0);
        *(uint32_t*)((char*)Ob + blk + offB) = packh2(oacc[nt][2] * inv1, oacc[nt][3] * inv1);
    }
}

// ---------------- launch ----------------
extern "C" void kernel_launch(void* const* d_in, const int* in_sizes, int n_in,
                              void* d_out, int out_size)
{
    (void)in_sizes; (void)n_in; (void)out_size;
    const float* x    = (const float*)d_in[0];
    const float* fcos = (const float*)d_in[1];
    const float* fsin = (const float*)d_in[2];
    const float* wq   = (const float*)d_in[3];
    const float* wk   = (const float*)d_in[4];
    const float* wv   = (const float*)d_in[5];
    const float* wo   = (const float*)d_in[6];
    float* out = (float*)d_out;

    __half *xb, *attb, *qb, *kb, *vb, *wqT, *wkT, *wvT, *woT;
    cudaGetSymbolAddress((void**)&xb,   g_xb);
    cudaGetSymbolAddress((void**)&attb, g_attb);
    cudaGetSymbolAddress((void**)&qb,   g_qb);
    cudaGetSymbolAddress((void**)&kb,   g_kb);
    cudaGetSymbolAddress((void**)&vb,   g_vb);
    cudaGetSymbolAddress((void**)&wqT,  g_wqT);
    cudaGetSymbolAddress((void**)&wkT,  g_wkT);
    cudaGetSymbolAddress((void**)&wvT,  g_wvT);
    cudaGetSymbolAddress((void**)&woT,  g_woT);

    cudaFuncSetAttribute(gemm_qkv, cudaFuncAttributeMaxDynamicSharedMemorySize, GSMEM);
    cudaFuncSetAttribute(gemm_wo,  cudaFuncAttributeMaxDynamicSharedMemorySize, GSMEM);
    cudaFuncSetAttribute(flash_f16, cudaFuncAttributeMaxDynamicSharedMemorySize, FSMEM);

    // conversions into tile-image layouts
    cvt_x<<<2048, 256>>>(x, xb);
    cvtT4_k<<<dim3(DMODEL / 32, DMODEL / 32, 4), dim3(32, 8)>>>(
        wq, wk, wv, wo, wqT, wkT, wvT, woT);

    // fused QKV GEMM with rope-fused epilogue (128x128 tiles, 2 CTAs/SM)
    dim3 gq3(DMODEL / 128, ROWS / 128, 3);   // (16, 32, 3)
    gemm_qkv<<<gq3, 128, GSMEM>>>(xb, wqT, wkT, wvT, fcos, fsin, qb, kb, vb);

    flash_f16<<<dim3(SEQ / 64, BATCH * NHEADS), 128, FSMEM>>>(qb, kb, vb, attb);

    gemm_wo<<<dim3(DMODEL / 128, ROWS / 128), 128, GSMEM>>>(attb, woT, out);
}

// round 14
// speedup vs baseline: 12.3380x; 1.0404x over previous
#include <cuda_runtime.h>
#include <cuda_fp16.h>
#include <cstdint>

// Problem constants
#define BATCH 2
#define SEQ   2048
#define DMODEL 2048
#define NHEADS 16
#define HDIM  128
#define ROWS  (BATCH * SEQ)          // 4096
#define QKV_ELEMS (ROWS * DMODEL)    // 8388608
#define WELEMS (DMODEL * DMODEL)     // 4194304

// ---------------- scratch (device globals; no allocation) ----------------
//  A-image : 8KB block per (m-panel128, k-chunk32): row*64 + ((u^(row&3))*16)
//  B-image : 8KB block per (n-panel128, k-chunk32): row*64 + ((u^(row&3))*16)
//  F-image : 32KB block per (head, seq-tile128): row*256 + ((g^(row&7))*16)
__device__ __align__(256) __half g_xb[QKV_ELEMS];                  // A-image
__device__ __align__(256) __half g_attb[QKV_ELEMS];                // A-image
__device__ __align__(256) __half g_qb[QKV_ELEMS], g_kb[QKV_ELEMS], g_vb[QKV_ELEMS]; // F-image
__device__ __align__(256) __half g_wqT[WELEMS], g_wkT[WELEMS];     // B-image
__device__ __align__(256) __half g_wvT[WELEMS], g_woT[WELEMS];     // B-image

// ---------------- PTX helpers ----------------
__device__ __forceinline__ uint32_t s2u(const void* p) {
    uint32_t a;
    asm("{ .reg .u64 t; cvta.to.shared.u64 t, %1; cvt.u32.u64 %0, t; }"
        : "=r"(a) : "l"(p));
    return a;
}
#define MBINIT(a, c) asm volatile("mbarrier.init.shared.b64 [%0], %1;" :: "r"(a), "r"(c) : "memory")
#define MBEXPECT(a, tx) asm volatile("mbarrier.arrive.expect_tx.shared.b64 _, [%0], %1;" :: "r"(a), "r"(tx) : "memory")
#define MBARRIVE(a) asm volatile("mbarrier.arrive.shared.b64 _, [%0];" :: "r"(a) : "memory")
#define MBWAIT(a, ph) do { \
    uint32_t _m = (a), _p = (ph), _d; \
    asm volatile("{ .reg .pred p; mbarrier.try_wait.parity.acquire.cta.shared::cta.b64 p, [%1], %2; selp.b32 %0,1,0,p; }" \
                 : "=r"(_d) : "r"(_m), "r"(_p) : "memory"); \
    if (!_d) { \
        asm volatile("{ .reg .pred P1; WL%=: mbarrier.try_wait.parity.acquire.cta.shared::cta.b64 P1, [%0], %1, 0x989680; @P1 bra.uni WD%=; bra.uni WL%=; WD%=: }" \
                     :: "r"(_m), "r"(_p) : "memory"); \
    } } while (0)
#define BULKG2S(dst, src, bytes, mbar) \
    asm volatile("cp.async.bulk.shared::cluster.global.mbarrier::complete_tx::bytes [%0], [%1], %2, [%3];" \
                 :: "r"(dst), "l"(src), "r"(bytes), "r"(mbar) : "memory")

#define LDSM4(r0, r1, r2, r3, a) \
    asm volatile("ldmatrix.sync.aligned.m8n8.x4.shared.b16 {%0,%1,%2,%3}, [%4];" \
                 : "=r"(r0), "=r"(r1), "=r"(r2), "=r"(r3) : "r"(a))
#define LDSM2(r0, r1, a) \
    asm volatile("ldmatrix.sync.aligned.m8n8.x2.shared.b16 {%0,%1}, [%2];" \
                 : "=r"(r0), "=r"(r1) : "r"(a))
#define LDSM4T(r, a) \
    asm volatile("ldmatrix.sync.aligned.m8n8.x4.trans.shared.b16 {%0,%1,%2,%3}, [%4];" \
                 : "=r"((r)[0]), "=r"((r)[1]), "=r"((r)[2]), "=r"((r)[3]) : "r"(a))

#define MMAF16(c, a, b) \
    asm volatile("mma.sync.aligned.m16n8k16.row.col.f32.f16.f16.f32 " \
                 "{%0,%1,%2,%3}, {%4,%5,%6,%7}, {%8,%9}, {%0,%1,%2,%3};" \
                 : "+f"((c)[0]), "+f"((c)[1]), "+f"((c)[2]), "+f"((c)[3]) \
                 : "r"((a)[0]), "r"((a)[1]), "r"((a)[2]), "r"((a)[3]), \
                   "r"((b)[0]), "r"((b)[1]))

__device__ __forceinline__ uint32_t packh2(float a, float b) {
    __half2 h = __floats2half2_rn(a, b);
    return *(uint32_t*)&h;
}

// ---------------- conversions ----------------
// x fp32 [4096,2048] -> A-image blocks. One CTA per 8KB block.
__global__ __launch_bounds__(256) void cvt_x(
    const float* __restrict__ x, __half* __restrict__ xb)
{
    int blk = blockIdx.x;                 // p*64 + ch
    int p = blk >> 6, ch = blk & 63;
    const float* src = x + (size_t)p * 128 * 2048 + ch * 32;
    char* dst = (char*)(xb + (size_t)blk * 4096);
    int t = threadIdx.x;
    #pragma unroll
    for (int i = 0; i < 2; i++) {
        int u = t + i * 256;              // 0..511
        int row = u >> 2, c16 = u & 3;
        const float4* s4 = (const float4*)(src + (size_t)row * 2048 + c16 * 8);
        float4 a = s4[0], b = s4[1];
        uint4 o;
        o.x = packh2(a.x, a.y); o.y = packh2(a.z, a.w);
        o.z = packh2(b.x, b.y); o.w = packh2(b.z, b.w);
        *(uint4*)(dst + row * 64 + ((c16 ^ (row & 3)) * 16)) = o;
    }
}

// 4 weights W[K,N] fp32 -> B-image (128-row panels), one launch
__global__ __launch_bounds__(256) void cvtT4_k(
    const float* __restrict__ wq, const float* __restrict__ wk,
    const float* __restrict__ wv, const float* __restrict__ wo,
    __half* __restrict__ tq, __half* __restrict__ tk,
    __half* __restrict__ tv, __half* __restrict__ to_)
{
    const float* W;
    __half* T;
    switch (blockIdx.z) {
        case 0:  W = wq; T = tq;  break;
        case 1:  W = wk; T = tk;  break;
        case 2:  W = wv; T = tv;  break;
        default: W = wo; T = to_; break;
    }
    __shared__ float tile[32][33];
    int bx = blockIdx.x * 32, by = blockIdx.y * 32;
    int tx = threadIdx.x, ty = threadIdx.y;   // block (32,8)
    #pragma unroll
    for (int r = 0; r < 32; r += 8)
        tile[ty + r][tx] = W[(size_t)(by + ty + r) * DMODEL + bx + tx];
    __syncthreads();
    #pragma unroll
    for (int r = 0; r < 32; r += 8) {
        int rr = bx + ty + r;       // n index
        int kk = by + tx;           // k index
        size_t blk = (size_t)((rr >> 7) * 64 + (kk >> 5));
        uint32_t off = (uint32_t)((rr & 127) * 64 +
                       ((((kk & 31) >> 3) ^ (rr & 3)) * 16) + (kk & 7) * 2);
        *(__half*)((char*)T + blk * 8192 + off) = __float2half(tile[tx][ty + r]);
    }
}

// ---------------- fp16 HMMA GEMM core (free-running mbarrier pipeline) ----------------
// CTA tile 128x128, 32 steps x BK=64, 3 stages x 32KB, 128 threads.
// full[s]: bulk-copy completion (tx). empty[s]: 4 warp arrivals release stage.
#define NITER 32
#define GS_A 0
#define GS_B 16384
#define GSTAGE 32768
#define GNST 3
#define GBAR (GNST * GSTAGE)       // 98304: full[0..2] then empty[0..2]
#define GSMEM (GBAR + 64)

__device__ __forceinline__ void gemm_core(
    const char* __restrict__ pA,   // A-image panel base (16KB per step)
    const char* __restrict__ pB,   // B-image panel base (16KB per step)
    float (&acc)[4][8][4])
{
    extern __shared__ __align__(128) char smem[];
    const uint32_t sbase = s2u(smem);
    const uint32_t mbF = sbase + GBAR;        // full barriers
    const uint32_t mbE = sbase + GBAR + 24;   // empty barriers
    const int t = threadIdx.x;
    const int lane = t & 31, wid = t >> 5;
    const int wm = wid >> 1, wn = wid & 1;

    #pragma unroll
    for (int i = 0; i < 4; i++)
        #pragma unroll
        for (int j = 0; j < 8; j++)
            #pragma unroll
            for (int r = 0; r < 4; r++) acc[i][j][r] = 0.f;

    if (t == 0) {
        #pragma unroll
        for (int s = 0; s < GNST; s++) { MBINIT(mbF + s * 8, 1); MBINIT(mbE + s * 8, 4); }
    }
    __syncthreads();
    if (t == 0) {
        #pragma unroll
        for (int s = 0; s < 2; s++) {
            MBEXPECT(mbF + s * 8, 32768u);
            BULKG2S(sbase + s * GSTAGE + GS_A, pA + (size_t)s * 16384, 16384u, mbF + s * 8);
            BULKG2S(sbase + s * GSTAGE + GS_B, pB + (size_t)s * 16384, 16384u, mbF + s * 8);
        }
    }

    for (int ic = 0; ic < NITER; ic++) {
        const int s = ic % 3;
        if (t == 0 && ic + 2 < NITER) {
            int c = ic + 2, ss = c % 3, f = c / 3;
            MBWAIT(mbE + ss * 8, (f == 0) ? 1 : ((f - 1) & 1));
            MBEXPECT(mbF + ss * 8, 32768u);
            BULKG2S(sbase + ss * GSTAGE + GS_A, pA + (size_t)c * 16384, 16384u, mbF + ss * 8);
            BULKG2S(sbase + ss * GSTAGE + GS_B, pB + (size_t)c * 16384, 16384u, mbF + ss * 8);
        }
        MBWAIT(mbF + s * 8, (ic / 3) & 1);

        const uint32_t stb = sbase + (uint32_t)s * GSTAGE;
        #pragma unroll
        for (int ksub = 0; ksub < 4; ksub++) {
            const uint32_t boff = (uint32_t)(ksub >> 1) * 8192;
            const int kp = ksub & 1;
            uint32_t af[4][4];
            #pragma unroll
            for (int ms = 0; ms < 4; ms++) {
                int r = wm * 64 + ms * 16 + (lane & 15);
                uint32_t c = (uint32_t)((2 * kp + (lane >> 4)) ^ (r & 3));
                LDSM4(af[ms][0], af[ms][1], af[ms][2], af[ms][3],
                      stb + GS_A + boff + (uint32_t)(r * 64) + c * 16);
            }
            #pragma unroll
            for (int ns = 0; ns < 8; ns++) {
                int rb = wn * 64 + ns * 8 + (lane & 7);
                uint32_t cb = (uint32_t)((2 * kp + ((lane >> 3) & 1)) ^ (rb & 3));
                uint32_t bf[2];
                LDSM2(bf[0], bf[1], stb + GS_B + boff + (uint32_t)(rb * 64) + cb * 16);
                #pragma unroll
                for (int ms = 0; ms < 4; ms++)
                    MMAF16(acc[ms][ns], af[ms], bf);
            }
        }
        if (lane == 0) MBARRIVE(mbE + s * 8);   // warp done with stage s
    }
    __syncthreads();
}

// QKV fused; z=0/1: rope fused -> qb/kb (F-image); z=2: vb (F-image).
#define RS 136   // smem row stride (floats) for rope exchange buffer

__global__ __launch_bounds__(128, 2) void gemm_qkv(
    const __half* __restrict__ xb,
    const __half* __restrict__ wqT, const __half* __restrict__ wkT,
    const __half* __restrict__ wvT,
    const float* __restrict__ fcos, const float* __restrict__ fsin,
    __half* __restrict__ qb, __half* __restrict__ kb, __half* __restrict__ vb)
{
    const int z = blockIdx.z;
    const __half* B = (z == 0) ? wqT : (z == 1) ? wkT : wvT;
    const int n0 = blockIdx.x * 128;
    const int m0 = blockIdx.y * 128;
    float acc[4][8][4];
    gemm_core((const char*)xb + (size_t)(m0 >> 7) * 64 * 8192,
              (const char*)B  + (size_t)(n0 >> 7) * 64 * 8192, acc);

    const int lane = threadIdx.x & 31, wid = threadIdx.x >> 5;
    const int wm = wid >> 1, wn = wid & 1;
    const int h = n0 >> 7;                 // single head per CTA

    if (z == 2) {
        #pragma unroll
        for (int ms = 0; ms < 4; ms++) {
            #pragma unroll
            for (int rh = 0; rh < 2; rh++) {
                int m = m0 + wm * 64 + ms * 16 + (lane >> 2) + rh * 8;
                int b = m >> 11, si = m & 2047;
                size_t blk = (size_t)((b * 16 + h) * 16 + (si >> 7));
                #pragma unroll
                for (int ns = 0; ns < 8; ns++) {
                    int d = wn * 64 + ns * 8 + 2 * (lane & 3);
                    float va = rh ? acc[ms][ns][2] : acc[ms][ns][0];
                    float vb_ = rh ? acc[ms][ns][3] : acc[ms][ns][1];
                    uint32_t off = (uint32_t)((si & 127) * 256 +
                                   (((d >> 3) ^ (si & 7)) * 16) + (d & 7) * 2);
                    *(uint32_t*)((char*)vb + blk * 32768 + off) = packh2(va, vb_);
                }
            }
        }
        return;
    }

    // ---- rope-fused epilogue for q/k -> F-image ----
    extern __shared__ __align__(128) char smem[];
    float* sm = (float*)smem;          // [32][RS] (stages no longer in use)
    const float qs = (z == 0) ? (0.08838834764831845f * 1.4426950408889634f) : 1.0f;
    __half* dst = (z == 0) ? qb : kb;

    #pragma unroll
    for (int ms = 0; ms < 4; ms++) {
        __syncthreads();
        #pragma unroll
        for (int rh = 0; rh < 2; rh++) {
            int lr = wm * 16 + (lane >> 2) + rh * 8;
            #pragma unroll
            for (int ns = 0; ns < 8; ns++) {
                int lc = wn * 64 + ns * 8 + 2 * (lane & 3);
                float va = rh ? acc[ms][ns][2] : acc[ms][ns][0];
                float vb_ = rh ? acc[ms][ns][3] : acc[ms][ns][1];
                *(float2*)&sm[lr * RS + lc] = make_float2(va, vb_);
            }
        }
        __syncthreads();
        // 32 rows; 4 warps x 8; lane covers rope pairs (d, d+64), d = 2*lane
        #pragma unroll
        for (int i = 0; i < 8; i++) {
            int lr = wid * 8 + i;       // 0..31
            int m = m0 + (lr >> 4) * 64 + ms * 16 + (lr & 15);
            int b = m >> 11, si = m & 2047;
            int d = 2 * lane;           // 0..62
            float2 v0 = *(float2*)&sm[lr * RS + d];
            float2 v1 = *(float2*)&sm[lr * RS + d + 64];
            float2 cc = *(const float2*)&fcos[si * 64 + d];
            float2 ss = *(const float2*)&fsin[si * 64 + d];
            float o0 = (v0.x * cc.x - v1.x * ss.x) * qs;
            float o1 = (v0.y * cc.y - v1.y * ss.y) * qs;
            float o2 = (v1.x * cc.x + v0.x * ss.x) * qs;
            float o3 = (v1.y * cc.y + v0.y * ss.y) * qs;
            size_t blk = (size_t)((b * 16 + h) * 16 + (si >> 7));
            char* bp = (char*)dst + blk * 32768;
            uint32_t r = (uint32_t)(si & 127);
            uint32_t off0 = r * 256 + (((d >> 3) ^ (r & 7)) * 16) + (d & 7) * 2;
            uint32_t off1 = r * 256 + ((((d + 64) >> 3) ^ (r & 7)) * 16) + (d & 7) * 2;
            *(uint32_t*)(bp + off0) = packh2(o0, o1);
            *(uint32_t*)(bp + off1) = packh2(o2, o3);
        }
    }
}

// WO: fp32 row-major out
__global__ __launch_bounds__(128, 2) void gemm_wo(
    const __half* __restrict__ attb, const __half* __restrict__ woT,
    float* __restrict__ out)
{
    const int n0 = blockIdx.x * 128;
    const int m0 = blockIdx.y * 128;
    float acc[4][8][4];
    gemm_core((const char*)attb + (size_t)(m0 >> 7) * 64 * 8192,
              (const char*)woT  + (size_t)(n0 >> 7) * 64 * 8192, acc);

    const int lane = threadIdx.x & 31, wid = threadIdx.x >> 5;
    const int wm = wid >> 1, wn = wid & 1;
    #pragma unroll
    for (int ms = 0; ms < 4; ms++) {
        #pragma unroll
        for (int rh = 0; rh < 2; rh++) {
            int m = m0 + wm * 64 + ms * 16 + (lane >> 2) + rh * 8;
            #pragma unroll
            for (int ns = 0; ns < 8; ns++) {
                int n = n0 + wn * 64 + ns * 8 + 2 * (lane & 3);
                float va = rh ? acc[ms][ns][2] : acc[ms][ns][0];
                float vb = rh ? acc[ms][ns][3] : acc[ms][ns][1];
                *(float2*)(out + (size_t)m * DMODEL + n) = make_float2(va, vb);
            }
        }
    }
}

// ---------------- fp16 HMMA flash attention, causal (free-running pipeline) ----------------
// CTA: 64 q rows, 4 warps x 16 rows, 64-key KV tiles, 3 stages. 112KB smem.
#define FQ 0
#define FST 16384
#define FSTG 32768
#define FK 0
#define FV 16384
#define FNST 3
#define FBAR (16384 + FNST * 32768)   // 114688: full[0..2], empty[0..2], mbQ
#define FSMEM (FBAR + 64)

__global__ __launch_bounds__(128, 2) void flash_f16(
    const __half* __restrict__ Qb, const __half* __restrict__ Kb,
    const __half* __restrict__ Vb, __half* __restrict__ Ob)
{
    extern __shared__ __align__(128) char smem[];
    const uint32_t sb = s2u(smem);
    const uint32_t mbF = sb + FBAR;          // full[s] at +8s
    const uint32_t mbE = sb + FBAR + 24;     // empty[s] at +8s
    const uint32_t mbQ = sb + FBAR + 48;
    const int t = threadIdx.x, lane = t & 31, wid = t >> 5;
    const int bh = blockIdx.y;
    const int qt = gridDim.x - 1 - blockIdx.x;   // LPT: longest first
    const int m0 = qt * 64;
    const int ntiles = qt + 1;                   // 64-key tiles

    const char* gq = (const char*)Qb + (size_t)(bh * 16 + (qt >> 1)) * 32768
                     + (size_t)(qt & 1) * 16384;
    const char* gk = (const char*)Kb + (size_t)(bh * 16) * 32768;
    const char* gv = (const char*)Vb + (size_t)(bh * 16) * 32768;

    if (t == 0) {
        #pragma unroll
        for (int s = 0; s < FNST; s++) { MBINIT(mbF + s * 8, 1); MBINIT(mbE + s * 8, 4); }
        MBINIT(mbQ, 1);
    }
    __syncthreads();
    if (t == 0) {
        MBEXPECT(mbQ, 16384u);
        BULKG2S(sb + FQ, gq, 16384u, mbQ);
        MBEXPECT(mbF, 32768u);
        BULKG2S(sb + FST + FK, gk, 16384u, mbF);
        BULKG2S(sb + FST + FV, gv, 16384u, mbF);
        if (ntiles > 1) {
            MBEXPECT(mbF + 8, 32768u);
            BULKG2S(sb + FST + FSTG + FK, gk + 16384, 16384u, mbF + 8);
            BULKG2S(sb + FST + FSTG + FV, gv + 16384, 16384u, mbF + 8);
        }
    }
    MBWAIT(mbQ, 0);

    const int rowA = wid * 16 + (lane & 15);
    const int rbB = (lane & 7) | ((lane >> 1) & 8);

    // hoist Q fragments (constant across KV tiles)
    uint32_t qfr[8][4];
    #pragma unroll
    for (int k8 = 0; k8 < 8; k8++) {
        int gA = 2 * k8 + (lane >> 4);
        LDSM4(qfr[k8][0], qfr[k8][1], qfr[k8][2], qfr[k8][3],
              sb + FQ + (uint32_t)(rowA * 256 + ((gA ^ (rowA & 7)) * 16)));
    }

    float oacc[16][4];
    #pragma unroll
    for (int i = 0; i < 16; i++)
        #pragma unroll
        for (int j = 0; j < 4; j++) oacc[i][j] = 0.f;
    float mrun0 = -1e30f, mrun1 = -1e30f, ls0 = 0.f, ls1 = 0.f;

    const int r0 = m0 + wid * 16 + (lane >> 2), r1 = r0 + 8;

    for (int jt = 0; jt < ntiles; jt++) {
        const int s = jt % 3;
        if (t == 0 && jt + 2 < ntiles) {
            int c = jt + 2, ss = c % 3, f = c / 3;
            MBWAIT(mbE + ss * 8, (f == 0) ? 1 : ((f - 1) & 1));
            MBEXPECT(mbF + ss * 8, 32768u);
            BULKG2S(sb + FST + (uint32_t)ss * FSTG + FK,
                    gk + (size_t)c * 16384, 16384u, mbF + ss * 8);
            BULKG2S(sb + FST + (uint32_t)ss * FSTG + FV,
                    gv + (size_t)c * 16384, 16384u, mbF + ss * 8);
        }
        MBWAIT(mbF + s * 8, (jt / 3) & 1);

        const uint32_t stb = sb + FST + (uint32_t)s * FSTG;
        float sacc[8][4];
        #pragma unroll
        for (int i = 0; i < 8; i++)
            #pragma unroll
            for (int j = 0; j < 4; j++) sacc[i][j] = 0.f;

        // ---- S = Q K^T (64 keys)
        #pragma unroll
        for (int k8 = 0; k8 < 8; k8++) {
            int gB = 2 * k8 + ((lane >> 3) & 1);
            #pragma unroll
            for (int np = 0; np < 4; np++) {
                int rowB = np * 16 + rbB;
                uint32_t bk[4];
                LDSM4(bk[0], bk[1], bk[2], bk[3],
                      stb + FK + (uint32_t)(rowB * 256 + ((gB ^ (rowB & 7)) * 16)));
                MMAF16(sacc[2 * np],     qfr[k8], &bk[0]);
                MMAF16(sacc[2 * np + 1], qfr[k8], &bk[2]);
            }
        }

        // ---- causal mask (diagonal tile only; k0 == m0 there)
        if (jt == ntiles - 1) {
            const int k0 = jt * 64;
            #pragma unroll
            for (int nt = 0; nt < 8; nt++) {
                int c = k0 + nt * 8 + 2 * (lane & 3);
                if (c     > r0) sacc[nt][0] = -1e30f;
                if (c + 1 > r0) sacc[nt][1] = -1e30f;
                if (c     > r1) sacc[nt][2] = -1e30f;
                if (c + 1 > r1) sacc[nt][3] = -1e30f;
            }
        }

        // ---- online softmax (log2 domain; scale*log2e folded into Q)
        float ml0 = -1e30f, ml1 = -1e30f;
        #pragma unroll
        for (int nt = 0; nt < 8; nt++) {
            ml0 = fmaxf(ml0, fmaxf(sacc[nt][0], sacc[nt][1]));
            ml1 = fmaxf(ml1, fmaxf(sacc[nt][2], sacc[nt][3]));
        }
        ml0 = fmaxf(ml0, __shfl_xor_sync(0xffffffffu, ml0, 1));
        ml0 = fmaxf(ml0, __shfl_xor_sync(0xffffffffu, ml0, 2));
        ml1 = fmaxf(ml1, __shfl_xor_sync(0xffffffffu, ml1, 1));
        ml1 = fmaxf(ml1, __shfl_xor_sync(0xffffffffu, ml1, 2));
        float mn0 = fmaxf(mrun0, ml0), mn1 = fmaxf(mrun1, ml1);
        float c0 = exp2f(mrun0 - mn0), c1 = exp2f(mrun1 - mn1);
        mrun0 = mn0; mrun1 = mn1;
        ls0 *= c0; ls1 *= c1;
        #pragma unroll
        for (int nt = 0; nt < 16; nt++) {
            oacc[nt][0] *= c0; oacc[nt][1] *= c0;
            oacc[nt][2] *= c1; oacc[nt][3] *= c1;
        }
        float ps0 = 0.f, ps1 = 0.f;
        #pragma unroll
        for (int nt = 0; nt < 8; nt++) {
            sacc[nt][0] = exp2f(sacc[nt][0] - mn0);
            sacc[nt][1] = exp2f(sacc[nt][1] - mn0);
            sacc[nt][2] = exp2f(sacc[nt][2] - mn1);
            sacc[nt][3] = exp2f(sacc[nt][3] - mn1);
            ps0 += sacc[nt][0] + sacc[nt][1];
            ps1 += sacc[nt][2] + sacc[nt][3];
        }
        ls0 += ps0; ls1 += ps1;

        // ---- O += P V ; P C-frags repack as fp16 A-frags
        #pragma unroll
        for (int kp = 0; kp < 4; kp++) {
            uint32_t pa[4];
            pa[0] = packh2(sacc[2 * kp][0],     sacc[2 * kp][1]);
            pa[1] = packh2(sacc[2 * kp][2],     sacc[2 * kp][3]);
            pa[2] = packh2(sacc[2 * kp + 1][0], sacc[2 * kp + 1][1]);
            pa[3] = packh2(sacc[2 * kp + 1][2], sacc[2 * kp + 1][3]);
            int rv = kp * 16 + (lane & 15);
            #pragma unroll
            for (int dp = 0; dp < 8; dp++) {
                int gV = 2 * dp + (lane >> 4);
                uint32_t vv[4];
                LDSM4T(vv, stb + FV + (uint32_t)(rv * 256 + ((gV ^ (rv & 7)) * 16)));
                MMAF16(oacc[2 * dp],     pa, &vv[0]);
                MMAF16(oacc[2 * dp + 1], pa, &vv[2]);
            }
        }
        if (lane == 0) MBARRIVE(mbE + s * 8);   // warp done with stage s
    }

    // ---- epilogue: normalize, write att as A-image blocks
    float lt0 = ls0 + __shfl_xor_sync(0xffffffffu, ls0, 1);
    lt0 += __shfl_xor_sync(0xffffffffu, lt0, 2);
    float lt1 = ls1 + __shfl_xor_sync(0xffffffffu, ls1, 1);
    lt1 += __shfl_xor_sync(0xffffffffu, lt1, 2);
    float inv0 = 1.f / lt0, inv1 = 1.f / lt1;

    const int b = bh >> 4, h = bh & 15;
    const size_t pbase = (size_t)((b * 16 + (r0 >> 7)) * 64) * 8192;
    #pragma unroll
    for (int nt = 0; nt < 16; nt++) {
        int d = nt * 8 + 2 * (lane & 3);
        int col = h * 128 + d;
        size_t blk = pbase + (size_t)(col >> 5) * 8192;
        uint32_t u = (uint32_t)((d & 31) >> 3);
        uint32_t rA = (uint32_t)(r0 & 127), rB = (uint32_t)(r1 & 127);
        uint32_t offA = rA * 64 + ((u ^ (rA & 3)) * 16) + (d & 7) * 2;
        uint32_t offB = rB * 64 + ((u ^ (rB & 3)) * 16) + (d & 7) * 2;
        *(uint32_t*)((char*)Ob + blk + offA) = packh2(oacc[nt][0] * inv0, oacc[nt][1] * inv0);
        *(uint32_t*)((char*)Ob + blk + offB) = packh2(oacc[nt][2] * inv1, oacc[nt][3] * inv1);
    }
}

// ---------------- launch ----------------
extern "C" void kernel_launch(void* const* d_in, const int* in_sizes, int n_in,
                              void* d_out, int out_size)
{
    (void)in_sizes; (void)n_in; (void)out_size;
    const float* x    = (const float*)d_in[0];
    const float* fcos = (const float*)d_in[1];
    const float* fsin = (const float*)d_in[2];
    const float* wq   = (const float*)d_in[3];
    const float* wk   = (const float*)d_in[4];
    const float* wv   = (const float*)d_in[5];
    const float* wo   = (const float*)d_in[6];
    float* out = (float*)d_out;

    __half *xb, *attb, *qb, *kb, *vb, *wqT, *wkT, *wvT, *woT;
    cudaGetSymbolAddress((void**)&xb,   g_xb);
    cudaGetSymbolAddress((void**)&attb, g_attb);
    cudaGetSymbolAddress((void**)&qb,   g_qb);
    cudaGetSymbolAddress((void**)&kb,   g_kb);
    cudaGetSymbolAddress((void**)&vb,   g_vb);
    cudaGetSymbolAddress((void**)&wqT,  g_wqT);
    cudaGetSymbolAddress((void**)&wkT,  g_wkT);
    cudaGetSymbolAddress((void**)&wvT,  g_wvT);
    cudaGetSymbolAddress((void**)&woT,  g_woT);

    cudaFuncSetAttribute(gemm_qkv, cudaFuncAttributeMaxDynamicSharedMemorySize, GSMEM);
    cudaFuncSetAttribute(gemm_wo,  cudaFuncAttributeMaxDynamicSharedMemorySize, GSMEM);
    cudaFuncSetAttribute(flash_f16, cudaFuncAttributeMaxDynamicSharedMemorySize, FSMEM);

    // conversions into tile-image layouts
    cvt_x<<<2048, 256>>>(x, xb);
    cvtT4_k<<<dim3(DMODEL / 32, DMODEL / 32, 4), dim3(32, 8)>>>(
        wq, wk, wv, wo, wqT, wkT, wvT, woT);

    // fused QKV GEMM with rope-fused epilogue (128x128 tiles, 2 CTAs/SM)
    dim3 gq3(DMODEL / 128, ROWS / 128, 3);   // (16, 32, 3)
    gemm_qkv<<<gq3, 128, GSMEM>>>(xb, wqT, wkT, wvT, fcos, fsin, qb, kb, vb);

    flash_f16<<<dim3(SEQ / 64, BATCH * NHEADS), 128, FSMEM>>>(qb, kb, vb, attb);

    gemm_wo<<<dim3(DMODEL / 128, ROWS / 128), 128, GSMEM>>>(attb, woT, out);
}